// round 1
// baseline (speedup 1.0000x reference)
#include <cuda_runtime.h>
#include <math.h>

#define L_ 2048
#define B_ 16
#define D_ 512
#define H_ 1024
#define Z_ 128
#define NC_ 16
#define NBASE 2176            // Z + H + 2D
#define MROWS (L_*B_)         // 32768

// ---------------- scratch (device globals; no allocations allowed) ----------------
__device__ float g_tmp [L_*B_*D_];     // ema fwd partial + residual
__device__ float g_mx  [L_*B_*D_];     // ema output (silu applied)
__device__ float g_v   [L_*B_*H_];     // silu(x@Wv+bv)
__device__ float g_base[L_*B_*NBASE];  // activated base: [u | z | r | hx]
__device__ float g_h   [L_*B_*H_];     // attention output
__device__ float g_o   [L_*B_*D_];     // pre-norm output

__device__ __forceinline__ float sigmf(float x){ return 1.0f/(1.0f + expf(-x)); }
__device__ __forceinline__ float siluf(float x){ return x/(1.0f + expf(-x)); }

// ---------------- EMA: forward scan ----------------
// y_fwd[l] = sum_n w_n * f_n[l],  f_n[l] = q_n f_n[l-1] + x[l]
// stores y_fwd + x*omega into g_tmp
__global__ void __launch_bounds__(256) ema_fwd(
    const float* __restrict__ x, const float* __restrict__ dlt,
    const float* __restrict__ alp, const float* __restrict__ bet,
    const float* __restrict__ gam, const float* __restrict__ omg)
{
    int tid = blockIdx.x*256 + threadIdx.x;   // 0..8191
    int b = tid >> 9;
    int d = tid & 511;
    int i0 = d*2, i1 = d*2 + 1;
    float p0 = sigmf(dlt[i0]), p1 = sigmf(dlt[i1]);
    float q0 = 1.f - p0*sigmf(alp[i0]);
    float q1 = 1.f - p1*sigmf(alp[i1]);
    const float invs = 0.7071067811865476f;
    float w0 = p0*bet[i0]*gam[i0]*invs;
    float w1 = p1*bet[i1]*gam[i1]*invs;
    float ow = omg[d];

    float f0 = 0.f, f1 = 0.f;
    int idx = b*512 + d;
    #pragma unroll 8
    for (int l = 0; l < L_; ++l, idx += 8192) {
        float xv = x[idx];
        f0 = fmaf(q0, f0, xv);
        f1 = fmaf(q1, f1, xv);
        g_tmp[idx] = fmaf(w0, f0, fmaf(w1, f1, xv*ow));
    }
}

// ---------------- EMA: backward scan + silu ----------------
__global__ void __launch_bounds__(256) ema_bwd(
    const float* __restrict__ x, const float* __restrict__ dlt,
    const float* __restrict__ alp, const float* __restrict__ bet,
    const float* __restrict__ gam)
{
    int tid = blockIdx.x*256 + threadIdx.x;
    int b = tid >> 9;
    int d = tid & 511;
    int i0 = (512 + d)*2, i1 = i0 + 1;
    float p0 = sigmf(dlt[i0]), p1 = sigmf(dlt[i1]);
    float q0 = 1.f - p0*sigmf(alp[i0]);
    float q1 = 1.f - p1*sigmf(alp[i1]);
    const float invs = 0.7071067811865476f;
    float w0 = p0*bet[i0]*gam[i0]*invs;
    float w1 = p1*bet[i1]*gam[i1]*invs;

    float f0 = 0.f, f1 = 0.f;
    int idx = (L_-1)*8192 + b*512 + d;
    #pragma unroll 8
    for (int l = 0; l < L_; ++l, idx -= 8192) {
        float xv = x[idx];
        f0 = fmaf(q0, f0, xv);
        f1 = fmaf(q1, f1, xv);
        float y = g_tmp[idx] + fmaf(w0, f0, w1*f1);
        g_mx[idx] = siluf(y);
    }
}

// ---------------- generic tiled fp32 GEMM (128x128x16, 8x8 micro) ----------------
// MODE 0: g_v   = silu(x @ Wv + bv)                        N=1024 K=512
// MODE 1: g_base= act(g_mx @ Wmx + bmx)  (seg activations) N=2176 K=512
// MODE 2: g_o   = x + u*(silu((g_h*r)@Wh + bh + hx) - x)   N=512  K=1024
template<int MODE>
__global__ void __launch_bounds__(256) gemm_kernel(
    const float* __restrict__ A, const float* __restrict__ Bm,
    const float* __restrict__ bias)
{
    constexpr int N = (MODE==0) ? 1024 : (MODE==1) ? 2176 : 512;
    constexpr int K = (MODE==2) ? 1024 : 512;

    __shared__ float As[16][132];   // transposed A tile: As[k][m]
    __shared__ float Bs[16][128];

    const int bm = blockIdx.y * 128;
    const int bn = blockIdx.x * 128;
    const int t  = threadIdx.x;
    const int tx = t & 15, ty = t >> 4;

    float acc[8][8];
    #pragma unroll
    for (int i = 0; i < 8; i++)
        #pragma unroll
        for (int j = 0; j < 8; j++) acc[i][j] = 0.f;

    for (int k0 = 0; k0 < K; k0 += 16) {
        #pragma unroll
        for (int e = 0; e < 8; e++) {
            int li = t + e*256;
            int r = li >> 4, c = li & 15;
            int m = bm + r, kk = k0 + c;
            float a;
            if (MODE == 2)      a = g_h[m*H_ + kk] * g_base[m*NBASE + 640 + kk];
            else if (MODE == 1) a = g_mx[m*D_ + kk];
            else                a = A[m*D_ + kk];
            As[c][r] = a;
        }
        #pragma unroll
        for (int e = 0; e < 8; e++) {
            int li = t + e*256;
            int r = li >> 7, c = li & 127;
            Bs[r][c] = Bm[(k0 + r)*N + bn + c];
        }
        __syncthreads();
        #pragma unroll
        for (int kk = 0; kk < 16; kk++) {
            float ar[8], br[8];
            *(float4*)(ar)   = *(const float4*)&As[kk][ty*8];
            *(float4*)(ar+4) = *(const float4*)&As[kk][ty*8 + 4];
            *(float4*)(br)   = *(const float4*)&Bs[kk][tx*8];
            *(float4*)(br+4) = *(const float4*)&Bs[kk][tx*8 + 4];
            #pragma unroll
            for (int i = 0; i < 8; i++)
                #pragma unroll
                for (int j = 0; j < 8; j++)
                    acc[i][j] = fmaf(ar[i], br[j], acc[i][j]);
        }
        __syncthreads();
    }

    #pragma unroll
    for (int i = 0; i < 8; i++) {
        int m = bm + ty*8 + i;
        #pragma unroll
        for (int j = 0; j < 8; j++) {
            int n = bn + tx*8 + j;
            float v = acc[i][j] + bias[n];
            if (MODE == 0) {
                g_v[m*H_ + n] = siluf(v);
            } else if (MODE == 1) {
                if (n < 512)       v = sigmf(v);
                else if (n < 1664) v = siluf(v);
                g_base[m*NBASE + n] = v;
            } else {
                float hx = g_base[m*NBASE + 1664 + n];
                float s  = siluf(v + hx);
                float u  = g_base[m*NBASE + n];
                float xr = A[m*D_ + n];               // A = x (residual)
                g_o[m*D_ + n] = xr + u*(s - xr);
            }
        }
    }
}

// ---------------- chunked attention (one block per (b, chunk)) ----------------
__global__ void __launch_bounds__(256) attn_kernel(
    const float* __restrict__ qkg, const float* __restrict__ qkb,
    const float* __restrict__ rp, float* __restrict__ attn_out)
{
    extern __shared__ float sm[];
    float* qT = sm;             // [z][i] 128*128
    float* kT = sm + 16384;     // [z][j] 128*128
    float* sT = sm + 32768;     // [j][i] stride 132
    float* vt = sm;             // reuse qT region: [j][col] 128*128

    const int b = blockIdx.x >> 4;
    const int c = blockIdx.x & 15;
    const int t = threadIdx.x;
    const float qscale = 0.08838834764831845f;   // 128^-0.5

    for (int idx = t; idx < 16384; idx += 256) {
        int i = idx >> 7, z = idx & 127;
        int row = (c*128 + i)*B_ + b;
        float zv = g_base[row*NBASE + 512 + z];
        qT[z*128 + i] = (zv*qkg[z]     + qkb[z]    ) * qscale;
        kT[z*128 + i] =  zv*qkg[128+z] + qkb[128+z];
    }
    __syncthreads();

    const int tx = t & 15, ty = t >> 4;
    const int i0 = ty*8, j0 = tx*8;

    float acc[8][8];
    #pragma unroll
    for (int i = 0; i < 8; i++)
        #pragma unroll
        for (int j = 0; j < 8; j++) acc[i][j] = 0.f;

    #pragma unroll 4
    for (int z = 0; z < 128; z++) {
        float qa[8], ka[8];
        *(float4*)(qa)   = *(const float4*)&qT[z*128 + i0];
        *(float4*)(qa+4) = *(const float4*)&qT[z*128 + i0 + 4];
        *(float4*)(ka)   = *(const float4*)&kT[z*128 + j0];
        *(float4*)(ka+4) = *(const float4*)&kT[z*128 + j0 + 4];
        #pragma unroll
        for (int i = 0; i < 8; i++)
            #pragma unroll
            for (int j = 0; j < 8; j++)
                acc[i][j] = fmaf(qa[i], ka[j], acc[i][j]);
    }
    #pragma unroll
    for (int r = 0; r < 8; r++)
        #pragma unroll
        for (int cc = 0; cc < 8; cc++) {
            int i = i0 + r, j = j0 + cc;
            sT[j*132 + i] = acc[r][cc] + rp[1023 + j - i];
        }
    __syncthreads();

    if (t < 128) {
        const int i = t;
        float mx = -1e30f;
        for (int j = 0; j < 128; j++) mx = fmaxf(mx, sT[j*132 + i]);
        float ssum = 0.f;
        for (int j = 0; j < 128; j++) {
            float e = expf(sT[j*132 + i] - mx);
            sT[j*132 + i] = e;
            ssum += e;
        }
        float inv = 1.f/ssum;
        for (int j = 0; j < 128; j++) sT[j*132 + i] *= inv;
    }
    __syncthreads();

    // write attn (B, nc, 128q, 128k)
    float* aout = attn_out + (b*NC_ + c)*16384;
    for (int idx = t; idx < 16384; idx += 256) {
        int i = idx >> 7, j = idx & 127;
        aout[idx] = sT[j*132 + i];
    }

    // h = attn @ v, stream v in 128-col tiles (reuses qT/kT smem)
    for (int hc = 0; hc < 8; hc++) {
        __syncthreads();
        for (int idx = t; idx < 16384; idx += 256) {
            int j = idx >> 7, col = idx & 127;
            vt[j*128 + col] = g_v[((c*128 + j)*B_ + b)*H_ + hc*128 + col];
        }
        __syncthreads();
        float o8[8][8];
        #pragma unroll
        for (int i = 0; i < 8; i++)
            #pragma unroll
            for (int j = 0; j < 8; j++) o8[i][j] = 0.f;
        #pragma unroll 4
        for (int j = 0; j < 128; j++) {
            float sa[8], va[8];
            *(float4*)(sa)   = *(const float4*)&sT[j*132 + i0];
            *(float4*)(sa+4) = *(const float4*)&sT[j*132 + i0 + 4];
            *(float4*)(va)   = *(const float4*)&vt[j*128 + j0];
            *(float4*)(va+4) = *(const float4*)&vt[j*128 + j0 + 4];
            #pragma unroll
            for (int r = 0; r < 8; r++)
                #pragma unroll
                for (int cc = 0; cc < 8; cc++)
                    o8[r][cc] = fmaf(sa[r], va[cc], o8[r][cc]);
        }
        #pragma unroll
        for (int r = 0; r < 8; r++) {
            int row = (c*128 + i0 + r)*B_ + b;
            float4 v0 = make_float4(o8[r][0], o8[r][1], o8[r][2], o8[r][3]);
            float4 v1 = make_float4(o8[r][4], o8[r][5], o8[r][6], o8[r][7]);
            *(float4*)&g_h[row*H_ + hc*128 + j0]     = v0;
            *(float4*)&g_h[row*H_ + hc*128 + j0 + 4] = v1;
        }
    }
}

// ---------------- final rmsnorm (one warp per row) ----------------
__global__ void __launch_bounds__(256) norm_kernel(
    const float* __restrict__ ns, float* __restrict__ out)
{
    int row  = blockIdx.x*8 + (threadIdx.x >> 5);
    int lane = threadIdx.x & 31;
    const float* op = g_o + row*512;
    float vals[16];
    float ss = 0.f;
    #pragma unroll
    for (int k = 0; k < 16; k++) {
        float v = op[lane + k*32];
        vals[k] = v;
        ss += v*v;
    }
    #pragma unroll
    for (int off = 16; off; off >>= 1) ss += __shfl_xor_sync(0xffffffffu, ss, off);
    float scale = ns[0] * rsqrtf(ss*(1.f/512.f) + 1e-6f);
    float* outp = out + row*512;
    #pragma unroll
    for (int k = 0; k < 16; k++) outp[lane + k*32] = vals[k]*scale;
}

// ---------------- launch ----------------
extern "C" void kernel_launch(void* const* d_in, const int* in_sizes, int n_in,
                              void* d_out, int out_size)
{
    const float* x   = (const float*)d_in[0];
    const float* edl = (const float*)d_in[1];
    const float* eal = (const float*)d_in[2];
    const float* ebt = (const float*)d_in[3];
    const float* egm = (const float*)d_in[4];
    const float* eom = (const float*)d_in[5];
    const float* Wv  = (const float*)d_in[6];
    const float* bv  = (const float*)d_in[7];
    const float* Wmx = (const float*)d_in[8];
    const float* bmx = (const float*)d_in[9];
    const float* Wh  = (const float*)d_in[10];
    const float* bh  = (const float*)d_in[11];
    const float* qkg = (const float*)d_in[12];
    const float* qkb = (const float*)d_in[13];
    const float* rp  = (const float*)d_in[14];
    const float* ns  = (const float*)d_in[15];

    float* out      = (float*)d_out;
    float* attn_out = out + (size_t)L_*B_*D_;

    cudaFuncSetAttribute(attn_kernel, cudaFuncAttributeMaxDynamicSharedMemorySize, 198656);

    ema_fwd<<<32, 256>>>(x, edl, eal, ebt, egm, eom);
    ema_bwd<<<32, 256>>>(x, edl, eal, ebt, egm);

    { dim3 g(1024/128, MROWS/128); gemm_kernel<0><<<g, 256>>>(x, Wv, bv); }
    { dim3 g(2176/128, MROWS/128); gemm_kernel<1><<<g, 256>>>(nullptr, Wmx, bmx); }

    attn_kernel<<<B_*NC_, 256, 198656>>>(qkg, qkb, rp, attn_out);

    { dim3 g(512/128, MROWS/128); gemm_kernel<2><<<g, 256>>>(x, Wh, bh); }

    norm_kernel<<<MROWS/8, 256>>>(ns, out);
}

// round 3
// speedup vs baseline: 1.3161x; 1.3161x over previous
#include <cuda_runtime.h>
#include <cuda_bf16.h>
#include <stdint.h>
#include <math.h>

#define L_ 2048
#define B_ 16
#define D_ 512
#define H_ 1024
#define Z_ 128
#define NC_ 16
#define NBASE 2176            // Z + H + 2D
#define MROWS (L_*B_)         // 32768

// ---------------- scratch (device globals; no allocations allowed) ----------------
__device__ float g_tmp [L_*B_*D_];     // ema fwd partial
__device__ float g_mx  [L_*B_*D_];     // ema output (silu applied)
__device__ float g_v   [L_*B_*H_];     // silu(x@Wv+bv)
__device__ float g_base[L_*B_*NBASE];  // activated base: [u | z | r | hx]
__device__ float g_h   [L_*B_*H_];     // attention output
__device__ float g_o   [L_*B_*D_];     // pre-norm output

__device__ __forceinline__ float sigmf(float x){ return 1.0f/(1.0f + expf(-x)); }
__device__ __forceinline__ float siluf(float x){ return x/(1.0f + expf(-x)); }

__device__ __forceinline__ void split2(float v, __nv_bfloat16& h, __nv_bfloat16& l){
    h = __float2bfloat16_rn(v);
    l = __float2bfloat16_rn(v - __bfloat162float(h));
}

#define MMA16816(d, a, b0, b1) \
  asm volatile("mma.sync.aligned.m16n8k16.row.col.f32.bf16.bf16.f32 " \
    "{%0,%1,%2,%3}, {%4,%5,%6,%7}, {%8,%9}, {%0,%1,%2,%3};" \
    : "+f"(d[0]), "+f"(d[1]), "+f"(d[2]), "+f"(d[3]) \
    : "r"(a[0]), "r"(a[1]), "r"(a[2]), "r"(a[3]), "r"(b0), "r"(b1))

// ---------------- EMA: forward scan ----------------
__global__ void __launch_bounds__(256) ema_fwd(
    const float* __restrict__ x, const float* __restrict__ dlt,
    const float* __restrict__ alp, const float* __restrict__ bet,
    const float* __restrict__ gam, const float* __restrict__ omg)
{
    int tid = blockIdx.x*256 + threadIdx.x;   // 0..8191
    int b = tid >> 9;
    int d = tid & 511;
    int i0 = d*2, i1 = d*2 + 1;
    float p0 = sigmf(dlt[i0]), p1 = sigmf(dlt[i1]);
    float q0 = 1.f - p0*sigmf(alp[i0]);
    float q1 = 1.f - p1*sigmf(alp[i1]);
    const float invs = 0.7071067811865476f;
    float w0 = p0*bet[i0]*gam[i0]*invs;
    float w1 = p1*bet[i1]*gam[i1]*invs;
    float ow = omg[d];

    float f0 = 0.f, f1 = 0.f;
    int idx = b*512 + d;
    #pragma unroll 8
    for (int l = 0; l < L_; ++l, idx += 8192) {
        float xv = x[idx];
        f0 = fmaf(q0, f0, xv);
        f1 = fmaf(q1, f1, xv);
        g_tmp[idx] = fmaf(w0, f0, fmaf(w1, f1, xv*ow));
    }
}

// ---------------- EMA: backward scan + silu ----------------
__global__ void __launch_bounds__(256) ema_bwd(
    const float* __restrict__ x, const float* __restrict__ dlt,
    const float* __restrict__ alp, const float* __restrict__ bet,
    const float* __restrict__ gam)
{
    int tid = blockIdx.x*256 + threadIdx.x;
    int b = tid >> 9;
    int d = tid & 511;
    int i0 = (512 + d)*2, i1 = i0 + 1;
    float p0 = sigmf(dlt[i0]), p1 = sigmf(dlt[i1]);
    float q0 = 1.f - p0*sigmf(alp[i0]);
    float q1 = 1.f - p1*sigmf(alp[i1]);
    const float invs = 0.7071067811865476f;
    float w0 = p0*bet[i0]*gam[i0]*invs;
    float w1 = p1*bet[i1]*gam[i1]*invs;

    float f0 = 0.f, f1 = 0.f;
    int idx = (L_-1)*8192 + b*512 + d;
    #pragma unroll 8
    for (int l = 0; l < L_; ++l, idx -= 8192) {
        float xv = x[idx];
        f0 = fmaf(q0, f0, xv);
        f1 = fmaf(q1, f1, xv);
        float y = g_tmp[idx] + fmaf(w0, f0, w1*f1);
        g_mx[idx] = siluf(y);
    }
}

// ---------------- split-bf16 tensor-core GEMM (128x128x32 tile, 8 warps) ----------
// MODE 0: g_v   = silu(x @ Wv + bv)                    M=32768 N=1024 K=512
// MODE 1: g_base= act(g_mx @ Wmx + bmx)                M=32768 N=2176 K=512
// MODE 2: g_o   = gate(silu((g_h*r)@Wh + bh + hx))     M=32768 N=512  K=1024
// MODE 3: g_h   = attn @ v   (batched, 256 batches)    M=128   N=1024 K=128
template<int MODE>
__global__ void __launch_bounds__(256, 2) mma_gemm(
    const float* __restrict__ A, const float* __restrict__ Bm,
    const float* __restrict__ bias)
{
    constexpr int N = (MODE==0) ? 1024 : (MODE==1) ? 2176 : (MODE==2) ? 512 : 1024;
    constexpr int K = (MODE==2) ? 1024 : (MODE==3) ? 128 : 512;

    __shared__ __align__(16) __nv_bfloat16 Ah[128][36];
    __shared__ __align__(16) __nv_bfloat16 Al[128][36];
    __shared__ __align__(16) __nv_bfloat16 Bh[128][36];   // [n][k]
    __shared__ __align__(16) __nv_bfloat16 Bl[128][36];

    const int t = threadIdx.x;
    const int warp = t >> 5, lane = t & 31;
    const int wm = warp & 3, wn = warp >> 2;      // 4 (m) x 2 (n)
    const int group = lane >> 2, tid4 = lane & 3;

    const int bn = blockIdx.x * 128;
    const int bm = (MODE==3) ? 0 : blockIdx.y * 128;

    // batch decode for MODE 3
    int bb = 0, cc = 0;
    const float* Abase = A;
    if (MODE == 3) {
        int batch = blockIdx.z;
        bb = batch >> 4; cc = batch & 15;
        Abase = A + (size_t)batch * 16384;   // attn[b,c] 128x128
    }

    float acc[2][8][4];
    #pragma unroll
    for (int mt = 0; mt < 2; mt++)
        #pragma unroll
        for (int nt = 0; nt < 8; nt++)
            #pragma unroll
            for (int e = 0; e < 4; e++) acc[mt][nt][e] = 0.f;

    for (int k0 = 0; k0 < K; k0 += 32) {
        // ---- load A tile (128 x 32 fp32 -> split bf16) ----
        #pragma unroll
        for (int e = 0; e < 4; e++) {
            int idx = t + e*256;           // 0..1023 over [128][8 float4]
            int r = idx >> 3;
            int kk = (idx & 7) * 4;
            float4 av;
            int m = bm + r;
            if (MODE == 2) {
                float4 hv = *(const float4*)&g_h[(size_t)m*H_ + k0 + kk];
                float4 rv = *(const float4*)&g_base[(size_t)m*NBASE + 640 + k0 + kk];
                av = make_float4(hv.x*rv.x, hv.y*rv.y, hv.z*rv.z, hv.w*rv.w);
            } else if (MODE == 3) {
                av = *(const float4*)&Abase[r*128 + k0 + kk];
            } else if (MODE == 1) {
                av = *(const float4*)&g_mx[(size_t)m*D_ + k0 + kk];
            } else {
                av = *(const float4*)&A[(size_t)m*D_ + k0 + kk];
            }
            split2(av.x, Ah[r][kk+0], Al[r][kk+0]);
            split2(av.y, Ah[r][kk+1], Al[r][kk+1]);
            split2(av.z, Ah[r][kk+2], Al[r][kk+2]);
            split2(av.w, Ah[r][kk+3], Al[r][kk+3]);
        }
        // ---- load B tile (32 x 128 fp32 -> transposed split bf16) ----
        #pragma unroll
        for (int e = 0; e < 4; e++) {
            int idx = t + e*256;           // over [32 k][32 float4 n]
            int r = idx >> 5;              // k within tile
            int n = (idx & 31) * 4;
            float4 bv;
            if (MODE == 3) {
                bv = *(const float4*)&g_v[(size_t)((cc*128 + k0 + r)*B_ + bb)*H_ + bn + n];
            } else {
                bv = *(const float4*)&Bm[(size_t)(k0 + r)*N + bn + n];
            }
            split2(bv.x, Bh[n+0][r], Bl[n+0][r]);
            split2(bv.y, Bh[n+1][r], Bl[n+1][r]);
            split2(bv.z, Bh[n+2][r], Bl[n+2][r]);
            split2(bv.w, Bh[n+3][r], Bl[n+3][r]);
        }
        __syncthreads();

        #pragma unroll
        for (int ks = 0; ks < 2; ks++) {
            uint32_t afh[2][4], afl[2][4];
            #pragma unroll
            for (int mt = 0; mt < 2; mt++) {
                int row = wm*32 + mt*16 + group;
                int col = ks*16 + tid4*2;
                afh[mt][0] = *(const uint32_t*)&Ah[row  ][col  ];
                afh[mt][1] = *(const uint32_t*)&Ah[row+8][col  ];
                afh[mt][2] = *(const uint32_t*)&Ah[row  ][col+8];
                afh[mt][3] = *(const uint32_t*)&Ah[row+8][col+8];
                afl[mt][0] = *(const uint32_t*)&Al[row  ][col  ];
                afl[mt][1] = *(const uint32_t*)&Al[row+8][col  ];
                afl[mt][2] = *(const uint32_t*)&Al[row  ][col+8];
                afl[mt][3] = *(const uint32_t*)&Al[row+8][col+8];
            }
            #pragma unroll
            for (int nt = 0; nt < 8; nt++) {
                int n = wn*64 + nt*8 + group;
                int kk = ks*16 + tid4*2;
                uint32_t bh0 = *(const uint32_t*)&Bh[n][kk];
                uint32_t bh1 = *(const uint32_t*)&Bh[n][kk+8];
                uint32_t bl0 = *(const uint32_t*)&Bl[n][kk];
                uint32_t bl1 = *(const uint32_t*)&Bl[n][kk+8];
                #pragma unroll
                for (int mt = 0; mt < 2; mt++) {
                    MMA16816(acc[mt][nt], afh[mt], bh0, bh1);
                    MMA16816(acc[mt][nt], afh[mt], bl0, bl1);
                    MMA16816(acc[mt][nt], afl[mt], bh0, bh1);
                }
            }
        }
        __syncthreads();
    }

    // ---- epilogue ----
    #pragma unroll
    for (int mt = 0; mt < 2; mt++) {
        #pragma unroll
        for (int nt = 0; nt < 8; nt++) {
            #pragma unroll
            for (int half = 0; half < 2; half++) {          // row, row+8
                int m = bm + wm*32 + mt*16 + group + half*8;
                #pragma unroll
                for (int e = 0; e < 2; e++) {               // col, col+1
                    int n = bn + wn*64 + nt*8 + tid4*2 + e;
                    float v = acc[mt][nt][half*2 + e];
                    if (MODE == 0) {
                        g_v[(size_t)m*H_ + n] = siluf(v + bias[n]);
                    } else if (MODE == 1) {
                        v += bias[n];
                        if (n < 512)       v = sigmf(v);
                        else if (n < 1664) v = siluf(v);
                        g_base[(size_t)m*NBASE + n] = v;
                    } else if (MODE == 2) {
                        float hx = g_base[(size_t)m*NBASE + 1664 + n];
                        float s  = siluf(v + bias[n] + hx);
                        float u  = g_base[(size_t)m*NBASE + n];
                        float xr = A[(size_t)m*D_ + n];     // A = x (residual)
                        g_o[(size_t)m*D_ + n] = xr + u*(s - xr);
                    } else {
                        g_h[(size_t)((cc*128 + m)*B_ + bb)*H_ + n] = v;
                    }
                }
            }
        }
    }
}

// ---------------- QK + softmax: writes attn probs ----------------
__global__ void __launch_bounds__(256) qk_kernel(
    const float* __restrict__ qkg, const float* __restrict__ qkb,
    const float* __restrict__ rp, float* __restrict__ attn_out)
{
    extern __shared__ float sm[];
    float* qT = sm;             // [z][i] 128*128
    float* kT = sm + 16384;     // [z][j] 128*128
    float* sT = sm + 32768;     // [j][i] stride 132

    const int b = blockIdx.x >> 4;
    const int c = blockIdx.x & 15;
    const int t = threadIdx.x;
    const float qscale = 0.08838834764831845f;   // 128^-0.5

    for (int idx = t; idx < 16384; idx += 256) {
        int i = idx >> 7, z = idx & 127;
        int row = (c*128 + i)*B_ + b;
        float zv = g_base[(size_t)row*NBASE + 512 + z];
        qT[z*128 + i] = (zv*qkg[z]     + qkb[z]    ) * qscale;
        kT[z*128 + i] =  zv*qkg[128+z] + qkb[128+z];
    }
    __syncthreads();

    const int tx = t & 15, ty = t >> 4;
    const int i0 = ty*8, j0 = tx*8;

    float acc[8][8];
    #pragma unroll
    for (int i = 0; i < 8; i++)
        #pragma unroll
        for (int j = 0; j < 8; j++) acc[i][j] = 0.f;

    #pragma unroll 4
    for (int z = 0; z < 128; z++) {
        float qa[8], ka[8];
        *(float4*)(qa)   = *(const float4*)&qT[z*128 + i0];
        *(float4*)(qa+4) = *(const float4*)&qT[z*128 + i0 + 4];
        *(float4*)(ka)   = *(const float4*)&kT[z*128 + j0];
        *(float4*)(ka+4) = *(const float4*)&kT[z*128 + j0 + 4];
        #pragma unroll
        for (int i = 0; i < 8; i++)
            #pragma unroll
            for (int j = 0; j < 8; j++)
                acc[i][j] = fmaf(qa[i], ka[j], acc[i][j]);
    }
    #pragma unroll
    for (int r = 0; r < 8; r++)
        #pragma unroll
        for (int cc = 0; cc < 8; cc++) {
            int i = i0 + r, j = j0 + cc;
            sT[j*132 + i] = acc[r][cc] + rp[1023 + j - i];
        }
    __syncthreads();

    if (t < 128) {
        const int i = t;
        float mx = -1e30f;
        for (int j = 0; j < 128; j++) mx = fmaxf(mx, sT[j*132 + i]);
        float ssum = 0.f;
        for (int j = 0; j < 128; j++) {
            float e = expf(sT[j*132 + i] - mx);
            sT[j*132 + i] = e;
            ssum += e;
        }
        float inv = 1.f/ssum;
        for (int j = 0; j < 128; j++) sT[j*132 + i] *= inv;
    }
    __syncthreads();

    float* aout = attn_out + (size_t)(b*NC_ + c)*16384;
    for (int idx = t; idx < 16384; idx += 256) {
        int i = idx >> 7, j = idx & 127;
        aout[idx] = sT[j*132 + i];
    }
}

// ---------------- final rmsnorm (one warp per row) ----------------
__global__ void __launch_bounds__(256) norm_kernel(
    const float* __restrict__ ns, float* __restrict__ out)
{
    int row  = blockIdx.x*8 + (threadIdx.x >> 5);
    int lane = threadIdx.x & 31;
    const float* op = g_o + (size_t)row*512;
    float vals[16];
    float ss = 0.f;
    #pragma unroll
    for (int k = 0; k < 16; k++) {
        float v = op[lane + k*32];
        vals[k] = v;
        ss += v*v;
    }
    #pragma unroll
    for (int off = 16; off; off >>= 1) ss += __shfl_xor_sync(0xffffffffu, ss, off);
    float scale = ns[0] * rsqrtf(ss*(1.f/512.f) + 1e-6f);
    float* outp = out + (size_t)row*512;
    #pragma unroll
    for (int k = 0; k < 16; k++) outp[lane + k*32] = vals[k]*scale;
}

// ---------------- launch ----------------
extern "C" void kernel_launch(void* const* d_in, const int* in_sizes, int n_in,
                              void* d_out, int out_size)
{
    const float* x   = (const float*)d_in[0];
    const float* edl = (const float*)d_in[1];
    const float* eal = (const float*)d_in[2];
    const float* ebt = (const float*)d_in[3];
    const float* egm = (const float*)d_in[4];
    const float* eom = (const float*)d_in[5];
    const float* Wv  = (const float*)d_in[6];
    const float* bv  = (const float*)d_in[7];
    const float* Wmx = (const float*)d_in[8];
    const float* bmx = (const float*)d_in[9];
    const float* Wh  = (const float*)d_in[10];
    const float* bh  = (const float*)d_in[11];
    const float* qkg = (const float*)d_in[12];
    const float* qkb = (const float*)d_in[13];
    const float* rp  = (const float*)d_in[14];
    const float* ns  = (const float*)d_in[15];

    float* out      = (float*)d_out;
    float* attn_out = out + (size_t)L_*B_*D_;

    cudaFuncSetAttribute(qk_kernel, cudaFuncAttributeMaxDynamicSharedMemorySize, 198656);

    ema_fwd<<<32, 256>>>(x, edl, eal, ebt, egm, eom);
    ema_bwd<<<32, 256>>>(x, edl, eal, ebt, egm);

    { dim3 g(1024/128, MROWS/128); mma_gemm<0><<<g, 256>>>(x, Wv, bv); }
    { dim3 g(2176/128, MROWS/128); mma_gemm<1><<<g, 256>>>(nullptr, Wmx, bmx); }

    qk_kernel<<<B_*NC_, 256, 198656>>>(qkg, qkb, rp, attn_out);

    { dim3 g(1024/128, 1, 256);   mma_gemm<3><<<g, 256>>>(attn_out, nullptr, nullptr); }
    { dim3 g(512/128, MROWS/128); mma_gemm<2><<<g, 256>>>(x, Wh, bh); }

    norm_kernel<<<MROWS/8, 256>>>(ns, out);
}

// round 4
// speedup vs baseline: 1.5732x; 1.1954x over previous
#include <cuda_runtime.h>
#include <cuda_bf16.h>
#include <stdint.h>
#include <math.h>

#define L_ 2048
#define B_ 16
#define D_ 512
#define H_ 1024
#define Z_ 128
#define NC_ 16
#define NBASE 2176            // Z + H + 2D
#define MROWS (L_*B_)         // 32768

// ---------------- fp32 scratch ----------------
__device__ float g_tmp [MROWS*D_];     // ema fwd partial
__device__ float g_v   [MROWS*H_];     // silu(x@Wv+bv) fp32 (consumed by conv_v)
__device__ float g_base[MROWS*NBASE];  // activated base: [u | z | r | hx]
__device__ float g_o   [MROWS*D_];     // pre-norm output

// ---------------- split-bf16 planes ----------------
__device__ __nv_bfloat16 xs_h [MROWS*D_],  xs_l [MROWS*D_];    // x
__device__ __nv_bfloat16 mxs_h[MROWS*D_],  mxs_l[MROWS*D_];    // silu(ema)
__device__ __nv_bfloat16 vs_h [MROWS*H_],  vs_l [MROWS*H_];    // v transposed [b*16+c][h][j]
__device__ __nv_bfloat16 hr_h [MROWS*H_],  hr_l [MROWS*H_];    // h*r
__device__ __nv_bfloat16 at_h [B_*NC_*128*128], at_l[B_*NC_*128*128]; // attn probs
__device__ __nv_bfloat16 wv_h [1024*512],  wv_l [1024*512];    // Wv^T  [n][k]
__device__ __nv_bfloat16 wmx_h[2176*512],  wmx_l[2176*512];    // Wmx^T [n][k]
__device__ __nv_bfloat16 wh_h [512*1024],  wh_l [512*1024];    // Wh^T  [n][k]

__device__ __forceinline__ float sigmf(float x){ return 1.0f/(1.0f + expf(-x)); }
__device__ __forceinline__ float siluf(float x){ return x/(1.0f + expf(-x)); }
__device__ __forceinline__ void split2(float v, __nv_bfloat16& h, __nv_bfloat16& l){
    h = __float2bfloat16_rn(v);
    l = __float2bfloat16_rn(v - __bfloat162float(h));
}

#define MMA16816(d, a, b0, b1) \
  asm volatile("mma.sync.aligned.m16n8k16.row.col.f32.bf16.bf16.f32 " \
    "{%0,%1,%2,%3}, {%4,%5,%6,%7}, {%8,%9}, {%0,%1,%2,%3};" \
    : "+f"(d[0]), "+f"(d[1]), "+f"(d[2]), "+f"(d[3]) \
    : "r"(a[0]), "r"(a[1]), "r"(a[2]), "r"(a[3]), "r"(b0), "r"(b1))

#define LDSM4(r0,r1,r2,r3,a) \
  asm volatile("ldmatrix.sync.aligned.m8n8.x4.shared.b16 {%0,%1,%2,%3}, [%4];" \
    : "=r"(r0),"=r"(r1),"=r"(r2),"=r"(r3) : "r"(a))

#define CPA16(s,g) asm volatile("cp.async.cg.shared.global [%0], [%1], 16;" :: "r"(s), "l"(g))

// ---------------- weight transpose + split: W[k][n] -> Wt_h/l[n][k] ----------------
__global__ void __launch_bounds__(256) conv_w(
    const float* __restrict__ W, __nv_bfloat16* __restrict__ oh,
    __nv_bfloat16* __restrict__ ol, int K, int N)
{
    __shared__ float tile[32][33];
    int n0 = blockIdx.x*32, k0 = blockIdx.y*32;
    int tx = threadIdx.x & 31, ty = threadIdx.x >> 5;
    #pragma unroll
    for (int i = 0; i < 4; i++) {
        int k = ty + i*8;
        tile[k][tx] = W[(size_t)(k0 + k)*N + n0 + tx];
    }
    __syncthreads();
    #pragma unroll
    for (int i = 0; i < 4; i++) {
        int n = ty + i*8;
        float v = tile[tx][n];
        __nv_bfloat16 h, l; split2(v, h, l);
        size_t o = (size_t)(n0 + n)*K + k0 + tx;
        oh[o] = h; ol[o] = l;
    }
}

// ---------------- elementwise split of x ----------------
__global__ void __launch_bounds__(256) conv_x(const float* __restrict__ x)
{
    int i4 = blockIdx.x*256 + threadIdx.x;      // float4 index
    float4 v = *(const float4*)&x[(size_t)i4*4];
    int o = i4*4;
    split2(v.x, xs_h[o+0], xs_l[o+0]);
    split2(v.y, xs_h[o+1], xs_l[o+1]);
    split2(v.z, xs_h[o+2], xs_l[o+2]);
    split2(v.w, xs_h[o+3], xs_l[o+3]);
}

// ---------------- EMA: forward scan ----------------
__global__ void __launch_bounds__(256) ema_fwd(
    const float* __restrict__ x, const float* __restrict__ dlt,
    const float* __restrict__ alp, const float* __restrict__ bet,
    const float* __restrict__ gam, const float* __restrict__ omg)
{
    int tid = blockIdx.x*256 + threadIdx.x;   // 0..8191
    int b = tid >> 9, d = tid & 511;
    int i0 = d*2, i1 = d*2 + 1;
    float p0 = sigmf(dlt[i0]), p1 = sigmf(dlt[i1]);
    float q0 = 1.f - p0*sigmf(alp[i0]);
    float q1 = 1.f - p1*sigmf(alp[i1]);
    const float invs = 0.7071067811865476f;
    float w0 = p0*bet[i0]*gam[i0]*invs;
    float w1 = p1*bet[i1]*gam[i1]*invs;
    float ow = omg[d];
    float f0 = 0.f, f1 = 0.f;
    int idx = b*512 + d;
    #pragma unroll 8
    for (int l = 0; l < L_; ++l, idx += 8192) {
        float xv = x[idx];
        f0 = fmaf(q0, f0, xv);
        f1 = fmaf(q1, f1, xv);
        g_tmp[idx] = fmaf(w0, f0, fmaf(w1, f1, xv*ow));
    }
}

// ---------------- EMA: backward scan + silu -> split-bf16 planes ----------------
__global__ void __launch_bounds__(256) ema_bwd(
    const float* __restrict__ x, const float* __restrict__ dlt,
    const float* __restrict__ alp, const float* __restrict__ bet,
    const float* __restrict__ gam)
{
    int tid = blockIdx.x*256 + threadIdx.x;
    int b = tid >> 9, d = tid & 511;
    int i0 = (512 + d)*2, i1 = i0 + 1;
    float p0 = sigmf(dlt[i0]), p1 = sigmf(dlt[i1]);
    float q0 = 1.f - p0*sigmf(alp[i0]);
    float q1 = 1.f - p1*sigmf(alp[i1]);
    const float invs = 0.7071067811865476f;
    float w0 = p0*bet[i0]*gam[i0]*invs;
    float w1 = p1*bet[i1]*gam[i1]*invs;
    float f0 = 0.f, f1 = 0.f;
    int idx = (L_-1)*8192 + b*512 + d;
    #pragma unroll 8
    for (int l = 0; l < L_; ++l, idx -= 8192) {
        float xv = x[idx];
        f0 = fmaf(q0, f0, xv);
        f1 = fmaf(q1, f1, xv);
        float y = g_tmp[idx] + fmaf(w0, f0, w1*f1);
        split2(siluf(y), mxs_h[idx], mxs_l[idx]);
    }
}

// ---------------- transpose g_v -> vs planes [batch][h][j] ----------------
__global__ void __launch_bounds__(256) conv_v()
{
    extern __shared__ float tl[];            // [128][129]
    int batch = blockIdx.x >> 3;
    int hc    = blockIdx.x & 7;
    int bb = batch >> 4, cc = batch & 15;
    int t = threadIdx.x;
    for (int q = t; q < 128*32; q += 256) {
        int j = q >> 5, h4 = (q & 31)*4;
        float4 v = *(const float4*)&g_v[(size_t)((cc*128 + j)*B_ + bb)*H_ + hc*128 + h4];
        tl[j*129 + h4+0] = v.x; tl[j*129 + h4+1] = v.y;
        tl[j*129 + h4+2] = v.z; tl[j*129 + h4+3] = v.w;
    }
    __syncthreads();
    size_t base = (size_t)batch*131072 + (size_t)hc*128*128;
    #pragma unroll
    for (int e = 0; e < 64; e++) {
        int idx = e*256 + t;
        int hh = idx >> 7, j = idx & 127;
        split2(tl[j*129 + hh], vs_h[base + hh*128 + j], vs_l[base + hh*128 + j]);
    }
}

// ---------------- pipelined bf16 tensor-core GEMM ----------------
// 128x128x32 tile, 8 warps (4m x 2n), cp.async double-buffer, ldmatrix.x4
// MODE 0: g_v   = silu(xs @ wv^T + bv)            N=1024 K=512
// MODE 1: g_base= act(mxs @ wmx^T + bmx)          N=2176 K=512
// MODE 2: g_o   = gate(silu(hr @ wh^T + bh + hx)) N=512  K=1024
// MODE 3: hr    = (attn @ v) * r   (256 batches)  N=1024 K=128
template<int MODE>
__global__ void __launch_bounds__(256, 2) mma_gemm(
    const float* __restrict__ Xres, const float* __restrict__ bias)
{
    constexpr int K = (MODE==2) ? 1024 : (MODE==3) ? 128 : 512;
    constexpr int NK = K/32;
    constexpr int STAGE = 40960;             // 4 planes * 128 rows * 80B

    extern __shared__ __align__(128) char smem_raw[];
    const uint32_t sb = (uint32_t)__cvta_generic_to_shared(smem_raw);

    const int t = threadIdx.x;
    const int warp = t >> 5, lane = t & 31;
    const int wm = warp & 3, wn = warp >> 2;
    const int group = lane >> 2, tid4 = lane & 3;

    const int bn = blockIdx.x * 128;
    const int bm = (MODE==3) ? 0 : blockIdx.y * 128;

    int bb = 0, cc = 0, batch = 0;
    if (MODE == 3) { batch = blockIdx.z; bb = batch >> 4; cc = batch & 15; }

    const __nv_bfloat16 *pAh, *pAl, *pBh, *pBl;
    if (MODE == 0) { pAh = xs_h  + (size_t)bm*K; pAl = xs_l  + (size_t)bm*K;
                     pBh = wv_h  + (size_t)bn*K; pBl = wv_l  + (size_t)bn*K; }
    else if (MODE == 1) { pAh = mxs_h + (size_t)bm*K; pAl = mxs_l + (size_t)bm*K;
                          pBh = wmx_h + (size_t)bn*K; pBl = wmx_l + (size_t)bn*K; }
    else if (MODE == 2) { pAh = hr_h  + (size_t)bm*K; pAl = hr_l  + (size_t)bm*K;
                          pBh = wh_h  + (size_t)bn*K; pBl = wh_l  + (size_t)bn*K; }
    else { pAh = at_h + (size_t)batch*16384;  pAl = at_l + (size_t)batch*16384;
           pBh = vs_h + (size_t)batch*131072 + (size_t)bn*K;
           pBl = vs_l + (size_t)batch*131072 + (size_t)bn*K; }

    // per-thread cp.async assignments: 8 chunks (2 per plane)
    const __nv_bfloat16* gB[8];
    uint32_t sO[8];
    #pragma unroll
    for (int e = 0; e < 8; e++) {
        int plane = e >> 1;
        int idx = ((e & 1) << 8) | t;      // 0..511
        int r = idx >> 2, c = idx & 3;
        const __nv_bfloat16* base = (plane==0)?pAh:(plane==1)?pAl:(plane==2)?pBh:pBl;
        gB[e] = base + (size_t)r*K + c*8;
        sO[e] = sb + plane*10240 + r*80 + (((uint32_t)(c ^ (r & 3))) << 4);
    }

    const int mat = lane >> 3, rim = lane & 7;
    const int arow_base = wm*32 + (mat & 1)*8 + rim;
    const int ac_sel = mat >> 1;
    const int axor = arow_base & 3;
    const int brow_base = wn*64 + ((mat >> 1) << 3) + rim;
    const int bc_sel = mat & 1;
    const int bxor = brow_base & 3;

    float acc[2][8][4];
    #pragma unroll
    for (int mt = 0; mt < 2; mt++)
        #pragma unroll
        for (int nt = 0; nt < 8; nt++)
            #pragma unroll
            for (int e = 0; e < 4; e++) acc[mt][nt][e] = 0.f;

    #pragma unroll
    for (int e = 0; e < 8; e++) CPA16(sO[e], gB[e]);
    asm volatile("cp.async.commit_group;");

    for (int it = 0; it < NK; it++) {
        if (it + 1 < NK) {
            uint32_t so = ((it + 1) & 1) * STAGE;
            int ko = (it + 1) * 32;
            #pragma unroll
            for (int e = 0; e < 8; e++) CPA16(sO[e] + so, gB[e] + ko);
            asm volatile("cp.async.commit_group;");
            asm volatile("cp.async.wait_group 1;");
        } else {
            asm volatile("cp.async.wait_group 0;");
        }
        __syncthreads();

        const uint32_t stg = sb + (it & 1)*STAGE;
        #pragma unroll
        for (int ks = 0; ks < 2; ks++) {
            uint32_t ah[2][4], al[2][4];
            #pragma unroll
            for (int mt = 0; mt < 2; mt++) {
                int row = arow_base + mt*16;
                int c = ks*2 + ac_sel;
                uint32_t ad = stg + row*80 + (((uint32_t)(c ^ axor)) << 4);
                LDSM4(ah[mt][0], ah[mt][1], ah[mt][2], ah[mt][3], ad);
                LDSM4(al[mt][0], al[mt][1], al[mt][2], al[mt][3], ad + 10240);
            }
            #pragma unroll
            for (int g = 0; g < 4; g++) {
                int row = brow_base + g*16;
                int c = ks*2 + bc_sel;
                uint32_t bd = stg + 2*10240 + row*80 + (((uint32_t)(c ^ bxor)) << 4);
                uint32_t bh0,bh1,bh2,bh3, bl0,bl1,bl2,bl3;
                LDSM4(bh0,bh1,bh2,bh3, bd);
                LDSM4(bl0,bl1,bl2,bl3, bd + 10240);
                #pragma unroll
                for (int mt = 0; mt < 2; mt++) {
                    MMA16816(acc[mt][2*g],   ah[mt], bh0, bh1);
                    MMA16816(acc[mt][2*g],   ah[mt], bl0, bl1);
                    MMA16816(acc[mt][2*g],   al[mt], bh0, bh1);
                    MMA16816(acc[mt][2*g+1], ah[mt], bh2, bh3);
                    MMA16816(acc[mt][2*g+1], ah[mt], bl2, bl3);
                    MMA16816(acc[mt][2*g+1], al[mt], bh2, bh3);
                }
            }
        }
        __syncthreads();
    }

    // ---- epilogue ----
    #pragma unroll
    for (int mt = 0; mt < 2; mt++) {
        #pragma unroll
        for (int nt = 0; nt < 8; nt++) {
            #pragma unroll
            for (int half = 0; half < 2; half++) {
                int m = bm + wm*32 + mt*16 + group + half*8;
                #pragma unroll
                for (int e = 0; e < 2; e++) {
                    int n = bn + wn*64 + nt*8 + tid4*2 + e;
                    float v = acc[mt][nt][half*2 + e];
                    if (MODE == 0) {
                        g_v[(size_t)m*H_ + n] = siluf(v + bias[n]);
                    } else if (MODE == 1) {
                        v += bias[n];
                        if (n < 512)       v = sigmf(v);
                        else if (n < 1664) v = siluf(v);
                        g_base[(size_t)m*NBASE + n] = v;
                    } else if (MODE == 2) {
                        float hx = g_base[(size_t)m*NBASE + 1664 + n];
                        float s  = siluf(v + bias[n] + hx);
                        float u  = g_base[(size_t)m*NBASE + n];
                        float xr = Xres[(size_t)m*D_ + n];
                        g_o[(size_t)m*D_ + n] = xr + u*(s - xr);
                    } else {
                        size_t row = (size_t)(cc*128 + m)*B_ + bb;
                        float rv = g_base[row*NBASE + 640 + n];
                        split2(v*rv, hr_h[row*H_ + n], hr_l[row*H_ + n]);
                    }
                }
            }
        }
    }
}

// ---------------- QK + softmax ----------------
__global__ void __launch_bounds__(256) qk_kernel(
    const float* __restrict__ qkg, const float* __restrict__ qkb,
    const float* __restrict__ rp, float* __restrict__ attn_out)
{
    extern __shared__ float sm[];
    float* qT = sm;             // [z][i] 128*128
    float* kT = sm + 16384;     // [z][j] 128*128
    float* sT = sm + 32768;     // [j][i] stride 132

    const int b = blockIdx.x >> 4;
    const int c = blockIdx.x & 15;
    const int t = threadIdx.x;
    const float qscale = 0.08838834764831845f;

    for (int idx = t; idx < 16384; idx += 256) {
        int i = idx >> 7, z = idx & 127;
        int row = (c*128 + i)*B_ + b;
        float zv = g_base[(size_t)row*NBASE + 512 + z];
        qT[z*128 + i] = (zv*qkg[z]     + qkb[z]    ) * qscale;
        kT[z*128 + i] =  zv*qkg[128+z] + qkb[128+z];
    }
    __syncthreads();

    const int tx = t & 15, ty = t >> 4;
    const int i0 = ty*8, j0 = tx*8;

    float acc[8][8];
    #pragma unroll
    for (int i = 0; i < 8; i++)
        #pragma unroll
        for (int j = 0; j < 8; j++) acc[i][j] = 0.f;

    #pragma unroll 4
    for (int z = 0; z < 128; z++) {
        float qa[8], ka[8];
        *(float4*)(qa)   = *(const float4*)&qT[z*128 + i0];
        *(float4*)(qa+4) = *(const float4*)&qT[z*128 + i0 + 4];
        *(float4*)(ka)   = *(const float4*)&kT[z*128 + j0];
        *(float4*)(ka+4) = *(const float4*)&kT[z*128 + j0 + 4];
        #pragma unroll
        for (int i = 0; i < 8; i++)
            #pragma unroll
            for (int j = 0; j < 8; j++)
                acc[i][j] = fmaf(qa[i], ka[j], acc[i][j]);
    }
    #pragma unroll
    for (int r = 0; r < 8; r++)
        #pragma unroll
        for (int cc = 0; cc < 8; cc++) {
            int i = i0 + r, j = j0 + cc;
            sT[j*132 + i] = acc[r][cc] + rp[1023 + j - i];
        }
    __syncthreads();

    if (t < 128) {
        const int i = t;
        float mx = -1e30f;
        for (int j = 0; j < 128; j++) mx = fmaxf(mx, sT[j*132 + i]);
        float ssum = 0.f;
        for (int j = 0; j < 128; j++) {
            float e = expf(sT[j*132 + i] - mx);
            sT[j*132 + i] = e;
            ssum += e;
        }
        float inv = 1.f/ssum;
        for (int j = 0; j < 128; j++) sT[j*132 + i] *= inv;
    }
    __syncthreads();

    size_t base = (size_t)(b*NC_ + c)*16384;
    float* aout = attn_out + base;
    for (int idx = t; idx < 16384; idx += 256) {
        int i = idx >> 7, j = idx & 127;
        float p = sT[j*132 + i];
        aout[idx] = p;
        split2(p, at_h[base + idx], at_l[base + idx]);
    }
}

// ---------------- final rmsnorm ----------------
__global__ void __launch_bounds__(256) norm_kernel(
    const float* __restrict__ ns, float* __restrict__ out)
{
    int row  = blockIdx.x*8 + (threadIdx.x >> 5);
    int lane = threadIdx.x & 31;
    const float* op = g_o + (size_t)row*512;
    float vals[16];
    float ss = 0.f;
    #pragma unroll
    for (int k = 0; k < 16; k++) {
        float v = op[lane + k*32];
        vals[k] = v;
        ss += v*v;
    }
    #pragma unroll
    for (int off = 16; off; off >>= 1) ss += __shfl_xor_sync(0xffffffffu, ss, off);
    float scale = ns[0] * rsqrtf(ss*(1.f/512.f) + 1e-6f);
    float* outp = out + (size_t)row*512;
    #pragma unroll
    for (int k = 0; k < 16; k++) outp[lane + k*32] = vals[k]*scale;
}

// ---------------- launch ----------------
extern "C" void kernel_launch(void* const* d_in, const int* in_sizes, int n_in,
                              void* d_out, int out_size)
{
    const float* x   = (const float*)d_in[0];
    const float* edl = (const float*)d_in[1];
    const float* eal = (const float*)d_in[2];
    const float* ebt = (const float*)d_in[3];
    const float* egm = (const float*)d_in[4];
    const float* eom = (const float*)d_in[5];
    const float* Wv  = (const float*)d_in[6];
    const float* bv  = (const float*)d_in[7];
    const float* Wmx = (const float*)d_in[8];
    const float* bmx = (const float*)d_in[9];
    const float* Wh  = (const float*)d_in[10];
    const float* bh  = (const float*)d_in[11];
    const float* qkg = (const float*)d_in[12];
    const float* qkb = (const float*)d_in[13];
    const float* rp  = (const float*)d_in[14];
    const float* ns  = (const float*)d_in[15];

    float* out      = (float*)d_out;
    float* attn_out = out + (size_t)L_*B_*D_;

    static __nv_bfloat16 *d_wvh=nullptr,*d_wvl=nullptr,*d_wmxh=nullptr,*d_wmxl=nullptr,*d_whh=nullptr,*d_whl=nullptr;
    if (!d_wvh) {
        cudaGetSymbolAddress((void**)&d_wvh,  wv_h);
        cudaGetSymbolAddress((void**)&d_wvl,  wv_l);
        cudaGetSymbolAddress((void**)&d_wmxh, wmx_h);
        cudaGetSymbolAddress((void**)&d_wmxl, wmx_l);
        cudaGetSymbolAddress((void**)&d_whh,  wh_h);
        cudaGetSymbolAddress((void**)&d_whl,  wh_l);
        cudaFuncSetAttribute(qk_kernel, cudaFuncAttributeMaxDynamicSharedMemorySize, 198656);
        cudaFuncSetAttribute(conv_v,    cudaFuncAttributeMaxDynamicSharedMemorySize, 66048);
        cudaFuncSetAttribute(mma_gemm<0>, cudaFuncAttributeMaxDynamicSharedMemorySize, 81920);
        cudaFuncSetAttribute(mma_gemm<1>, cudaFuncAttributeMaxDynamicSharedMemorySize, 81920);
        cudaFuncSetAttribute(mma_gemm<2>, cudaFuncAttributeMaxDynamicSharedMemorySize, 81920);
        cudaFuncSetAttribute(mma_gemm<3>, cudaFuncAttributeMaxDynamicSharedMemorySize, 81920);
    }

    { dim3 g(1024/32, 512/32);  conv_w<<<g, 256>>>(Wv,  d_wvh,  d_wvl,  512,  1024); }
    { dim3 g(2176/32, 512/32);  conv_w<<<g, 256>>>(Wmx, d_wmxh, d_wmxl, 512,  2176); }
    { dim3 g(512/32,  1024/32); conv_w<<<g, 256>>>(Wh,  d_whh,  d_whl,  1024, 512);  }

    conv_x<<<16384, 256>>>(x);

    ema_fwd<<<32, 256>>>(x, edl, eal, ebt, egm, eom);
    ema_bwd<<<32, 256>>>(x, edl, eal, ebt, egm);

    { dim3 g(8, 256);  mma_gemm<0><<<g, 256, 81920>>>(x, bv); }
    conv_v<<<2048, 256, 66048>>>();

    { dim3 g(17, 256); mma_gemm<1><<<g, 256, 81920>>>(x, bmx); }

    qk_kernel<<<B_*NC_, 256, 198656>>>(qkg, qkb, rp, attn_out);

    { dim3 g(8, 1, 256); mma_gemm<3><<<g, 256, 81920>>>(x, bv); }
    { dim3 g(4, 256);    mma_gemm<2><<<g, 256, 81920>>>(x, bh); }

    norm_kernel<<<MROWS/8, 256>>>(ns, out);
}

// round 5
// speedup vs baseline: 1.6979x; 1.0793x over previous
#include <cuda_runtime.h>
#include <cuda_bf16.h>
#include <stdint.h>
#include <math.h>

#define L_ 2048
#define B_ 16
#define D_ 512
#define H_ 1024
#define NC_ 16
#define NBASE 2176            // Z + H + 2D
#define MROWS (L_*B_)         // 32768

// ---------------- fp32 scratch ----------------
__device__ float g_tmp [MROWS*D_];     // ema fwd partial
__device__ float g_base[MROWS*NBASE];  // activated base: [u | z | r | hx]
__device__ float g_o   [MROWS*D_];     // pre-norm output

// ---------------- split-bf16 planes (all natural layout) ----------------
__device__ __align__(16) __nv_bfloat16 xs_h [MROWS*D_],  xs_l [MROWS*D_];
__device__ __align__(16) __nv_bfloat16 mxs_h[MROWS*D_],  mxs_l[MROWS*D_];
__device__ __align__(16) __nv_bfloat16 vs_h [MROWS*H_],  vs_l [MROWS*H_];   // v [m][h]
__device__ __align__(16) __nv_bfloat16 hr_h [MROWS*H_],  hr_l [MROWS*H_];   // h*r [m][h]
__device__ __align__(16) __nv_bfloat16 at_h [B_*NC_*128*128], at_l[B_*NC_*128*128];
__device__ __align__(16) __nv_bfloat16 wv_h [512*1024],  wv_l [512*1024];   // [k][n]
__device__ __align__(16) __nv_bfloat16 wmx_h[512*2176],  wmx_l[512*2176];   // [k][n]
__device__ __align__(16) __nv_bfloat16 wh_h [1024*512],  wh_l [1024*512];   // [k][n]

__device__ __forceinline__ float sigmf(float x){ return 1.0f/(1.0f + expf(-x)); }
__device__ __forceinline__ float siluf(float x){ return x/(1.0f + expf(-x)); }
__device__ __forceinline__ void split2(float v, __nv_bfloat16& h, __nv_bfloat16& l){
    h = __float2bfloat16_rn(v);
    l = __float2bfloat16_rn(v - __bfloat162float(h));
}

#define MMA16816(d, a, b0, b1) \
  asm volatile("mma.sync.aligned.m16n8k16.row.col.f32.bf16.bf16.f32 " \
    "{%0,%1,%2,%3}, {%4,%5,%6,%7}, {%8,%9}, {%0,%1,%2,%3};" \
    : "+f"(d[0]), "+f"(d[1]), "+f"(d[2]), "+f"(d[3]) \
    : "r"(a[0]), "r"(a[1]), "r"(a[2]), "r"(a[3]), "r"(b0), "r"(b1))

#define LDSM4(r0,r1,r2,r3,a) \
  asm volatile("ldmatrix.sync.aligned.m8n8.x4.shared.b16 {%0,%1,%2,%3}, [%4];" \
    : "=r"(r0),"=r"(r1),"=r"(r2),"=r"(r3) : "r"(a))

#define LDSM4T(r0,r1,r2,r3,a) \
  asm volatile("ldmatrix.sync.aligned.m8n8.x4.trans.shared.b16 {%0,%1,%2,%3}, [%4];" \
    : "=r"(r0),"=r"(r1),"=r"(r2),"=r"(r3) : "r"(a))

#define CPA16(s,g) asm volatile("cp.async.cg.shared.global [%0], [%1], 16;" :: "r"(s), "l"(g))

// ---------------- generic fp32 -> split-bf16 (elementwise, float4) ----------------
__global__ void __launch_bounds__(256) split_kernel(
    const float* __restrict__ src, __nv_bfloat16* __restrict__ oh,
    __nv_bfloat16* __restrict__ ol)
{
    size_t i4 = (size_t)blockIdx.x*256 + threadIdx.x;
    float4 v = *(const float4*)&src[i4*4];
    size_t o = i4*4;
    split2(v.x, oh[o+0], ol[o+0]);
    split2(v.y, oh[o+1], ol[o+1]);
    split2(v.z, oh[o+2], ol[o+2]);
    split2(v.w, oh[o+3], ol[o+3]);
}

// ---------------- EMA: forward scan ----------------
__global__ void __launch_bounds__(256) ema_fwd(
    const float* __restrict__ x, const float* __restrict__ dlt,
    const float* __restrict__ alp, const float* __restrict__ bet,
    const float* __restrict__ gam, const float* __restrict__ omg)
{
    int tid = blockIdx.x*256 + threadIdx.x;
    int b = tid >> 9, d = tid & 511;
    int i0 = d*2, i1 = d*2 + 1;
    float p0 = sigmf(dlt[i0]), p1 = sigmf(dlt[i1]);
    float q0 = 1.f - p0*sigmf(alp[i0]);
    float q1 = 1.f - p1*sigmf(alp[i1]);
    const float invs = 0.7071067811865476f;
    float w0 = p0*bet[i0]*gam[i0]*invs;
    float w1 = p1*bet[i1]*gam[i1]*invs;
    float ow = omg[d];
    float f0 = 0.f, f1 = 0.f;
    int idx = b*512 + d;
    #pragma unroll 8
    for (int l = 0; l < L_; ++l, idx += 8192) {
        float xv = x[idx];
        f0 = fmaf(q0, f0, xv);
        f1 = fmaf(q1, f1, xv);
        g_tmp[idx] = fmaf(w0, f0, fmaf(w1, f1, xv*ow));
    }
}

// ---------------- EMA: backward scan + silu -> split planes ----------------
__global__ void __launch_bounds__(256) ema_bwd(
    const float* __restrict__ x, const float* __restrict__ dlt,
    const float* __restrict__ alp, const float* __restrict__ bet,
    const float* __restrict__ gam)
{
    int tid = blockIdx.x*256 + threadIdx.x;
    int b = tid >> 9, d = tid & 511;
    int i0 = (512 + d)*2, i1 = i0 + 1;
    float p0 = sigmf(dlt[i0]), p1 = sigmf(dlt[i1]);
    float q0 = 1.f - p0*sigmf(alp[i0]);
    float q1 = 1.f - p1*sigmf(alp[i1]);
    const float invs = 0.7071067811865476f;
    float w0 = p0*bet[i0]*gam[i0]*invs;
    float w1 = p1*bet[i1]*gam[i1]*invs;
    float f0 = 0.f, f1 = 0.f;
    int idx = (L_-1)*8192 + b*512 + d;
    #pragma unroll 8
    for (int l = 0; l < L_; ++l, idx -= 8192) {
        float xv = x[idx];
        f0 = fmaf(q0, f0, xv);
        f1 = fmaf(q1, f1, xv);
        float y = g_tmp[idx] + fmaf(w0, f0, w1*f1);
        split2(siluf(y), mxs_h[idx], mxs_l[idx]);
    }
}

// ---------------- pipelined split-bf16 tensor-core GEMM ----------------
// A natural [m][k], B natural [k][n] (ldmatrix.trans), cp.async double-buffer.
// MODE 0: vs    = split(silu(xs @ Wv + bv))        TM=256 N=1024 K=512
// MODE 1: g_base= act(mxs @ Wmx + bmx)             TM=256 N=2176 K=512
// MODE 2: g_o   = gate(silu(hr @ Wh + bh + hx))    TM=256 N=512  K=1024
// MODE 3: hr    = split((attn @ v) * r)  (256 bat) TM=128 N=1024 K=128
template<int MODE>
__global__ void __launch_bounds__((MODE==3)?256:512, 1) mma_gemm(
    const float* __restrict__ Xres, const float* __restrict__ bias)
{
    constexpr int TM  = (MODE==3) ? 128 : 256;
    constexpr int NTH = (MODE==3) ? 256 : 512;
    constexpr int WM  = TM/64;
    constexpr int K   = (MODE==2) ? 1024 : (MODE==3) ? 128 : 512;
    constexpr int ldA = (MODE==2) ? 1024 : (MODE==3) ? 128 : 512;
    constexpr int ldB = (MODE==0) ? 1024 : (MODE==1) ? 2176 : (MODE==2) ? 512 : 16384;
    constexpr int NK  = K/32;
    constexpr int APS = TM*80;                // A plane bytes per stage
    constexpr int BOFF = 2*APS;
    constexpr int STAGE = BOFF + 2*8192;
    constexpr int NA_E = (2*TM*4)/NTH;        // 4
    constexpr int NB_E = 1024/NTH;            // 2 or 4

    extern __shared__ __align__(128) char smem_raw[];
    const uint32_t sb = (uint32_t)__cvta_generic_to_shared(smem_raw);

    const int t = threadIdx.x;
    const int warp = t >> 5, lane = t & 31;
    const int wm = warp % WM, wn = warp / WM;
    const int group = lane >> 2, tid4 = lane & 3;
    const int mat = lane >> 3, rim = lane & 7;
    const int rOff = ((mat & 1) << 3) + rim;
    const int cOff = mat >> 1;

    const int bn = blockIdx.x * 128;
    const int bm = (MODE==3) ? 0 : blockIdx.y * TM;

    int bb = 0, cc = 0, batch = 0;
    if (MODE == 3) { batch = blockIdx.z; bb = batch >> 4; cc = batch & 15; }

    const __nv_bfloat16 *pA0, *pA1, *pB0, *pB1;
    if (MODE == 0) { pA0 = xs_h  + (size_t)bm*ldA; pA1 = xs_l  + (size_t)bm*ldA;
                     pB0 = wv_h  + bn;             pB1 = wv_l  + bn; }
    else if (MODE == 1) { pA0 = mxs_h + (size_t)bm*ldA; pA1 = mxs_l + (size_t)bm*ldA;
                          pB0 = wmx_h + bn;             pB1 = wmx_l + bn; }
    else if (MODE == 2) { pA0 = hr_h  + (size_t)bm*ldA; pA1 = hr_l  + (size_t)bm*ldA;
                          pB0 = wh_h  + bn;             pB1 = wh_l  + bn; }
    else { pA0 = at_h + (size_t)batch*16384; pA1 = at_l + (size_t)batch*16384;
           size_t vb = (size_t)(cc*2048 + bb)*H_ + bn;
           pB0 = vs_h + vb; pB1 = vs_l + vb; }

    // cp.async descriptors
    const __nv_bfloat16* gA[NA_E]; uint32_t sA[NA_E];
    #pragma unroll
    for (int e = 0; e < NA_E; e++) {
        int idx = e*NTH + t;
        int plane = idx / (TM*4), w = idx % (TM*4);
        int r = w >> 2, c = w & 3;
        gA[e] = (plane ? pA1 : pA0) + (size_t)r*ldA + c*8;
        sA[e] = sb + plane*APS + r*80 + (c << 4);
    }
    const __nv_bfloat16* gB[NB_E]; uint32_t sB[NB_E];
    #pragma unroll
    for (int e = 0; e < NB_E; e++) {
        int idx = e*NTH + t;
        int plane = idx >> 9, w = idx & 511;
        int r = w >> 4, c = w & 15;
        gB[e] = (plane ? pB1 : pB0) + (size_t)r*ldB + c*8;
        sB[e] = sb + BOFF + plane*8192 + r*256 + (((uint32_t)(c ^ (r & 7))) << 4);
    }

    float acc[4][4][4];
    #pragma unroll
    for (int a = 0; a < 4; a++)
        #pragma unroll
        for (int b2 = 0; b2 < 4; b2++)
            #pragma unroll
            for (int e = 0; e < 4; e++) acc[a][b2][e] = 0.f;

    #pragma unroll
    for (int e = 0; e < NA_E; e++) CPA16(sA[e], gA[e]);
    #pragma unroll
    for (int e = 0; e < NB_E; e++) CPA16(sB[e], gB[e]);
    asm volatile("cp.async.commit_group;");

    for (int it = 0; it < NK; it++) {
        if (it + 1 < NK) {
            uint32_t so = ((it + 1) & 1) * STAGE;
            int ka = (it + 1) * 32;
            #pragma unroll
            for (int e = 0; e < NA_E; e++) CPA16(sA[e] + so, gA[e] + ka);
            #pragma unroll
            for (int e = 0; e < NB_E; e++) CPA16(sB[e] + so, gB[e] + (size_t)ka*ldB);
            asm volatile("cp.async.commit_group;");
            asm volatile("cp.async.wait_group 1;");
        } else {
            asm volatile("cp.async.wait_group 0;");
        }
        __syncthreads();

        const uint32_t stg = sb + (it & 1)*STAGE;
        #pragma unroll
        for (int ks = 0; ks < 2; ks++) {
            #pragma unroll
            for (int mp = 0; mp < 2; mp++) {
                uint32_t ah[2][4], al[2][4];
                #pragma unroll
                for (int ml = 0; ml < 2; ml++) {
                    int row = wm*64 + (mp*2 + ml)*16 + rOff;
                    uint32_t ad = stg + row*80 + ((uint32_t)(ks*2 + cOff) << 4);
                    LDSM4(ah[ml][0], ah[ml][1], ah[ml][2], ah[ml][3], ad);
                    LDSM4(al[ml][0], al[ml][1], al[ml][2], al[ml][3], ad + APS);
                }
                #pragma unroll
                for (int g = 0; g < 2; g++) {
                    int kin = ks*16 + rOff;
                    int cB = wn*4 + g*2 + cOff;
                    uint32_t bd = stg + BOFF + kin*256 + (((uint32_t)(cB ^ (kin & 7))) << 4);
                    uint32_t bh0,bh1,bh2,bh3, bl0,bl1,bl2,bl3;
                    LDSM4T(bh0,bh1,bh2,bh3, bd);
                    LDSM4T(bl0,bl1,bl2,bl3, bd + 8192);
                    #pragma unroll
                    for (int ml = 0; ml < 2; ml++) {
                        int mt = mp*2 + ml;
                        MMA16816(acc[mt][g*2],   ah[ml], bh0, bh1);
                        MMA16816(acc[mt][g*2],   ah[ml], bl0, bl1);
                        MMA16816(acc[mt][g*2],   al[ml], bh0, bh1);
                        MMA16816(acc[mt][g*2+1], ah[ml], bh2, bh3);
                        MMA16816(acc[mt][g*2+1], ah[ml], bl2, bl3);
                        MMA16816(acc[mt][g*2+1], al[ml], bh2, bh3);
                    }
                }
            }
        }
        __syncthreads();
    }

    // ---- epilogue ----
    #pragma unroll
    for (int mt = 0; mt < 4; mt++) {
        #pragma unroll
        for (int nt = 0; nt < 4; nt++) {
            #pragma unroll
            for (int half = 0; half < 2; half++) {
                int m = bm + wm*64 + mt*16 + group + half*8;
                #pragma unroll
                for (int e = 0; e < 2; e++) {
                    int n = bn + wn*32 + nt*8 + tid4*2 + e;
                    float v = acc[mt][nt][half*2 + e];
                    if (MODE == 0) {
                        float s = siluf(v + bias[n]);
                        split2(s, vs_h[(size_t)m*H_ + n], vs_l[(size_t)m*H_ + n]);
                    } else if (MODE == 1) {
                        v += bias[n];
                        if (n < 512)       v = sigmf(v);
                        else if (n < 1664) v = siluf(v);
                        g_base[(size_t)m*NBASE + n] = v;
                    } else if (MODE == 2) {
                        float hx = g_base[(size_t)m*NBASE + 1664 + n];
                        float s  = siluf(v + bias[n] + hx);
                        float u  = g_base[(size_t)m*NBASE + n];
                        float xr = Xres[(size_t)m*D_ + n];
                        g_o[(size_t)m*D_ + n] = xr + u*(s - xr);
                    } else {
                        size_t row = (size_t)(cc*128 + m)*B_ + bb;
                        float rv = g_base[row*NBASE + 640 + n];
                        split2(v*rv, hr_h[row*H_ + n], hr_l[row*H_ + n]);
                    }
                }
            }
        }
    }
}

// ---------------- QK + softmax ----------------
__global__ void __launch_bounds__(256) qk_kernel(
    const float* __restrict__ qkg, const float* __restrict__ qkb,
    const float* __restrict__ rp, float* __restrict__ attn_out)
{
    extern __shared__ float sm[];
    float* qT = sm;             // [z][i] 128*128
    float* kT = sm + 16384;     // [z][j] 128*128
    float* sT = sm + 32768;     // [j][i] stride 132
    float* red = sm;            // reused after QK compute

    const int b = blockIdx.x >> 4;
    const int c = blockIdx.x & 15;
    const int t = threadIdx.x;
    const float qscale = 0.08838834764831845f;

    for (int idx = t; idx < 16384; idx += 256) {
        int i = idx >> 7, z = idx & 127;
        int row = (c*128 + i)*B_ + b;
        float zv = g_base[(size_t)row*NBASE + 512 + z];
        qT[z*128 + i] = (zv*qkg[z]     + qkb[z]    ) * qscale;
        kT[z*128 + i] =  zv*qkg[128+z] + qkb[128+z];
    }
    __syncthreads();

    {
        const int tx = t & 15, ty = t >> 4;
        const int i0 = ty*8, j0 = tx*8;
        float acc[8][8];
        #pragma unroll
        for (int i = 0; i < 8; i++)
            #pragma unroll
            for (int j = 0; j < 8; j++) acc[i][j] = 0.f;

        #pragma unroll 4
        for (int z = 0; z < 128; z++) {
            float qa[8], ka[8];
            *(float4*)(qa)   = *(const float4*)&qT[z*128 + i0];
            *(float4*)(qa+4) = *(const float4*)&qT[z*128 + i0 + 4];
            *(float4*)(ka)   = *(const float4*)&kT[z*128 + j0];
            *(float4*)(ka+4) = *(const float4*)&kT[z*128 + j0 + 4];
            #pragma unroll
            for (int i = 0; i < 8; i++)
                #pragma unroll
                for (int j = 0; j < 8; j++)
                    acc[i][j] = fmaf(qa[i], ka[j], acc[i][j]);
        }
        #pragma unroll
        for (int r = 0; r < 8; r++)
            #pragma unroll
            for (int cc2 = 0; cc2 < 8; cc2++) {
                int i = i0 + r, j = j0 + cc2;
                sT[j*132 + i] = acc[r][cc2] + rp[1023 + j - i];
            }
    }
    __syncthreads();

    // parallel softmax over rows i: 2 threads per row
    {
        const int i = t & 127, half = t >> 7;
        const int jb = half*64;
        float mx = -1e30f;
        for (int j = jb; j < jb + 64; j++) mx = fmaxf(mx, sT[j*132 + i]);
        red[half*128 + i] = mx;
        __syncthreads();
        float M = fmaxf(red[i], red[128 + i]);
        float s = 0.f;
        for (int j = jb; j < jb + 64; j++) {
            float e = expf(sT[j*132 + i] - M);
            sT[j*132 + i] = e;
            s += e;
        }
        red[256 + half*128 + i] = s;
        __syncthreads();
        if (half == 0) red[512 + i] = 1.f / (red[256 + i] + red[384 + i]);
        __syncthreads();
    }

    size_t base = (size_t)(b*NC_ + c)*16384;
    float* aout = attn_out + base;
    for (int idx = t; idx < 16384; idx += 256) {
        int i = idx >> 7, j = idx & 127;
        float p = sT[j*132 + i] * red[512 + i];
        aout[idx] = p;
        split2(p, at_h[base + idx], at_l[base + idx]);
    }
}

// ---------------- final rmsnorm ----------------
__global__ void __launch_bounds__(256) norm_kernel(
    const float* __restrict__ ns, float* __restrict__ out)
{
    int row  = blockIdx.x*8 + (threadIdx.x >> 5);
    int lane = threadIdx.x & 31;
    const float* op = g_o + (size_t)row*512;
    float vals[16];
    float ss = 0.f;
    #pragma unroll
    for (int k = 0; k < 16; k++) {
        float v = op[lane + k*32];
        vals[k] = v;
        ss += v*v;
    }
    #pragma unroll
    for (int off = 16; off; off >>= 1) ss += __shfl_xor_sync(0xffffffffu, ss, off);
    float scale = ns[0] * rsqrtf(ss*(1.f/512.f) + 1e-6f);
    float* outp = out + (size_t)row*512;
    #pragma unroll
    for (int k = 0; k < 16; k++) outp[lane + k*32] = vals[k]*scale;
}

// ---------------- launch ----------------
extern "C" void kernel_launch(void* const* d_in, const int* in_sizes, int n_in,
                              void* d_out, int out_size)
{
    const float* x   = (const float*)d_in[0];
    const float* edl = (const float*)d_in[1];
    const float* eal = (const float*)d_in[2];
    const float* ebt = (const float*)d_in[3];
    const float* egm = (const float*)d_in[4];
    const float* eom = (const float*)d_in[5];
    const float* Wv  = (const float*)d_in[6];
    const float* bv  = (const float*)d_in[7];
    const float* Wmx = (const float*)d_in[8];
    const float* bmx = (const float*)d_in[9];
    const float* Wh  = (const float*)d_in[10];
    const float* bh  = (const float*)d_in[11];
    const float* qkg = (const float*)d_in[12];
    const float* qkb = (const float*)d_in[13];
    const float* rp  = (const float*)d_in[14];
    const float* ns  = (const float*)d_in[15];

    float* out      = (float*)d_out;
    float* attn_out = out + (size_t)L_*B_*D_;

    static __nv_bfloat16 *p_wvh=nullptr,*p_wvl,*p_wmxh,*p_wmxl,*p_whh,*p_whl,*p_xsh,*p_xsl;
    if (!p_wvh) {
        cudaGetSymbolAddress((void**)&p_wvh,  wv_h);
        cudaGetSymbolAddress((void**)&p_wvl,  wv_l);
        cudaGetSymbolAddress((void**)&p_wmxh, wmx_h);
        cudaGetSymbolAddress((void**)&p_wmxl, wmx_l);
        cudaGetSymbolAddress((void**)&p_whh,  wh_h);
        cudaGetSymbolAddress((void**)&p_whl,  wh_l);
        cudaGetSymbolAddress((void**)&p_xsh,  xs_h);
        cudaGetSymbolAddress((void**)&p_xsl,  xs_l);
        cudaFuncSetAttribute(qk_kernel,   cudaFuncAttributeMaxDynamicSharedMemorySize, 198656);
        cudaFuncSetAttribute(mma_gemm<0>, cudaFuncAttributeMaxDynamicSharedMemorySize, 114688);
        cudaFuncSetAttribute(mma_gemm<1>, cudaFuncAttributeMaxDynamicSharedMemorySize, 114688);
        cudaFuncSetAttribute(mma_gemm<2>, cudaFuncAttributeMaxDynamicSharedMemorySize, 114688);
        cudaFuncSetAttribute(mma_gemm<3>, cudaFuncAttributeMaxDynamicSharedMemorySize, 73728);
    }

    split_kernel<<<512,  256>>>(Wv,  p_wvh,  p_wvl);
    split_kernel<<<1088, 256>>>(Wmx, p_wmxh, p_wmxl);
    split_kernel<<<512,  256>>>(Wh,  p_whh,  p_whl);
    split_kernel<<<16384,256>>>(x,   p_xsh,  p_xsl);

    ema_fwd<<<32, 256>>>(x, edl, eal, ebt, egm, eom);
    ema_bwd<<<32, 256>>>(x, edl, eal, ebt, egm);

    { dim3 g(8, 128);  mma_gemm<0><<<g, 512, 114688>>>(x, bv); }
    { dim3 g(17, 128); mma_gemm<1><<<g, 512, 114688>>>(x, bmx); }

    qk_kernel<<<B_*NC_, 256, 198656>>>(qkg, qkb, rp, attn_out);

    { dim3 g(8, 1, 256); mma_gemm<3><<<g, 256, 73728>>>(x, bv); }
    { dim3 g(4, 128);    mma_gemm<2><<<g, 512, 114688>>>(x, bh); }

    norm_kernel<<<MROWS/8, 256>>>(ns, out);
}

// round 7
// speedup vs baseline: 1.7132x; 1.0090x over previous
#include <cuda_runtime.h>
#include <cuda_bf16.h>
#include <stdint.h>
#include <math.h>

#define L_ 2048
#define B_ 16
#define D_ 512
#define H_ 1024
#define NC_ 16
#define NBASE 2176            // Z + H + 2D
#define MROWS (L_*B_)         // 32768

// ---------------- fp32 scratch ----------------
__device__ float g_tmp [MROWS*D_];     // ema fwd partial
__device__ float g_base[MROWS*NBASE];  // activated base: [u | z | r | hx]
__device__ float g_o   [MROWS*D_];     // pre-norm output

// ---------------- split-bf16 planes (all natural layout) ----------------
__device__ __align__(16) __nv_bfloat16 xs_h [MROWS*D_],  xs_l [MROWS*D_];
__device__ __align__(16) __nv_bfloat16 mxs_h[MROWS*D_],  mxs_l[MROWS*D_];
__device__ __align__(16) __nv_bfloat16 vs_h [MROWS*H_],  vs_l [MROWS*H_];   // v [m][h]
__device__ __align__(16) __nv_bfloat16 hr_h [MROWS*H_],  hr_l [MROWS*H_];   // h*r [m][h]
__device__ __align__(16) __nv_bfloat16 at_h [B_*NC_*128*128], at_l[B_*NC_*128*128];
__device__ __align__(16) __nv_bfloat16 wv_h [512*1024],  wv_l [512*1024];   // [k][n]
__device__ __align__(16) __nv_bfloat16 wmx_h[512*2176],  wmx_l[512*2176];   // [k][n]
__device__ __align__(16) __nv_bfloat16 wh_h [1024*512],  wh_l [1024*512];   // [k][n]

__device__ __forceinline__ float sigmf(float x){ return 1.0f/(1.0f + expf(-x)); }
__device__ __forceinline__ float siluf(float x){ return x/(1.0f + expf(-x)); }
__device__ __forceinline__ void split2(float v, __nv_bfloat16& h, __nv_bfloat16& l){
    h = __float2bfloat16_rn(v);
    l = __float2bfloat16_rn(v - __bfloat162float(h));
}

#define MMA16816(d, a, b0, b1) \
  asm volatile("mma.sync.aligned.m16n8k16.row.col.f32.bf16.bf16.f32 " \
    "{%0,%1,%2,%3}, {%4,%5,%6,%7}, {%8,%9}, {%0,%1,%2,%3};" \
    : "+f"(d[0]), "+f"(d[1]), "+f"(d[2]), "+f"(d[3]) \
    : "r"(a[0]), "r"(a[1]), "r"(a[2]), "r"(a[3]), "r"(b0), "r"(b1))

#define LDSM4(r0,r1,r2,r3,a) \
  asm volatile("ldmatrix.sync.aligned.m8n8.x4.shared.b16 {%0,%1,%2,%3}, [%4];" \
    : "=r"(r0),"=r"(r1),"=r"(r2),"=r"(r3) : "r"(a))

#define LDSM4T(r0,r1,r2,r3,a) \
  asm volatile("ldmatrix.sync.aligned.m8n8.x4.trans.shared.b16 {%0,%1,%2,%3}, [%4];" \
    : "=r"(r0),"=r"(r1),"=r"(r2),"=r"(r3) : "r"(a))

#define CPA16(s,g) asm volatile("cp.async.cg.shared.global [%0], [%1], 16;" :: "r"(s), "l"(g))

// ---------------- generic fp32 -> split-bf16 (elementwise, float4) ----------------
__global__ void __launch_bounds__(256) split_kernel(
    const float* __restrict__ src, __nv_bfloat16* __restrict__ oh,
    __nv_bfloat16* __restrict__ ol)
{
    size_t i4 = (size_t)blockIdx.x*256 + threadIdx.x;
    float4 v = *(const float4*)&src[i4*4];
    size_t o = i4*4;
    split2(v.x, oh[o+0], ol[o+0]);
    split2(v.y, oh[o+1], ol[o+1]);
    split2(v.z, oh[o+2], ol[o+2]);
    split2(v.w, oh[o+3], ol[o+3]);
}

// ---------------- EMA: forward scan ----------------
__global__ void __launch_bounds__(256) ema_fwd(
    const float* __restrict__ x, const float* __restrict__ dlt,
    const float* __restrict__ alp, const float* __restrict__ bet,
    const float* __restrict__ gam, const float* __restrict__ omg)
{
    int tid = blockIdx.x*256 + threadIdx.x;
    int b = tid >> 9, d = tid & 511;
    int i0 = d*2, i1 = d*2 + 1;
    float p0 = sigmf(dlt[i0]), p1 = sigmf(dlt[i1]);
    float q0 = 1.f - p0*sigmf(alp[i0]);
    float q1 = 1.f - p1*sigmf(alp[i1]);
    const float invs = 0.7071067811865476f;
    float w0 = p0*bet[i0]*gam[i0]*invs;
    float w1 = p1*bet[i1]*gam[i1]*invs;
    float ow = omg[d];
    float f0 = 0.f, f1 = 0.f;
    int idx = b*512 + d;
    #pragma unroll 8
    for (int l = 0; l < L_; ++l, idx += 8192) {
        float xv = x[idx];
        f0 = fmaf(q0, f0, xv);
        f1 = fmaf(q1, f1, xv);
        g_tmp[idx] = fmaf(w0, f0, fmaf(w1, f1, xv*ow));
    }
}

// ---------------- EMA: backward scan + silu -> split planes ----------------
__global__ void __launch_bounds__(256) ema_bwd(
    const float* __restrict__ x, const float* __restrict__ dlt,
    const float* __restrict__ alp, const float* __restrict__ bet,
    const float* __restrict__ gam)
{
    int tid = blockIdx.x*256 + threadIdx.x;
    int b = tid >> 9, d = tid & 511;
    int i0 = (512 + d)*2, i1 = i0 + 1;
    float p0 = sigmf(dlt[i0]), p1 = sigmf(dlt[i1]);
    float q0 = 1.f - p0*sigmf(alp[i0]);
    float q1 = 1.f - p1*sigmf(alp[i1]);
    const float invs = 0.7071067811865476f;
    float w0 = p0*bet[i0]*gam[i0]*invs;
    float w1 = p1*bet[i1]*gam[i1]*invs;
    float f0 = 0.f, f1 = 0.f;
    int idx = (L_-1)*8192 + b*512 + d;
    #pragma unroll 8
    for (int l = 0; l < L_; ++l, idx -= 8192) {
        float xv = x[idx];
        f0 = fmaf(q0, f0, xv);
        f1 = fmaf(q1, f1, xv);
        float y = g_tmp[idx] + fmaf(w0, f0, w1*f1);
        split2(siluf(y), mxs_h[idx], mxs_l[idx]);
    }
}

// ---------------- pipelined split-bf16 tensor-core GEMM (3-stage ring) ----------
// A natural [m][k], B natural [k][n] (ldmatrix.trans), cp.async triple-buffer.
// MODE 0: vs    = split(silu(xs @ Wv + bv))        TM=256 N=1024 K=512
// MODE 1: g_base= act(mxs @ Wmx + bmx)             TM=256 N=2176 K=512
// MODE 2: g_o   = gate(silu(hr @ Wh + bh + hx))    TM=256 N=512  K=1024
// MODE 3: hr    = split((attn @ v) * r)  (256 bat) TM=128 N=1024 K=128
template<int MODE>
__global__ void __launch_bounds__((MODE==3)?256:512, 1) mma_gemm(
    const float* __restrict__ Xres, const float* __restrict__ bias)
{
    constexpr int TM  = (MODE==3) ? 128 : 256;
    constexpr int NTH = (MODE==3) ? 256 : 512;
    constexpr int WM  = TM/64;
    constexpr int K   = (MODE==2) ? 1024 : (MODE==3) ? 128 : 512;
    constexpr int ldA = (MODE==2) ? 1024 : (MODE==3) ? 128 : 512;
    constexpr int ldB = (MODE==0) ? 1024 : (MODE==1) ? 2176 : (MODE==2) ? 512 : 16384;
    constexpr int NK  = K/32;
    constexpr int APS = TM*80;                // A plane bytes per stage
    constexpr int BOFF = 2*APS;
    constexpr int STAGE = BOFF + 2*8192;
    constexpr int NA_E = (2*TM*4)/NTH;        // 4
    constexpr int NB_E = 1024/NTH;            // 2 or 4

    extern __shared__ __align__(128) char smem_raw[];
    const uint32_t sb = (uint32_t)__cvta_generic_to_shared(smem_raw);

    const int t = threadIdx.x;
    const int warp = t >> 5, lane = t & 31;
    const int wm = warp % WM, wn = warp / WM;
    const int group = lane >> 2, tid4 = lane & 3;
    const int mat = lane >> 3, rim = lane & 7;
    const int rOff = ((mat & 1) << 3) + rim;
    const int cOff = mat >> 1;

    const int bn = blockIdx.x * 128;
    const int bm = (MODE==3) ? 0 : blockIdx.y * TM;

    int bb = 0, cc = 0, batch = 0;
    if (MODE == 3) { batch = blockIdx.z; bb = batch >> 4; cc = batch & 15; }

    const __nv_bfloat16 *pA0, *pA1, *pB0, *pB1;
    if (MODE == 0) { pA0 = xs_h  + (size_t)bm*ldA; pA1 = xs_l  + (size_t)bm*ldA;
                     pB0 = wv_h  + bn;             pB1 = wv_l  + bn; }
    else if (MODE == 1) { pA0 = mxs_h + (size_t)bm*ldA; pA1 = mxs_l + (size_t)bm*ldA;
                          pB0 = wmx_h + bn;             pB1 = wmx_l + bn; }
    else if (MODE == 2) { pA0 = hr_h  + (size_t)bm*ldA; pA1 = hr_l  + (size_t)bm*ldA;
                          pB0 = wh_h  + bn;             pB1 = wh_l  + bn; }
    else { pA0 = at_h + (size_t)batch*16384; pA1 = at_l + (size_t)batch*16384;
           size_t vb = (size_t)(cc*2048 + bb)*H_ + bn;
           pB0 = vs_h + vb; pB1 = vs_l + vb; }

    // cp.async descriptors
    const __nv_bfloat16* gA[NA_E]; uint32_t sA[NA_E];
    #pragma unroll
    for (int e = 0; e < NA_E; e++) {
        int idx = e*NTH + t;
        int plane = idx / (TM*4), w = idx % (TM*4);
        int r = w >> 2, c = w & 3;
        gA[e] = (plane ? pA1 : pA0) + (size_t)r*ldA + c*8;
        sA[e] = sb + plane*APS + r*80 + (c << 4);
    }
    const __nv_bfloat16* gB[NB_E]; uint32_t sB[NB_E];
    #pragma unroll
    for (int e = 0; e < NB_E; e++) {
        int idx = e*NTH + t;
        int plane = idx >> 9, w = idx & 511;
        int r = w >> 4, c = w & 15;
        gB[e] = (plane ? pB1 : pB0) + (size_t)r*ldB + c*8;
        sB[e] = sb + BOFF + plane*8192 + r*256 + (((uint32_t)(c ^ (r & 7))) << 4);
    }

    auto load_chunk = [&](int ck) {
        uint32_t so = (uint32_t)(ck % 3) * STAGE;
        int ka = ck * 32;
        #pragma unroll
        for (int e = 0; e < NA_E; e++) CPA16(sA[e] + so, gA[e] + ka);
        #pragma unroll
        for (int e = 0; e < NB_E; e++) CPA16(sB[e] + so, gB[e] + (size_t)ka*ldB);
        asm volatile("cp.async.commit_group;");
    };

    float acc[4][4][4];
    #pragma unroll
    for (int a = 0; a < 4; a++)
        #pragma unroll
        for (int b2 = 0; b2 < 4; b2++)
            #pragma unroll
            for (int e = 0; e < 4; e++) acc[a][b2][e] = 0.f;

    load_chunk(0);
    load_chunk(1);

    for (int it = 0; it < NK; it++) {
        if (it + 1 < NK) asm volatile("cp.async.wait_group 1;" ::: "memory");
        else             asm volatile("cp.async.wait_group 0;" ::: "memory");
        __syncthreads();
        if (it + 2 < NK) load_chunk(it + 2);

        const uint32_t stg = sb + (uint32_t)(it % 3)*STAGE;
        #pragma unroll
        for (int ks = 0; ks < 2; ks++) {
            #pragma unroll
            for (int mp = 0; mp < 2; mp++) {
                uint32_t ah[2][4], al[2][4];
                #pragma unroll
                for (int ml = 0; ml < 2; ml++) {
                    int row = wm*64 + (mp*2 + ml)*16 + rOff;
                    uint32_t ad = stg + row*80 + ((uint32_t)(ks*2 + cOff) << 4);
                    LDSM4(ah[ml][0], ah[ml][1], ah[ml][2], ah[ml][3], ad);
                    LDSM4(al[ml][0], al[ml][1], al[ml][2], al[ml][3], ad + APS);
                }
                #pragma unroll
                for (int g = 0; g < 2; g++) {
                    int kin = ks*16 + rOff;
                    int cB = wn*4 + g*2 + cOff;
                    uint32_t bd = stg + BOFF + kin*256 + (((uint32_t)(cB ^ (kin & 7))) << 4);
                    uint32_t bh0,bh1,bh2,bh3, bl0,bl1,bl2,bl3;
                    LDSM4T(bh0,bh1,bh2,bh3, bd);
                    LDSM4T(bl0,bl1,bl2,bl3, bd + 8192);
                    #pragma unroll
                    for (int ml = 0; ml < 2; ml++) {
                        int mt = mp*2 + ml;
                        MMA16816(acc[mt][g*2],   ah[ml], bh0, bh1);
                        MMA16816(acc[mt][g*2],   ah[ml], bl0, bl1);
                        MMA16816(acc[mt][g*2],   al[ml], bh0, bh1);
                        MMA16816(acc[mt][g*2+1], ah[ml], bh2, bh3);
                        MMA16816(acc[mt][g*2+1], ah[ml], bl2, bl3);
                        MMA16816(acc[mt][g*2+1], al[ml], bh2, bh3);
                    }
                }
            }
        }
        __syncthreads();
    }

    // ---- epilogue ----
    #pragma unroll
    for (int mt = 0; mt < 4; mt++) {
        #pragma unroll
        for (int nt = 0; nt < 4; nt++) {
            #pragma unroll
            for (int half = 0; half < 2; half++) {
                int m = bm + wm*64 + mt*16 + group + half*8;
                #pragma unroll
                for (int e = 0; e < 2; e++) {
                    int n = bn + wn*32 + nt*8 + tid4*2 + e;
                    float v = acc[mt][nt][half*2 + e];
                    if (MODE == 0) {
                        float s = siluf(v + bias[n]);
                        split2(s, vs_h[(size_t)m*H_ + n], vs_l[(size_t)m*H_ + n]);
                    } else if (MODE == 1) {
                        v += bias[n];
                        if (n < 512)       v = sigmf(v);
                        else if (n < 1664) v = siluf(v);
                        g_base[(size_t)m*NBASE + n] = v;
                    } else if (MODE == 2) {
                        float hx = g_base[(size_t)m*NBASE + 1664 + n];
                        float s  = siluf(v + bias[n] + hx);
                        float u  = g_base[(size_t)m*NBASE + n];
                        float xr = Xres[(size_t)m*D_ + n];
                        g_o[(size_t)m*D_ + n] = xr + u*(s - xr);
                    } else {
                        size_t row = (size_t)(cc*128 + m)*B_ + bb;
                        float rv = g_base[row*NBASE + 640 + n];
                        split2(v*rv, hr_h[row*H_ + n], hr_l[row*H_ + n]);
                    }
                }
            }
        }
    }
}

// ---------------- QK + softmax ----------------
__global__ void __launch_bounds__(256) qk_kernel(
    const float* __restrict__ qkg, const float* __restrict__ qkb,
    const float* __restrict__ rp, float* __restrict__ attn_out)
{
    extern __shared__ float sm[];
    float* qT = sm;             // [z][i] 128*128
    float* kT = sm + 16384;     // [z][j] 128*128
    float* sT = sm + 32768;     // [j][i] stride 132
    float* red = sm;            // reused after QK compute

    const int b = blockIdx.x >> 4;
    const int c = blockIdx.x & 15;
    const int t = threadIdx.x;
    const float qscale = 0.08838834764831845f;

    for (int idx = t; idx < 16384; idx += 256) {
        int i = idx >> 7, z = idx & 127;
        int row = (c*128 + i)*B_ + b;
        float zv = g_base[(size_t)row*NBASE + 512 + z];
        qT[z*128 + i] = (zv*qkg[z]     + qkb[z]    ) * qscale;
        kT[z*128 + i] =  zv*qkg[128+z] + qkb[128+z];
    }
    __syncthreads();

    {
        const int tx = t & 15, ty = t >> 4;
        const int i0 = ty*8, j0 = tx*8;
        float acc[8][8];
        #pragma unroll
        for (int i = 0; i < 8; i++)
            #pragma unroll
            for (int j = 0; j < 8; j++) acc[i][j] = 0.f;

        #pragma unroll 4
        for (int z = 0; z < 128; z++) {
            float qa[8], ka[8];
            *(float4*)(qa)   = *(const float4*)&qT[z*128 + i0];
            *(float4*)(qa+4) = *(const float4*)&qT[z*128 + i0 + 4];
            *(float4*)(ka)   = *(const float4*)&kT[z*128 + j0];
            *(float4*)(ka+4) = *(const float4*)&kT[z*128 + j0 + 4];
            #pragma unroll
            for (int i = 0; i < 8; i++)
                #pragma unroll
                for (int j = 0; j < 8; j++)
                    acc[i][j] = fmaf(qa[i], ka[j], acc[i][j]);
        }
        #pragma unroll
        for (int r = 0; r < 8; r++)
            #pragma unroll
            for (int cc2 = 0; cc2 < 8; cc2++) {
                int i = i0 + r, j = j0 + cc2;
                sT[j*132 + i] = acc[r][cc2] + rp[1023 + j - i];
            }
    }
    __syncthreads();

    // parallel softmax over rows i: 2 threads per row
    {
        const int i = t & 127, half = t >> 7;
        const int jb = half*64;
        float mx = -1e30f;
        for (int j = jb; j < jb + 64; j++) mx = fmaxf(mx, sT[j*132 + i]);
        red[half*128 + i] = mx;
        __syncthreads();
        float M = fmaxf(red[i], red[128 + i]);
        float s = 0.f;
        for (int j = jb; j < jb + 64; j++) {
            float e = expf(sT[j*132 + i] - M);
            sT[j*132 + i] = e;
            s += e;
        }
        red[256 + half*128 + i] = s;
        __syncthreads();
        if (half == 0) red[512 + i] = 1.f / (red[256 + i] + red[384 + i]);
        __syncthreads();
    }

    size_t base = (size_t)(b*NC_ + c)*16384;
    float* aout = attn_out + base;
    for (int idx = t; idx < 16384; idx += 256) {
        int i = idx >> 7, j = idx & 127;
        float p = sT[j*132 + i] * red[512 + i];
        aout[idx] = p;
        split2(p, at_h[base + idx], at_l[base + idx]);
    }
}

// ---------------- final rmsnorm ----------------
__global__ void __launch_bounds__(256) norm_kernel(
    const float* __restrict__ ns, float* __restrict__ out)
{
    int row  = blockIdx.x*8 + (threadIdx.x >> 5);
    int lane = threadIdx.x & 31;
    const float* op = g_o + (size_t)row*512;
    float vals[16];
    float ss = 0.f;
    #pragma unroll
    for (int k = 0; k < 16; k++) {
        float v = op[lane + k*32];
        vals[k] = v;
        ss += v*v;
    }
    #pragma unroll
    for (int off = 16; off; off >>= 1) ss += __shfl_xor_sync(0xffffffffu, ss, off);
    float scale = ns[0] * rsqrtf(ss*(1.f/512.f) + 1e-6f);
    float* outp = out + (size_t)row*512;
    #pragma unroll
    for (int k = 0; k < 16; k++) outp[lane + k*32] = vals[k]*scale;
}

// ---------------- launch ----------------
extern "C" void kernel_launch(void* const* d_in, const int* in_sizes, int n_in,
                              void* d_out, int out_size)
{
    const float* x   = (const float*)d_in[0];
    const float* edl = (const float*)d_in[1];
    const float* eal = (const float*)d_in[2];
    const float* ebt = (const float*)d_in[3];
    const float* egm = (const float*)d_in[4];
    const float* eom = (const float*)d_in[5];
    const float* Wv  = (const float*)d_in[6];
    const float* bv  = (const float*)d_in[7];
    const float* Wmx = (const float*)d_in[8];
    const float* bmx = (const float*)d_in[9];
    const float* Wh  = (const float*)d_in[10];
    const float* bh  = (const float*)d_in[11];
    const float* qkg = (const float*)d_in[12];
    const float* qkb = (const float*)d_in[13];
    const float* rp  = (const float*)d_in[14];
    const float* ns  = (const float*)d_in[15];

    float* out      = (float*)d_out;
    float* attn_out = out + (size_t)L_*B_*D_;

    static __nv_bfloat16 *p_wvh=nullptr,*p_wvl,*p_wmxh,*p_wmxl,*p_whh,*p_whl,*p_xsh,*p_xsl;
    if (!p_wvh) {
        cudaGetSymbolAddress((void**)&p_wvh,  wv_h);
        cudaGetSymbolAddress((void**)&p_wvl,  wv_l);
        cudaGetSymbolAddress((void**)&p_wmxh, wmx_h);
        cudaGetSymbolAddress((void**)&p_wmxl, wmx_l);
        cudaGetSymbolAddress((void**)&p_whh,  wh_h);
        cudaGetSymbolAddress((void**)&p_whl,  wh_l);
        cudaGetSymbolAddress((void**)&p_xsh,  xs_h);
        cudaGetSymbolAddress((void**)&p_xsl,  xs_l);
        cudaFuncSetAttribute(qk_kernel,   cudaFuncAttributeMaxDynamicSharedMemorySize, 198656);
        cudaFuncSetAttribute(mma_gemm<0>, cudaFuncAttributeMaxDynamicSharedMemorySize, 172032);
        cudaFuncSetAttribute(mma_gemm<1>, cudaFuncAttributeMaxDynamicSharedMemorySize, 172032);
        cudaFuncSetAttribute(mma_gemm<2>, cudaFuncAttributeMaxDynamicSharedMemorySize, 172032);
        cudaFuncSetAttribute(mma_gemm<3>, cudaFuncAttributeMaxDynamicSharedMemorySize, 110592);
    }

    split_kernel<<<512,  256>>>(Wv,  p_wvh,  p_wvl);
    split_kernel<<<1088, 256>>>(Wmx, p_wmxh, p_wmxl);
    split_kernel<<<512,  256>>>(Wh,  p_whh,  p_whl);
    split_kernel<<<16384,256>>>(x,   p_xsh,  p_xsl);

    ema_fwd<<<32, 256>>>(x, edl, eal, ebt, egm, eom);
    ema_bwd<<<32, 256>>>(x, edl, eal, ebt, egm);

    { dim3 g(8, 128);  mma_gemm<0><<<g, 512, 172032>>>(x, bv); }
    { dim3 g(17, 128); mma_gemm<1><<<g, 512, 172032>>>(x, bmx); }

    qk_kernel<<<B_*NC_, 256, 198656>>>(qkg, qkb, rp, attn_out);

    { dim3 g(8, 1, 256); mma_gemm<3><<<g, 256, 110592>>>(x, bv); }
    { dim3 g(4, 128);    mma_gemm<2><<<g, 512, 172032>>>(x, bh); }

    norm_kernel<<<MROWS/8, 256>>>(ns, out);
}

// round 8
// speedup vs baseline: 2.4480x; 1.4289x over previous
#include <cuda_runtime.h>
#include <cuda_bf16.h>
#include <stdint.h>
#include <math.h>

#define L_ 2048
#define B_ 16
#define D_ 512
#define H_ 1024
#define NC_ 16
#define NBASE 2176            // Z + H + 2D
#define MROWS (L_*B_)         // 32768
#define NCH 16                // EMA chunks
#define CHL 128               // chunk length

// ---------------- fp32 scratch ----------------
__device__ float g_base[MROWS*NBASE];  // activated base: [u | z | r | hx]
__device__ float g_o   [MROWS*D_];     // pre-norm output
__device__ float e_st  [4*NCH*8192];   // per-chunk local states [comp][c][bd]
__device__ float seed_st[4*NCH*8192];  // per-chunk seeds        [comp][c][bd]

// ---------------- split-bf16 planes (all natural layout) ----------------
__device__ __align__(16) __nv_bfloat16 xs_h [MROWS*D_],  xs_l [MROWS*D_];
__device__ __align__(16) __nv_bfloat16 mxs_h[MROWS*D_],  mxs_l[MROWS*D_];
__device__ __align__(16) __nv_bfloat16 vs_h [MROWS*H_],  vs_l [MROWS*H_];   // v [m][h]
__device__ __align__(16) __nv_bfloat16 hr_h [MROWS*H_],  hr_l [MROWS*H_];   // h*r [m][h]
__device__ __align__(16) __nv_bfloat16 at_h [B_*NC_*128*128], at_l[B_*NC_*128*128];
__device__ __align__(16) __nv_bfloat16 wv_h [512*1024],  wv_l [512*1024];   // [k][n]
__device__ __align__(16) __nv_bfloat16 wmx_h[512*2176],  wmx_l[512*2176];   // [k][n]
__device__ __align__(16) __nv_bfloat16 wh_h [1024*512],  wh_l [1024*512];   // [k][n]

__device__ __forceinline__ float sigmf(float x){ return 1.0f/(1.0f + expf(-x)); }
__device__ __forceinline__ float siluf(float x){ return x/(1.0f + expf(-x)); }
__device__ __forceinline__ void split2(float v, __nv_bfloat16& h, __nv_bfloat16& l){
    h = __float2bfloat16_rn(v);
    l = __float2bfloat16_rn(v - __bfloat162float(h));
}

#define MMA16816(d, a, b0, b1) \
  asm volatile("mma.sync.aligned.m16n8k16.row.col.f32.bf16.bf16.f32 " \
    "{%0,%1,%2,%3}, {%4,%5,%6,%7}, {%8,%9}, {%0,%1,%2,%3};" \
    : "+f"(d[0]), "+f"(d[1]), "+f"(d[2]), "+f"(d[3]) \
    : "r"(a[0]), "r"(a[1]), "r"(a[2]), "r"(a[3]), "r"(b0), "r"(b1))

#define LDSM4(r0,r1,r2,r3,a) \
  asm volatile("ldmatrix.sync.aligned.m8n8.x4.shared.b16 {%0,%1,%2,%3}, [%4];" \
    : "=r"(r0),"=r"(r1),"=r"(r2),"=r"(r3) : "r"(a))

#define LDSM4T(r0,r1,r2,r3,a) \
  asm volatile("ldmatrix.sync.aligned.m8n8.x4.trans.shared.b16 {%0,%1,%2,%3}, [%4];" \
    : "=r"(r0),"=r"(r1),"=r"(r2),"=r"(r3) : "r"(a))

#define CPA16(s,g) asm volatile("cp.async.cg.shared.global [%0], [%1], 16;" :: "r"(s), "l"(g))

// ---------------- generic fp32 -> split-bf16 (weights) ----------------
__global__ void __launch_bounds__(256) split_kernel(
    const float* __restrict__ src, __nv_bfloat16* __restrict__ oh,
    __nv_bfloat16* __restrict__ ol)
{
    size_t i4 = (size_t)blockIdx.x*256 + threadIdx.x;
    float4 v = *(const float4*)&src[i4*4];
    size_t o = i4*4;
    split2(v.x, oh[o+0], ol[o+0]);
    split2(v.y, oh[o+1], ol[o+1]);
    split2(v.z, oh[o+2], ol[o+2]);
    split2(v.w, oh[o+3], ol[o+3]);
}

// ---------------- EMA phase 1: per-chunk local states + x split ----------------
// fwd local end-state (recurrence, zero init) and bwd local state via power-accum.
__global__ void __launch_bounds__(256) ema_p1(
    const float* __restrict__ x, const float* __restrict__ dlt,
    const float* __restrict__ alp)
{
    int t = blockIdx.x*256 + threadIdx.x;      // 0..131071
    int c = t >> 13, bd = t & 8191;
    int d = bd & 511;
    int i0f = d*2, i1f = d*2 + 1;
    int i0b = (512 + d)*2, i1b = i0b + 1;
    float q0f = 1.f - sigmf(dlt[i0f])*sigmf(alp[i0f]);
    float q1f = 1.f - sigmf(dlt[i1f])*sigmf(alp[i1f]);
    float q0b = 1.f - sigmf(dlt[i0b])*sigmf(alp[i0b]);
    float q1b = 1.f - sigmf(dlt[i1b])*sigmf(alp[i1b]);

    float f0 = 0.f, f1 = 0.f, a0 = 0.f, a1 = 0.f, pw0 = 1.f, pw1 = 1.f;
    size_t idx = (size_t)(c*CHL)*8192 + bd;
    #pragma unroll 4
    for (int j = 0; j < CHL; j++, idx += 8192) {
        float xv = x[idx];
        f0 = fmaf(q0f, f0, xv);
        f1 = fmaf(q1f, f1, xv);
        a0 = fmaf(pw0, xv, a0);
        a1 = fmaf(pw1, xv, a1);
        pw0 *= q0b; pw1 *= q1b;
        split2(xv, xs_h[idx], xs_l[idx]);
    }
    int o = c*8192 + bd;
    e_st[0*NCH*8192 + o] = f0;
    e_st[1*NCH*8192 + o] = f1;
    e_st[2*NCH*8192 + o] = a0;
    e_st[3*NCH*8192 + o] = a1;
}

// ---------------- EMA phase 2: cross-chunk prefix/suffix combine ----------------
__global__ void __launch_bounds__(256) ema_p2(
    const float* __restrict__ dlt, const float* __restrict__ alp)
{
    int bd = blockIdx.x*256 + threadIdx.x;     // 0..8191
    int d = bd & 511;
    int i0f = d*2, i1f = d*2 + 1;
    int i0b = (512 + d)*2, i1b = i0b + 1;
    float q0f = 1.f - sigmf(dlt[i0f])*sigmf(alp[i0f]);
    float q1f = 1.f - sigmf(dlt[i1f])*sigmf(alp[i1f]);
    float q0b = 1.f - sigmf(dlt[i0b])*sigmf(alp[i0b]);
    float q1b = 1.f - sigmf(dlt[i1b])*sigmf(alp[i1b]);
    // q^128 via 7 squarings
    float q0f8 = q0f, q1f8 = q1f, q0b8 = q0b, q1b8 = q1b;
    #pragma unroll
    for (int i = 0; i < 7; i++) { q0f8 *= q0f8; q1f8 *= q1f8; q0b8 *= q0b8; q1b8 *= q1b8; }

    float P0 = 0.f, P1 = 0.f;
    #pragma unroll
    for (int c = 0; c < NCH; c++) {
        int o = c*8192 + bd;
        seed_st[0*NCH*8192 + o] = P0;
        seed_st[1*NCH*8192 + o] = P1;
        P0 = fmaf(q0f8, P0, e_st[0*NCH*8192 + o]);
        P1 = fmaf(q1f8, P1, e_st[1*NCH*8192 + o]);
    }
    float T0 = 0.f, T1 = 0.f;
    #pragma unroll
    for (int c = NCH-1; c >= 0; c--) {
        int o = c*8192 + bd;
        seed_st[2*NCH*8192 + o] = T0;
        seed_st[3*NCH*8192 + o] = T1;
        T0 = fmaf(q0b8, T0, e_st[2*NCH*8192 + o]);
        T1 = fmaf(q1b8, T1, e_st[3*NCH*8192 + o]);
    }
}

// ---------------- EMA phase 3: seeded scans, fused combine + silu + split -------
__global__ void __launch_bounds__(128) ema_p3(
    const float* __restrict__ x, const float* __restrict__ dlt,
    const float* __restrict__ alp, const float* __restrict__ bet,
    const float* __restrict__ gam, const float* __restrict__ omg)
{
    extern __shared__ float ybuf[];            // [CHL][128]
    int t = blockIdx.x*128 + threadIdx.x;      // 0..131071
    int tid = threadIdx.x;
    int c = t >> 13, bd = t & 8191;
    int d = bd & 511;
    const float invs = 0.7071067811865476f;

    int i0f = d*2, i1f = d*2 + 1;
    int i0b = (512 + d)*2, i1b = i0b + 1;
    float p0f = sigmf(dlt[i0f]), p1f = sigmf(dlt[i1f]);
    float p0b = sigmf(dlt[i0b]), p1b = sigmf(dlt[i1b]);
    float q0f = 1.f - p0f*sigmf(alp[i0f]);
    float q1f = 1.f - p1f*sigmf(alp[i1f]);
    float q0b = 1.f - p0b*sigmf(alp[i0b]);
    float q1b = 1.f - p1b*sigmf(alp[i1b]);
    float w0f = p0f*bet[i0f]*gam[i0f]*invs;
    float w1f = p1f*bet[i1f]*gam[i1f]*invs;
    float w0b = p0b*bet[i0b]*gam[i0b]*invs;
    float w1b = p1b*bet[i1b]*gam[i1b]*invs;
    float ow = omg[d];

    int o = c*8192 + bd;
    size_t base = (size_t)(c*CHL)*8192 + bd;

    // descending bwd scan, stash partial in smem (per-thread private)
    {
        float g0 = seed_st[2*NCH*8192 + o];
        float g1 = seed_st[3*NCH*8192 + o];
        size_t idx = base + (size_t)(CHL-1)*8192;
        #pragma unroll 4
        for (int j = CHL-1; j >= 0; j--, idx -= 8192) {
            float xv = x[idx];
            g0 = fmaf(q0b, g0, xv);
            g1 = fmaf(q1b, g1, xv);
            ybuf[j*128 + tid] = fmaf(w0b, g0, w1b*g1);
        }
    }
    // ascending fwd scan + combine + silu + split
    {
        float f0 = seed_st[0*NCH*8192 + o];
        float f1 = seed_st[1*NCH*8192 + o];
        size_t idx = base;
        #pragma unroll 4
        for (int j = 0; j < CHL; j++, idx += 8192) {
            float xv = x[idx];
            f0 = fmaf(q0f, f0, xv);
            f1 = fmaf(q1f, f1, xv);
            float y = ybuf[j*128 + tid] + fmaf(w0f, f0, fmaf(w1f, f1, xv*ow));
            split2(siluf(y), mxs_h[idx], mxs_l[idx]);
        }
    }
}

// ---------------- pipelined split-bf16 tensor-core GEMM (3-stage ring) ----------
// MODE 0: vs    = split(silu(xs @ Wv + bv))        TM=256 N=1024 K=512
// MODE 1: g_base= act(mxs @ Wmx + bmx)             TM=256 N=2176 K=512
// MODE 2: g_o   = gate(silu(hr @ Wh + bh + hx))    TM=256 N=512  K=1024
// MODE 3: hr    = split((attn @ v) * r)  (256 bat) TM=128 N=1024 K=128
template<int MODE>
__global__ void __launch_bounds__((MODE==3)?256:512, 1) mma_gemm(
    const float* __restrict__ Xres, const float* __restrict__ bias)
{
    constexpr int TM  = (MODE==3) ? 128 : 256;
    constexpr int NTH = (MODE==3) ? 256 : 512;
    constexpr int WM  = TM/64;
    constexpr int K   = (MODE==2) ? 1024 : (MODE==3) ? 128 : 512;
    constexpr int ldA = (MODE==2) ? 1024 : (MODE==3) ? 128 : 512;
    constexpr int ldB = (MODE==0) ? 1024 : (MODE==1) ? 2176 : (MODE==2) ? 512 : 16384;
    constexpr int NK  = K/32;
    constexpr int APS = TM*80;
    constexpr int BOFF = 2*APS;
    constexpr int STAGE = BOFF + 2*8192;
    constexpr int NA_E = (2*TM*4)/NTH;
    constexpr int NB_E = 1024/NTH;

    extern __shared__ __align__(128) char smem_raw[];
    const uint32_t sb = (uint32_t)__cvta_generic_to_shared(smem_raw);

    const int t = threadIdx.x;
    const int warp = t >> 5, lane = t & 31;
    const int wm = warp % WM, wn = warp / WM;
    const int group = lane >> 2, tid4 = lane & 3;
    const int mat = lane >> 3, rim = lane & 7;
    const int rOff = ((mat & 1) << 3) + rim;
    const int cOff = mat >> 1;

    const int bn = blockIdx.x * 128;
    const int bm = (MODE==3) ? 0 : blockIdx.y * TM;

    int bb = 0, cc = 0, batch = 0;
    if (MODE == 3) { batch = blockIdx.z; bb = batch >> 4; cc = batch & 15; }

    const __nv_bfloat16 *pA0, *pA1, *pB0, *pB1;
    if (MODE == 0) { pA0 = xs_h  + (size_t)bm*ldA; pA1 = xs_l  + (size_t)bm*ldA;
                     pB0 = wv_h  + bn;             pB1 = wv_l  + bn; }
    else if (MODE == 1) { pA0 = mxs_h + (size_t)bm*ldA; pA1 = mxs_l + (size_t)bm*ldA;
                          pB0 = wmx_h + bn;             pB1 = wmx_l + bn; }
    else if (MODE == 2) { pA0 = hr_h  + (size_t)bm*ldA; pA1 = hr_l  + (size_t)bm*ldA;
                          pB0 = wh_h  + bn;             pB1 = wh_l  + bn; }
    else { pA0 = at_h + (size_t)batch*16384; pA1 = at_l + (size_t)batch*16384;
           size_t vb = (size_t)(cc*2048 + bb)*H_ + bn;
           pB0 = vs_h + vb; pB1 = vs_l + vb; }

    const __nv_bfloat16* gA[NA_E]; uint32_t sA[NA_E];
    #pragma unroll
    for (int e = 0; e < NA_E; e++) {
        int idx = e*NTH + t;
        int plane = idx / (TM*4), w = idx % (TM*4);
        int r = w >> 2, c = w & 3;
        gA[e] = (plane ? pA1 : pA0) + (size_t)r*ldA + c*8;
        sA[e] = sb + plane*APS + r*80 + (c << 4);
    }
    const __nv_bfloat16* gB[NB_E]; uint32_t sB[NB_E];
    #pragma unroll
    for (int e = 0; e < NB_E; e++) {
        int idx = e*NTH + t;
        int plane = idx >> 9, w = idx & 511;
        int r = w >> 4, c = w & 15;
        gB[e] = (plane ? pB1 : pB0) + (size_t)r*ldB + c*8;
        sB[e] = sb + BOFF + plane*8192 + r*256 + (((uint32_t)(c ^ (r & 7))) << 4);
    }

    auto load_chunk = [&](int ck) {
        uint32_t so = (uint32_t)(ck % 3) * STAGE;
        int ka = ck * 32;
        #pragma unroll
        for (int e = 0; e < NA_E; e++) CPA16(sA[e] + so, gA[e] + ka);
        #pragma unroll
        for (int e = 0; e < NB_E; e++) CPA16(sB[e] + so, gB[e] + (size_t)ka*ldB);
        asm volatile("cp.async.commit_group;");
    };

    float acc[4][4][4];
    #pragma unroll
    for (int a = 0; a < 4; a++)
        #pragma unroll
        for (int b2 = 0; b2 < 4; b2++)
            #pragma unroll
            for (int e = 0; e < 4; e++) acc[a][b2][e] = 0.f;

    load_chunk(0);
    load_chunk(1);

    for (int it = 0; it < NK; it++) {
        if (it + 1 < NK) asm volatile("cp.async.wait_group 1;" ::: "memory");
        else             asm volatile("cp.async.wait_group 0;" ::: "memory");
        __syncthreads();
        if (it + 2 < NK) load_chunk(it + 2);

        const uint32_t stg = sb + (uint32_t)(it % 3)*STAGE;
        #pragma unroll
        for (int ks = 0; ks < 2; ks++) {
            #pragma unroll
            for (int mp = 0; mp < 2; mp++) {
                uint32_t ah[2][4], al[2][4];
                #pragma unroll
                for (int ml = 0; ml < 2; ml++) {
                    int row = wm*64 + (mp*2 + ml)*16 + rOff;
                    uint32_t ad = stg + row*80 + ((uint32_t)(ks*2 + cOff) << 4);
                    LDSM4(ah[ml][0], ah[ml][1], ah[ml][2], ah[ml][3], ad);
                    LDSM4(al[ml][0], al[ml][1], al[ml][2], al[ml][3], ad + APS);
                }
                #pragma unroll
                for (int g = 0; g < 2; g++) {
                    int kin = ks*16 + rOff;
                    int cB = wn*4 + g*2 + cOff;
                    uint32_t bd = stg + BOFF + kin*256 + (((uint32_t)(cB ^ (kin & 7))) << 4);
                    uint32_t bh0,bh1,bh2,bh3, bl0,bl1,bl2,bl3;
                    LDSM4T(bh0,bh1,bh2,bh3, bd);
                    LDSM4T(bl0,bl1,bl2,bl3, bd + 8192);
                    #pragma unroll
                    for (int ml = 0; ml < 2; ml++) {
                        int mt = mp*2 + ml;
                        MMA16816(acc[mt][g*2],   ah[ml], bh0, bh1);
                        MMA16816(acc[mt][g*2],   ah[ml], bl0, bl1);
                        MMA16816(acc[mt][g*2],   al[ml], bh0, bh1);
                        MMA16816(acc[mt][g*2+1], ah[ml], bh2, bh3);
                        MMA16816(acc[mt][g*2+1], ah[ml], bl2, bl3);
                        MMA16816(acc[mt][g*2+1], al[ml], bh2, bh3);
                    }
                }
            }
        }
        __syncthreads();
    }

    #pragma unroll
    for (int mt = 0; mt < 4; mt++) {
        #pragma unroll
        for (int nt = 0; nt < 4; nt++) {
            #pragma unroll
            for (int half = 0; half < 2; half++) {
                int m = bm + wm*64 + mt*16 + group + half*8;
                #pragma unroll
                for (int e = 0; e < 2; e++) {
                    int n = bn + wn*32 + nt*8 + tid4*2 + e;
                    float v = acc[mt][nt][half*2 + e];
                    if (MODE == 0) {
                        float s = siluf(v + bias[n]);
                        split2(s, vs_h[(size_t)m*H_ + n], vs_l[(size_t)m*H_ + n]);
                    } else if (MODE == 1) {
                        v += bias[n];
                        if (n < 512)       v = sigmf(v);
                        else if (n < 1664) v = siluf(v);
                        g_base[(size_t)m*NBASE + n] = v;
                    } else if (MODE == 2) {
                        float hx = g_base[(size_t)m*NBASE + 1664 + n];
                        float s  = siluf(v + bias[n] + hx);
                        float u  = g_base[(size_t)m*NBASE + n];
                        float xr = Xres[(size_t)m*D_ + n];
                        g_o[(size_t)m*D_ + n] = xr + u*(s - xr);
                    } else {
                        size_t row = (size_t)(cc*128 + m)*B_ + bb;
                        float rv = g_base[row*NBASE + 640 + n];
                        split2(v*rv, hr_h[row*H_ + n], hr_l[row*H_ + n]);
                    }
                }
            }
        }
    }
}

// ---------------- QK + softmax ----------------
__global__ void __launch_bounds__(256) qk_kernel(
    const float* __restrict__ qkg, const float* __restrict__ qkb,
    const float* __restrict__ rp, float* __restrict__ attn_out)
{
    extern __shared__ float sm[];
    float* qT = sm;
    float* kT = sm + 16384;
    float* sT = sm + 32768;
    float* red = sm;

    const int b = blockIdx.x >> 4;
    const int c = blockIdx.x & 15;
    const int t = threadIdx.x;
    const float qscale = 0.08838834764831845f;

    for (int idx = t; idx < 16384; idx += 256) {
        int i = idx >> 7, z = idx & 127;
        int row = (c*128 + i)*B_ + b;
        float zv = g_base[(size_t)row*NBASE + 512 + z];
        qT[z*128 + i] = (zv*qkg[z]     + qkb[z]    ) * qscale;
        kT[z*128 + i] =  zv*qkg[128+z] + qkb[128+z];
    }
    __syncthreads();

    {
        const int tx = t & 15, ty = t >> 4;
        const int i0 = ty*8, j0 = tx*8;
        float acc[8][8];
        #pragma unroll
        for (int i = 0; i < 8; i++)
            #pragma unroll
            for (int j = 0; j < 8; j++) acc[i][j] = 0.f;

        #pragma unroll 4
        for (int z = 0; z < 128; z++) {
            float qa[8], ka[8];
            *(float4*)(qa)   = *(const float4*)&qT[z*128 + i0];
            *(float4*)(qa+4) = *(const float4*)&qT[z*128 + i0 + 4];
            *(float4*)(ka)   = *(const float4*)&kT[z*128 + j0];
            *(float4*)(ka+4) = *(const float4*)&kT[z*128 + j0 + 4];
            #pragma unroll
            for (int i = 0; i < 8; i++)
                #pragma unroll
                for (int j = 0; j < 8; j++)
                    acc[i][j] = fmaf(qa[i], ka[j], acc[i][j]);
        }
        #pragma unroll
        for (int r = 0; r < 8; r++)
            #pragma unroll
            for (int cc2 = 0; cc2 < 8; cc2++) {
                int i = i0 + r, j = j0 + cc2;
                sT[j*132 + i] = acc[r][cc2] + rp[1023 + j - i];
            }
    }
    __syncthreads();

    {
        const int i = t & 127, half = t >> 7;
        const int jb = half*64;
        float mx = -1e30f;
        for (int j = jb; j < jb + 64; j++) mx = fmaxf(mx, sT[j*132 + i]);
        red[half*128 + i] = mx;
        __syncthreads();
        float M = fmaxf(red[i], red[128 + i]);
        float s = 0.f;
        for (int j = jb; j < jb + 64; j++) {
            float e = expf(sT[j*132 + i] - M);
            sT[j*132 + i] = e;
            s += e;
        }
        red[256 + half*128 + i] = s;
        __syncthreads();
        if (half == 0) red[512 + i] = 1.f / (red[256 + i] + red[384 + i]);
        __syncthreads();
    }

    size_t base = (size_t)(b*NC_ + c)*16384;
    float* aout = attn_out + base;
    for (int idx = t; idx < 16384; idx += 256) {
        int i = idx >> 7, j = idx & 127;
        float p = sT[j*132 + i] * red[512 + i];
        aout[idx] = p;
        split2(p, at_h[base + idx], at_l[base + idx]);
    }
}

// ---------------- final rmsnorm ----------------
__global__ void __launch_bounds__(256) norm_kernel(
    const float* __restrict__ ns, float* __restrict__ out)
{
    int row  = blockIdx.x*8 + (threadIdx.x >> 5);
    int lane = threadIdx.x & 31;
    const float* op = g_o + (size_t)row*512;
    float vals[16];
    float ss = 0.f;
    #pragma unroll
    for (int k = 0; k < 16; k++) {
        float v = op[lane + k*32];
        vals[k] = v;
        ss += v*v;
    }
    #pragma unroll
    for (int off = 16; off; off >>= 1) ss += __shfl_xor_sync(0xffffffffu, ss, off);
    float scale = ns[0] * rsqrtf(ss*(1.f/512.f) + 1e-6f);
    float* outp = out + (size_t)row*512;
    #pragma unroll
    for (int k = 0; k < 16; k++) outp[lane + k*32] = vals[k]*scale;
}

// ---------------- launch ----------------
extern "C" void kernel_launch(void* const* d_in, const int* in_sizes, int n_in,
                              void* d_out, int out_size)
{
    const float* x   = (const float*)d_in[0];
    const float* edl = (const float*)d_in[1];
    const float* eal = (const float*)d_in[2];
    const float* ebt = (const float*)d_in[3];
    const float* egm = (const float*)d_in[4];
    const float* eom = (const float*)d_in[5];
    const float* Wv  = (const float*)d_in[6];
    const float* bv  = (const float*)d_in[7];
    const float* Wmx = (const float*)d_in[8];
    const float* bmx = (const float*)d_in[9];
    const float* Wh  = (const float*)d_in[10];
    const float* bh  = (const float*)d_in[11];
    const float* qkg = (const float*)d_in[12];
    const float* qkb = (const float*)d_in[13];
    const float* rp  = (const float*)d_in[14];
    const float* ns  = (const float*)d_in[15];

    float* out      = (float*)d_out;
    float* attn_out = out + (size_t)L_*B_*D_;

    static __nv_bfloat16 *p_wvh=nullptr,*p_wvl,*p_wmxh,*p_wmxl,*p_whh,*p_whl;
    if (!p_wvh) {
        cudaGetSymbolAddress((void**)&p_wvh,  wv_h);
        cudaGetSymbolAddress((void**)&p_wvl,  wv_l);
        cudaGetSymbolAddress((void**)&p_wmxh, wmx_h);
        cudaGetSymbolAddress((void**)&p_wmxl, wmx_l);
        cudaGetSymbolAddress((void**)&p_whh,  wh_h);
        cudaGetSymbolAddress((void**)&p_whl,  wh_l);
        cudaFuncSetAttribute(qk_kernel,   cudaFuncAttributeMaxDynamicSharedMemorySize, 198656);
        cudaFuncSetAttribute(ema_p3,      cudaFuncAttributeMaxDynamicSharedMemorySize, 65536);
        cudaFuncSetAttribute(mma_gemm<0>, cudaFuncAttributeMaxDynamicSharedMemorySize, 172032);
        cudaFuncSetAttribute(mma_gemm<1>, cudaFuncAttributeMaxDynamicSharedMemorySize, 172032);
        cudaFuncSetAttribute(mma_gemm<2>, cudaFuncAttributeMaxDynamicSharedMemorySize, 172032);
        cudaFuncSetAttribute(mma_gemm<3>, cudaFuncAttributeMaxDynamicSharedMemorySize, 110592);
    }

    split_kernel<<<512,  256>>>(Wv,  p_wvh,  p_wvl);
    split_kernel<<<1088, 256>>>(Wmx, p_wmxh, p_wmxl);
    split_kernel<<<512,  256>>>(Wh,  p_whh,  p_whl);

    ema_p1<<<512, 256>>>(x, edl, eal);
    ema_p2<<<32, 256>>>(edl, eal);
    ema_p3<<<1024, 128, 65536>>>(x, edl, eal, ebt, egm, eom);

    { dim3 g(8, 128);  mma_gemm<0><<<g, 512, 172032>>>(x, bv); }
    { dim3 g(17, 128); mma_gemm<1><<<g, 512, 172032>>>(x, bmx); }

    qk_kernel<<<B_*NC_, 256, 198656>>>(qkg, qkb, rp, attn_out);

    { dim3 g(8, 1, 256); mma_gemm<3><<<g, 256, 110592>>>(x, bv); }
    { dim3 g(4, 128);    mma_gemm<2><<<g, 512, 172032>>>(x, bh); }

    norm_kernel<<<MROWS/8, 256>>>(ns, out);
}

// round 9
// speedup vs baseline: 2.7087x; 1.1065x over previous
#include <cuda_runtime.h>
#include <cuda_bf16.h>
#include <stdint.h>
#include <math.h>

#define L_ 2048
#define B_ 16
#define D_ 512
#define H_ 1024
#define NC_ 16
#define NBASE 2176            // Z + H + 2D
#define MROWS (L_*B_)         // 32768
#define NCH 16                // EMA chunks
#define CHL 128               // chunk length

// ---------------- fp32 scratch ----------------
__device__ float g_base[MROWS*NBASE];  // activated base: [u | z | r | hx]
__device__ float g_o   [MROWS*D_];     // pre-norm output
__device__ float e_st  [4*NCH*8192];   // per-chunk local states [comp][c][bd]
__device__ float seed_st[4*NCH*8192];  // per-chunk seeds        [comp][c][bd]

// ---------------- split-bf16 planes (all natural layout) ----------------
__device__ __align__(16) __nv_bfloat16 xs_h [MROWS*D_],  xs_l [MROWS*D_];
__device__ __align__(16) __nv_bfloat16 mxs_h[MROWS*D_],  mxs_l[MROWS*D_];
__device__ __align__(16) __nv_bfloat16 vs_h [MROWS*H_],  vs_l [MROWS*H_];   // v [m][h]
__device__ __align__(16) __nv_bfloat16 hr_h [MROWS*H_],  hr_l [MROWS*H_];   // h*r [m][h]
__device__ __align__(16) __nv_bfloat16 at_h [B_*NC_*128*128], at_l[B_*NC_*128*128];
__device__ __align__(16) __nv_bfloat16 wv_h [512*1024],  wv_l [512*1024];   // [k][n]
__device__ __align__(16) __nv_bfloat16 wmx_h[512*2176],  wmx_l[512*2176];   // [k][n]
__device__ __align__(16) __nv_bfloat16 wh_h [1024*512],  wh_l [1024*512];   // [k][n]

__device__ __forceinline__ float sigmf(float x){ return 1.0f/(1.0f + expf(-x)); }
__device__ __forceinline__ float siluf(float x){ return x/(1.0f + expf(-x)); }
__device__ __forceinline__ void split2(float v, __nv_bfloat16& h, __nv_bfloat16& l){
    h = __float2bfloat16_rn(v);
    l = __float2bfloat16_rn(v - __bfloat162float(h));
}

#define MMA16816(d, a, b0, b1) \
  asm volatile("mma.sync.aligned.m16n8k16.row.col.f32.bf16.bf16.f32 " \
    "{%0,%1,%2,%3}, {%4,%5,%6,%7}, {%8,%9}, {%0,%1,%2,%3};" \
    : "+f"(d[0]), "+f"(d[1]), "+f"(d[2]), "+f"(d[3]) \
    : "r"(a[0]), "r"(a[1]), "r"(a[2]), "r"(a[3]), "r"(b0), "r"(b1))

#define LDSM4(r0,r1,r2,r3,a) \
  asm volatile("ldmatrix.sync.aligned.m8n8.x4.shared.b16 {%0,%1,%2,%3}, [%4];" \
    : "=r"(r0),"=r"(r1),"=r"(r2),"=r"(r3) : "r"(a))

#define LDSM4T(r0,r1,r2,r3,a) \
  asm volatile("ldmatrix.sync.aligned.m8n8.x4.trans.shared.b16 {%0,%1,%2,%3}, [%4];" \
    : "=r"(r0),"=r"(r1),"=r"(r2),"=r"(r3) : "r"(a))

#define CPA16(s,g) asm volatile("cp.async.cg.shared.global [%0], [%1], 16;" :: "r"(s), "l"(g))

// ---------------- generic fp32 -> split-bf16 (weights) ----------------
__global__ void __launch_bounds__(256) split_kernel(
    const float* __restrict__ src, __nv_bfloat16* __restrict__ oh,
    __nv_bfloat16* __restrict__ ol)
{
    size_t i4 = (size_t)blockIdx.x*256 + threadIdx.x;
    float4 v = *(const float4*)&src[i4*4];
    size_t o = i4*4;
    split2(v.x, oh[o+0], ol[o+0]);
    split2(v.y, oh[o+1], ol[o+1]);
    split2(v.z, oh[o+2], ol[o+2]);
    split2(v.w, oh[o+3], ol[o+3]);
}

// ---------------- EMA phase 1: per-chunk local states + x split ----------------
__global__ void __launch_bounds__(256) ema_p1(
    const float* __restrict__ x, const float* __restrict__ dlt,
    const float* __restrict__ alp)
{
    int t = blockIdx.x*256 + threadIdx.x;      // 0..131071
    int c = t >> 13, bd = t & 8191;
    int d = bd & 511;
    int i0f = d*2, i1f = d*2 + 1;
    int i0b = (512 + d)*2, i1b = i0b + 1;
    float q0f = 1.f - sigmf(dlt[i0f])*sigmf(alp[i0f]);
    float q1f = 1.f - sigmf(dlt[i1f])*sigmf(alp[i1f]);
    float q0b = 1.f - sigmf(dlt[i0b])*sigmf(alp[i0b]);
    float q1b = 1.f - sigmf(dlt[i1b])*sigmf(alp[i1b]);

    float f0 = 0.f, f1 = 0.f, a0 = 0.f, a1 = 0.f, pw0 = 1.f, pw1 = 1.f;
    size_t idx = (size_t)(c*CHL)*8192 + bd;
    #pragma unroll 4
    for (int j = 0; j < CHL; j++, idx += 8192) {
        float xv = x[idx];
        f0 = fmaf(q0f, f0, xv);
        f1 = fmaf(q1f, f1, xv);
        a0 = fmaf(pw0, xv, a0);
        a1 = fmaf(pw1, xv, a1);
        pw0 *= q0b; pw1 *= q1b;
        split2(xv, xs_h[idx], xs_l[idx]);
    }
    int o = c*8192 + bd;
    e_st[0*NCH*8192 + o] = f0;
    e_st[1*NCH*8192 + o] = f1;
    e_st[2*NCH*8192 + o] = a0;
    e_st[3*NCH*8192 + o] = a1;
}

// ---------------- EMA phase 2: cross-chunk prefix/suffix combine ----------------
__global__ void __launch_bounds__(256) ema_p2(
    const float* __restrict__ dlt, const float* __restrict__ alp)
{
    int bd = blockIdx.x*256 + threadIdx.x;     // 0..8191
    int d = bd & 511;
    int i0f = d*2, i1f = d*2 + 1;
    int i0b = (512 + d)*2, i1b = i0b + 1;
    float q0f = 1.f - sigmf(dlt[i0f])*sigmf(alp[i0f]);
    float q1f = 1.f - sigmf(dlt[i1f])*sigmf(alp[i1f]);
    float q0b = 1.f - sigmf(dlt[i0b])*sigmf(alp[i0b]);
    float q1b = 1.f - sigmf(dlt[i1b])*sigmf(alp[i1b]);
    float q0f8 = q0f, q1f8 = q1f, q0b8 = q0b, q1b8 = q1b;
    #pragma unroll
    for (int i = 0; i < 7; i++) { q0f8 *= q0f8; q1f8 *= q1f8; q0b8 *= q0b8; q1b8 *= q1b8; }

    float P0 = 0.f, P1 = 0.f;
    #pragma unroll
    for (int c = 0; c < NCH; c++) {
        int o = c*8192 + bd;
        seed_st[0*NCH*8192 + o] = P0;
        seed_st[1*NCH*8192 + o] = P1;
        P0 = fmaf(q0f8, P0, e_st[0*NCH*8192 + o]);
        P1 = fmaf(q1f8, P1, e_st[1*NCH*8192 + o]);
    }
    float T0 = 0.f, T1 = 0.f;
    #pragma unroll
    for (int c = NCH-1; c >= 0; c--) {
        int o = c*8192 + bd;
        seed_st[2*NCH*8192 + o] = T0;
        seed_st[3*NCH*8192 + o] = T1;
        T0 = fmaf(q0b8, T0, e_st[2*NCH*8192 + o]);
        T1 = fmaf(q1b8, T1, e_st[3*NCH*8192 + o]);
    }
}

// ---------------- EMA phase 3: seeded scans, fused combine + silu + split -------
__global__ void __launch_bounds__(128) ema_p3(
    const float* __restrict__ x, const float* __restrict__ dlt,
    const float* __restrict__ alp, const float* __restrict__ bet,
    const float* __restrict__ gam, const float* __restrict__ omg)
{
    extern __shared__ float ybuf[];            // [CHL][128]
    int t = blockIdx.x*128 + threadIdx.x;
    int tid = threadIdx.x;
    int c = t >> 13, bd = t & 8191;
    int d = bd & 511;
    const float invs = 0.7071067811865476f;

    int i0f = d*2, i1f = d*2 + 1;
    int i0b = (512 + d)*2, i1b = i0b + 1;
    float p0f = sigmf(dlt[i0f]), p1f = sigmf(dlt[i1f]);
    float p0b = sigmf(dlt[i0b]), p1b = sigmf(dlt[i1b]);
    float q0f = 1.f - p0f*sigmf(alp[i0f]);
    float q1f = 1.f - p1f*sigmf(alp[i1f]);
    float q0b = 1.f - p0b*sigmf(alp[i0b]);
    float q1b = 1.f - p1b*sigmf(alp[i1b]);
    float w0f = p0f*bet[i0f]*gam[i0f]*invs;
    float w1f = p1f*bet[i1f]*gam[i1f]*invs;
    float w0b = p0b*bet[i0b]*gam[i0b]*invs;
    float w1b = p1b*bet[i1b]*gam[i1b]*invs;
    float ow = omg[d];

    int o = c*8192 + bd;
    size_t base = (size_t)(c*CHL)*8192 + bd;

    {
        float g0 = seed_st[2*NCH*8192 + o];
        float g1 = seed_st[3*NCH*8192 + o];
        size_t idx = base + (size_t)(CHL-1)*8192;
        #pragma unroll 4
        for (int j = CHL-1; j >= 0; j--, idx -= 8192) {
            float xv = x[idx];
            g0 = fmaf(q0b, g0, xv);
            g1 = fmaf(q1b, g1, xv);
            ybuf[j*128 + tid] = fmaf(w0b, g0, w1b*g1);
        }
    }
    {
        float f0 = seed_st[0*NCH*8192 + o];
        float f1 = seed_st[1*NCH*8192 + o];
        size_t idx = base;
        #pragma unroll 4
        for (int j = 0; j < CHL; j++, idx += 8192) {
            float xv = x[idx];
            f0 = fmaf(q0f, f0, xv);
            f1 = fmaf(q1f, f1, xv);
            float y = ybuf[j*128 + tid] + fmaf(w0f, f0, fmaf(w1f, f1, xv*ow));
            split2(siluf(y), mxs_h[idx], mxs_l[idx]);
        }
    }
}

// ---------------- pipelined split-bf16 tensor-core GEMM ----------------
// 128x128 tile, 256 threads, 3-stage ring, 2 CTAs/SM, B-frags hoisted.
// MODE 0: vs    = split(silu(xs @ Wv + bv))        N=1024 K=512
// MODE 1: g_base= act(mxs @ Wmx + bmx)             N=2176 K=512
// MODE 2: g_o   = gate(silu(hr @ Wh + bh + hx))    N=512  K=1024
// MODE 3: hr    = split((attn @ v) * r)  (256 bat) N=1024 K=128
template<int MODE>
__global__ void __launch_bounds__(256, 2) mma_gemm(
    const float* __restrict__ Xres, const float* __restrict__ bias)
{
    constexpr int K   = (MODE==2) ? 1024 : (MODE==3) ? 128 : 512;
    constexpr int ldA = (MODE==2) ? 1024 : (MODE==3) ? 128 : 512;
    constexpr int ldB = (MODE==0) ? 1024 : (MODE==1) ? 2176 : (MODE==2) ? 512 : 16384;
    constexpr int NK  = K/32;
    constexpr int APS = 128*80;               // 10240: A plane bytes per stage
    constexpr int BOFF = 2*APS;               // 20480
    constexpr int STAGE = BOFF + 2*8192;      // 36864

    extern __shared__ __align__(128) char smem_raw[];
    const uint32_t sb = (uint32_t)__cvta_generic_to_shared(smem_raw);

    const int t = threadIdx.x;
    const int warp = t >> 5, lane = t & 31;
    const int wm = warp & 1, wn = warp >> 1;        // 2m x 4n
    const int group = lane >> 2, tid4 = lane & 3;
    const int mat = lane >> 3, rim = lane & 7;
    const int rOff = ((mat & 1) << 3) + rim;
    const int cOff = mat >> 1;

    const int bn = blockIdx.x * 128;
    const int bm = (MODE==3) ? 0 : blockIdx.y * 128;

    int bb = 0, cc = 0, batch = 0;
    if (MODE == 3) { batch = blockIdx.z; bb = batch >> 4; cc = batch & 15; }

    const __nv_bfloat16 *pA0, *pA1, *pB0, *pB1;
    if (MODE == 0) { pA0 = xs_h  + (size_t)bm*ldA; pA1 = xs_l  + (size_t)bm*ldA;
                     pB0 = wv_h  + bn;             pB1 = wv_l  + bn; }
    else if (MODE == 1) { pA0 = mxs_h + (size_t)bm*ldA; pA1 = mxs_l + (size_t)bm*ldA;
                          pB0 = wmx_h + bn;             pB1 = wmx_l + bn; }
    else if (MODE == 2) { pA0 = hr_h  + (size_t)bm*ldA; pA1 = hr_l  + (size_t)bm*ldA;
                          pB0 = wh_h  + bn;             pB1 = wh_l  + bn; }
    else { pA0 = at_h + (size_t)batch*16384; pA1 = at_l + (size_t)batch*16384;
           size_t vb = (size_t)(cc*2048 + bb)*H_ + bn;
           pB0 = vs_h + vb; pB1 = vs_l + vb; }

    // cp.async descriptors: NA_E = NB_E = 4 at 256 threads
    const __nv_bfloat16* gA[4]; uint32_t sA[4];
    #pragma unroll
    for (int e = 0; e < 4; e++) {
        int idx = e*256 + t;                  // 0..1023
        int plane = idx >> 9, w = idx & 511;
        int r = w >> 2, c = w & 3;
        gA[e] = (plane ? pA1 : pA0) + (size_t)r*ldA + c*8;
        sA[e] = sb + plane*APS + r*80 + (c << 4);
    }
    const __nv_bfloat16* gB[4]; uint32_t sB[4];
    #pragma unroll
    for (int e = 0; e < 4; e++) {
        int idx = e*256 + t;
        int plane = idx >> 9, w = idx & 511;
        int r = w >> 4, c = w & 15;
        gB[e] = (plane ? pB1 : pB0) + (size_t)r*ldB + c*8;
        sB[e] = sb + BOFF + plane*8192 + r*256 + (((uint32_t)(c ^ (r & 7))) << 4);
    }

    auto load_chunk = [&](int ck) {
        uint32_t so = (uint32_t)(ck % 3) * STAGE;
        int ka = ck * 32;
        #pragma unroll
        for (int e = 0; e < 4; e++) CPA16(sA[e] + so, gA[e] + ka);
        #pragma unroll
        for (int e = 0; e < 4; e++) CPA16(sB[e] + so, gB[e] + (size_t)ka*ldB);
        asm volatile("cp.async.commit_group;");
    };

    float acc[4][4][4];
    #pragma unroll
    for (int a = 0; a < 4; a++)
        #pragma unroll
        for (int b2 = 0; b2 < 4; b2++)
            #pragma unroll
            for (int e = 0; e < 4; e++) acc[a][b2][e] = 0.f;

    load_chunk(0);
    load_chunk(1);

    for (int it = 0; it < NK; it++) {
        if (it + 1 < NK) asm volatile("cp.async.wait_group 1;" ::: "memory");
        else             asm volatile("cp.async.wait_group 0;" ::: "memory");
        __syncthreads();
        if (it + 2 < NK) load_chunk(it + 2);

        const uint32_t stg = sb + (uint32_t)(it % 3)*STAGE;
        #pragma unroll
        for (int ks = 0; ks < 2; ks++) {
            // B fragments hoisted: loaded once per ks for both g
            uint32_t bh[2][4], bl[2][4];
            const int kin = ks*16 + rOff;
            #pragma unroll
            for (int g = 0; g < 2; g++) {
                int cB = wn*4 + g*2 + cOff;
                uint32_t bd = stg + BOFF + kin*256 + (((uint32_t)(cB ^ (kin & 7))) << 4);
                LDSM4T(bh[g][0], bh[g][1], bh[g][2], bh[g][3], bd);
                LDSM4T(bl[g][0], bl[g][1], bl[g][2], bl[g][3], bd + 8192);
            }
            #pragma unroll
            for (int mp = 0; mp < 2; mp++) {
                uint32_t ah[2][4], al[2][4];
                #pragma unroll
                for (int ml = 0; ml < 2; ml++) {
                    int row = wm*64 + (mp*2 + ml)*16 + rOff;
                    uint32_t ad = stg + row*80 + ((uint32_t)(ks*2 + cOff) << 4);
                    LDSM4(ah[ml][0], ah[ml][1], ah[ml][2], ah[ml][3], ad);
                    LDSM4(al[ml][0], al[ml][1], al[ml][2], al[ml][3], ad + APS);
                }
                #pragma unroll
                for (int g = 0; g < 2; g++) {
                    #pragma unroll
                    for (int ml = 0; ml < 2; ml++) {
                        int mt = mp*2 + ml;
                        MMA16816(acc[mt][g*2],   ah[ml], bh[g][0], bh[g][1]);
                        MMA16816(acc[mt][g*2],   ah[ml], bl[g][0], bl[g][1]);
                        MMA16816(acc[mt][g*2],   al[ml], bh[g][0], bh[g][1]);
                        MMA16816(acc[mt][g*2+1], ah[ml], bh[g][2], bh[g][3]);
                        MMA16816(acc[mt][g*2+1], ah[ml], bl[g][2], bl[g][3]);
                        MMA16816(acc[mt][g*2+1], al[ml], bh[g][2], bh[g][3]);
                    }
                }
            }
        }
        __syncthreads();
    }

    // ---- epilogue ----
    #pragma unroll
    for (int mt = 0; mt < 4; mt++) {
        #pragma unroll
        for (int nt = 0; nt < 4; nt++) {
            #pragma unroll
            for (int half = 0; half < 2; half++) {
                int m = bm + wm*64 + mt*16 + group + half*8;
                #pragma unroll
                for (int e = 0; e < 2; e++) {
                    int n = bn + wn*32 + nt*8 + tid4*2 + e;
                    float v = acc[mt][nt][half*2 + e];
                    if (MODE == 0) {
                        float s = siluf(v + bias[n]);
                        split2(s, vs_h[(size_t)m*H_ + n], vs_l[(size_t)m*H_ + n]);
                    } else if (MODE == 1) {
                        v += bias[n];
                        if (n < 512)       v = sigmf(v);
                        else if (n < 1664) v = siluf(v);
                        g_base[(size_t)m*NBASE + n] = v;
                    } else if (MODE == 2) {
                        float hx = g_base[(size_t)m*NBASE + 1664 + n];
                        float s  = siluf(v + bias[n] + hx);
                        float u  = g_base[(size_t)m*NBASE + n];
                        float xr = Xres[(size_t)m*D_ + n];
                        g_o[(size_t)m*D_ + n] = xr + u*(s - xr);
                    } else {
                        size_t row = (size_t)(cc*128 + m)*B_ + bb;
                        float rv = g_base[row*NBASE + 640 + n];
                        split2(v*rv, hr_h[row*H_ + n], hr_l[row*H_ + n]);
                    }
                }
            }
        }
    }
}

// ---------------- QK + softmax ----------------
__global__ void __launch_bounds__(256) qk_kernel(
    const float* __restrict__ qkg, const float* __restrict__ qkb,
    const float* __restrict__ rp, float* __restrict__ attn_out)
{
    extern __shared__ float sm[];
    float* qT = sm;
    float* kT = sm + 16384;
    float* sT = sm + 32768;
    float* red = sm;

    const int b = blockIdx.x >> 4;
    const int c = blockIdx.x & 15;
    const int t = threadIdx.x;
    const float qscale = 0.08838834764831845f;

    for (int idx = t; idx < 16384; idx += 256) {
        int i = idx >> 7, z = idx & 127;
        int row = (c*128 + i)*B_ + b;
        float zv = g_base[(size_t)row*NBASE + 512 + z];
        qT[z*128 + i] = (zv*qkg[z]     + qkb[z]    ) * qscale;
        kT[z*128 + i] =  zv*qkg[128+z] + qkb[128+z];
    }
    __syncthreads();

    {
        const int tx = t & 15, ty = t >> 4;
        const int i0 = ty*8, j0 = tx*8;
        float acc[8][8];
        #pragma unroll
        for (int i = 0; i < 8; i++)
            #pragma unroll
            for (int j = 0; j < 8; j++) acc[i][j] = 0.f;

        #pragma unroll 4
        for (int z = 0; z < 128; z++) {
            float qa[8], ka[8];
            *(float4*)(qa)   = *(const float4*)&qT[z*128 + i0];
            *(float4*)(qa+4) = *(const float4*)&qT[z*128 + i0 + 4];
            *(float4*)(ka)   = *(const float4*)&kT[z*128 + j0];
            *(float4*)(ka+4) = *(const float4*)&kT[z*128 + j0 + 4];
            #pragma unroll
            for (int i = 0; i < 8; i++)
                #pragma unroll
                for (int j = 0; j < 8; j++)
                    acc[i][j] = fmaf(qa[i], ka[j], acc[i][j]);
        }
        #pragma unroll
        for (int r = 0; r < 8; r++)
            #pragma unroll
            for (int cc2 = 0; cc2 < 8; cc2++) {
                int i = i0 + r, j = j0 + cc2;
                sT[j*132 + i] = acc[r][cc2] + rp[1023 + j - i];
            }
    }
    __syncthreads();

    {
        const int i = t & 127, half = t >> 7;
        const int jb = half*64;
        float mx = -1e30f;
        for (int j = jb; j < jb + 64; j++) mx = fmaxf(mx, sT[j*132 + i]);
        red[half*128 + i] = mx;
        __syncthreads();
        float M = fmaxf(red[i], red[128 + i]);
        float s = 0.f;
        for (int j = jb; j < jb + 64; j++) {
            float e = expf(sT[j*132 + i] - M);
            sT[j*132 + i] = e;
            s += e;
        }
        red[256 + half*128 + i] = s;
        __syncthreads();
        if (half == 0) red[512 + i] = 1.f / (red[256 + i] + red[384 + i]);
        __syncthreads();
    }

    size_t base = (size_t)(b*NC_ + c)*16384;
    float* aout = attn_out + base;
    for (int idx = t; idx < 16384; idx += 256) {
        int i = idx >> 7, j = idx & 127;
        float p = sT[j*132 + i] * red[512 + i];
        aout[idx] = p;
        split2(p, at_h[base + idx], at_l[base + idx]);
    }
}

// ---------------- final rmsnorm ----------------
__global__ void __launch_bounds__(256) norm_kernel(
    const float* __restrict__ ns, float* __restrict__ out)
{
    int row  = blockIdx.x*8 + (threadIdx.x >> 5);
    int lane = threadIdx.x & 31;
    const float* op = g_o + (size_t)row*512;
    float vals[16];
    float ss = 0.f;
    #pragma unroll
    for (int k = 0; k < 16; k++) {
        float v = op[lane + k*32];
        vals[k] = v;
        ss += v*v;
    }
    #pragma unroll
    for (int off = 16; off; off >>= 1) ss += __shfl_xor_sync(0xffffffffu, ss, off);
    float scale = ns[0] * rsqrtf(ss*(1.f/512.f) + 1e-6f);
    float* outp = out + (size_t)row*512;
    #pragma unroll
    for (int k = 0; k < 16; k++) outp[lane + k*32] = vals[k]*scale;
}

// ---------------- launch ----------------
extern "C" void kernel_launch(void* const* d_in, const int* in_sizes, int n_in,
                              void* d_out, int out_size)
{
    const float* x   = (const float*)d_in[0];
    const float* edl = (const float*)d_in[1];
    const float* eal = (const float*)d_in[2];
    const float* ebt = (const float*)d_in[3];
    const float* egm = (const float*)d_in[4];
    const float* eom = (const float*)d_in[5];
    const float* Wv  = (const float*)d_in[6];
    const float* bv  = (const float*)d_in[7];
    const float* Wmx = (const float*)d_in[8];
    const float* bmx = (const float*)d_in[9];
    const float* Wh  = (const float*)d_in[10];
    const float* bh  = (const float*)d_in[11];
    const float* qkg = (const float*)d_in[12];
    const float* qkb = (const float*)d_in[13];
    const float* rp  = (const float*)d_in[14];
    const float* ns  = (const float*)d_in[15];

    float* out      = (float*)d_out;
    float* attn_out = out + (size_t)L_*B_*D_;

    static __nv_bfloat16 *p_wvh=nullptr,*p_wvl,*p_wmxh,*p_wmxl,*p_whh,*p_whl;
    if (!p_wvh) {
        cudaGetSymbolAddress((void**)&p_wvh,  wv_h);
        cudaGetSymbolAddress((void**)&p_wvl,  wv_l);
        cudaGetSymbolAddress((void**)&p_wmxh, wmx_h);
        cudaGetSymbolAddress((void**)&p_wmxl, wmx_l);
        cudaGetSymbolAddress((void**)&p_whh,  wh_h);
        cudaGetSymbolAddress((void**)&p_whl,  wh_l);
        cudaFuncSetAttribute(qk_kernel,   cudaFuncAttributeMaxDynamicSharedMemorySize, 198656);
        cudaFuncSetAttribute(ema_p3,      cudaFuncAttributeMaxDynamicSharedMemorySize, 65536);
        cudaFuncSetAttribute(mma_gemm<0>, cudaFuncAttributeMaxDynamicSharedMemorySize, 110592);
        cudaFuncSetAttribute(mma_gemm<1>, cudaFuncAttributeMaxDynamicSharedMemorySize, 110592);
        cudaFuncSetAttribute(mma_gemm<2>, cudaFuncAttributeMaxDynamicSharedMemorySize, 110592);
        cudaFuncSetAttribute(mma_gemm<3>, cudaFuncAttributeMaxDynamicSharedMemorySize, 110592);
    }

    split_kernel<<<512,  256>>>(Wv,  p_wvh,  p_wvl);
    split_kernel<<<1088, 256>>>(Wmx, p_wmxh, p_wmxl);
    split_kernel<<<512,  256>>>(Wh,  p_whh,  p_whl);

    ema_p1<<<512, 256>>>(x, edl, eal);
    ema_p2<<<32, 256>>>(edl, eal);
    ema_p3<<<1024, 128, 65536>>>(x, edl, eal, ebt, egm, eom);

    { dim3 g(8, 256);  mma_gemm<0><<<g, 256, 110592>>>(x, bv); }
    { dim3 g(17, 256); mma_gemm<1><<<g, 256, 110592>>>(x, bmx); }

    qk_kernel<<<B_*NC_, 256, 198656>>>(qkg, qkb, rp, attn_out);

    { dim3 g(8, 1, 256); mma_gemm<3><<<g, 256, 110592>>>(x, bv); }
    { dim3 g(4, 256);    mma_gemm<2><<<g, 256, 110592>>>(x, bh); }

    norm_kernel<<<MROWS/8, 256>>>(ns, out);
}

// round 10
// speedup vs baseline: 3.4405x; 1.2702x over previous
#include <cuda_runtime.h>
#include <cuda_fp16.h>
#include <stdint.h>
#include <math.h>

#define L_ 2048
#define B_ 16
#define D_ 512
#define H_ 1024
#define NC_ 16
#define NBASE 2176            // Z + H + 2D
#define MROWS (L_*B_)         // 32768
#define NCH 16                // EMA chunks
#define CHL 128               // chunk length

// ---------------- fp32 scratch ----------------
__device__ float g_base[MROWS*NBASE];  // activated base: [u | z | r | hx]
__device__ float g_o   [MROWS*D_];     // pre-norm output
__device__ float e_st  [4*NCH*8192];   // per-chunk local states
__device__ float seed_st[4*NCH*8192];  // per-chunk seeds

// ---------------- fp16 planes: A operands split (hi+lo), B operands hi-only ------
__device__ __align__(16) __half xs_h [MROWS*D_],  xs_l [MROWS*D_];
__device__ __align__(16) __half mxs_h[MROWS*D_],  mxs_l[MROWS*D_];
__device__ __align__(16) __half hr_h [MROWS*H_],  hr_l [MROWS*H_];
__device__ __align__(16) __half at_h [B_*NC_*128*128], at_l[B_*NC_*128*128];
__device__ __align__(16) __half vs_h [MROWS*H_];                 // B side (AV)
__device__ __align__(16) __half wv_h [512*1024];                 // B side [k][n]
__device__ __align__(16) __half wmx_h[512*2176];
__device__ __align__(16) __half wh_h [1024*512];

__device__ __forceinline__ float sigmf(float x){ return 1.0f/(1.0f + expf(-x)); }
__device__ __forceinline__ float siluf(float x){ return x/(1.0f + expf(-x)); }
__device__ __forceinline__ void split2h(float v, __half& h, __half& l){
    h = __float2half_rn(v);
    l = __float2half_rn(v - __half2float(h));
}

#define MMA16816(d, a, b0, b1) \
  asm volatile("mma.sync.aligned.m16n8k16.row.col.f32.f16.f16.f32 " \
    "{%0,%1,%2,%3}, {%4,%5,%6,%7}, {%8,%9}, {%0,%1,%2,%3};" \
    : "+f"(d[0]), "+f"(d[1]), "+f"(d[2]), "+f"(d[3]) \
    : "r"(a[0]), "r"(a[1]), "r"(a[2]), "r"(a[3]), "r"(b0), "r"(b1))

#define LDSM4(r0,r1,r2,r3,a) \
  asm volatile("ldmatrix.sync.aligned.m8n8.x4.shared.b16 {%0,%1,%2,%3}, [%4];" \
    : "=r"(r0),"=r"(r1),"=r"(r2),"=r"(r3) : "r"(a))

#define LDSM4T(r0,r1,r2,r3,a) \
  asm volatile("ldmatrix.sync.aligned.m8n8.x4.trans.shared.b16 {%0,%1,%2,%3}, [%4];" \
    : "=r"(r0),"=r"(r1),"=r"(r2),"=r"(r3) : "r"(a))

#define CPA16(s,g) asm volatile("cp.async.cg.shared.global [%0], [%1], 16;" :: "r"(s), "l"(g))

// ---------------- weights: fp32 -> fp16 hi plane ----------------
__global__ void __launch_bounds__(256) splitw_kernel(
    const float* __restrict__ src, __half* __restrict__ oh)
{
    size_t i4 = (size_t)blockIdx.x*256 + threadIdx.x;
    float4 v = *(const float4*)&src[i4*4];
    size_t o = i4*4;
    oh[o+0] = __float2half_rn(v.x);
    oh[o+1] = __float2half_rn(v.y);
    oh[o+2] = __float2half_rn(v.z);
    oh[o+3] = __float2half_rn(v.w);
}

// ---------------- EMA phase 1: per-chunk local states + x split ----------------
__global__ void __launch_bounds__(256) ema_p1(
    const float* __restrict__ x, const float* __restrict__ dlt,
    const float* __restrict__ alp)
{
    int t = blockIdx.x*256 + threadIdx.x;
    int c = t >> 13, bd = t & 8191;
    int d = bd & 511;
    int i0f = d*2, i1f = d*2 + 1;
    int i0b = (512 + d)*2, i1b = i0b + 1;
    float q0f = 1.f - sigmf(dlt[i0f])*sigmf(alp[i0f]);
    float q1f = 1.f - sigmf(dlt[i1f])*sigmf(alp[i1f]);
    float q0b = 1.f - sigmf(dlt[i0b])*sigmf(alp[i0b]);
    float q1b = 1.f - sigmf(dlt[i1b])*sigmf(alp[i1b]);

    float f0 = 0.f, f1 = 0.f, a0 = 0.f, a1 = 0.f, pw0 = 1.f, pw1 = 1.f;
    size_t idx = (size_t)(c*CHL)*8192 + bd;
    #pragma unroll 4
    for (int j = 0; j < CHL; j++, idx += 8192) {
        float xv = x[idx];
        f0 = fmaf(q0f, f0, xv);
        f1 = fmaf(q1f, f1, xv);
        a0 = fmaf(pw0, xv, a0);
        a1 = fmaf(pw1, xv, a1);
        pw0 *= q0b; pw1 *= q1b;
        split2h(xv, xs_h[idx], xs_l[idx]);
    }
    int o = c*8192 + bd;
    e_st[0*NCH*8192 + o] = f0;
    e_st[1*NCH*8192 + o] = f1;
    e_st[2*NCH*8192 + o] = a0;
    e_st[3*NCH*8192 + o] = a1;
}

// ---------------- EMA phase 2: cross-chunk prefix/suffix combine ----------------
__global__ void __launch_bounds__(256) ema_p2(
    const float* __restrict__ dlt, const float* __restrict__ alp)
{
    int bd = blockIdx.x*256 + threadIdx.x;
    int d = bd & 511;
    int i0f = d*2, i1f = d*2 + 1;
    int i0b = (512 + d)*2, i1b = i0b + 1;
    float q0f = 1.f - sigmf(dlt[i0f])*sigmf(alp[i0f]);
    float q1f = 1.f - sigmf(dlt[i1f])*sigmf(alp[i1f]);
    float q0b = 1.f - sigmf(dlt[i0b])*sigmf(alp[i0b]);
    float q1b = 1.f - sigmf(dlt[i1b])*sigmf(alp[i1b]);
    float q0f8 = q0f, q1f8 = q1f, q0b8 = q0b, q1b8 = q1b;
    #pragma unroll
    for (int i = 0; i < 7; i++) { q0f8 *= q0f8; q1f8 *= q1f8; q0b8 *= q0b8; q1b8 *= q1b8; }

    float P0 = 0.f, P1 = 0.f;
    #pragma unroll
    for (int c = 0; c < NCH; c++) {
        int o = c*8192 + bd;
        seed_st[0*NCH*8192 + o] = P0;
        seed_st[1*NCH*8192 + o] = P1;
        P0 = fmaf(q0f8, P0, e_st[0*NCH*8192 + o]);
        P1 = fmaf(q1f8, P1, e_st[1*NCH*8192 + o]);
    }
    float T0 = 0.f, T1 = 0.f;
    #pragma unroll
    for (int c = NCH-1; c >= 0; c--) {
        int o = c*8192 + bd;
        seed_st[2*NCH*8192 + o] = T0;
        seed_st[3*NCH*8192 + o] = T1;
        T0 = fmaf(q0b8, T0, e_st[2*NCH*8192 + o]);
        T1 = fmaf(q1b8, T1, e_st[3*NCH*8192 + o]);
    }
}

// ---------------- EMA phase 3: seeded scans + silu + split ----------------
__global__ void __launch_bounds__(128) ema_p3(
    const float* __restrict__ x, const float* __restrict__ dlt,
    const float* __restrict__ alp, const float* __restrict__ bet,
    const float* __restrict__ gam, const float* __restrict__ omg)
{
    extern __shared__ float ybuf[];            // [CHL][128]
    int t = blockIdx.x*128 + threadIdx.x;
    int tid = threadIdx.x;
    int c = t >> 13, bd = t & 8191;
    int d = bd & 511;
    const float invs = 0.7071067811865476f;

    int i0f = d*2, i1f = d*2 + 1;
    int i0b = (512 + d)*2, i1b = i0b + 1;
    float p0f = sigmf(dlt[i0f]), p1f = sigmf(dlt[i1f]);
    float p0b = sigmf(dlt[i0b]), p1b = sigmf(dlt[i1b]);
    float q0f = 1.f - p0f*sigmf(alp[i0f]);
    float q1f = 1.f - p1f*sigmf(alp[i1f]);
    float q0b = 1.f - p0b*sigmf(alp[i0b]);
    float q1b = 1.f - p1b*sigmf(alp[i1b]);
    float w0f = p0f*bet[i0f]*gam[i0f]*invs;
    float w1f = p1f*bet[i1f]*gam[i1f]*invs;
    float w0b = p0b*bet[i0b]*gam[i0b]*invs;
    float w1b = p1b*bet[i1b]*gam[i1b]*invs;
    float ow = omg[d];

    int o = c*8192 + bd;
    size_t base = (size_t)(c*CHL)*8192 + bd;

    {
        float g0 = seed_st[2*NCH*8192 + o];
        float g1 = seed_st[3*NCH*8192 + o];
        size_t idx = base + (size_t)(CHL-1)*8192;
        #pragma unroll 4
        for (int j = CHL-1; j >= 0; j--, idx -= 8192) {
            float xv = x[idx];
            g0 = fmaf(q0b, g0, xv);
            g1 = fmaf(q1b, g1, xv);
            ybuf[j*128 + tid] = fmaf(w0b, g0, w1b*g1);
        }
    }
    {
        float f0 = seed_st[0*NCH*8192 + o];
        float f1 = seed_st[1*NCH*8192 + o];
        size_t idx = base;
        #pragma unroll 4
        for (int j = 0; j < CHL; j++, idx += 8192) {
            float xv = x[idx];
            f0 = fmaf(q0f, f0, xv);
            f1 = fmaf(q1f, f1, xv);
            float y = ybuf[j*128 + tid] + fmaf(w0f, f0, fmaf(w1f, f1, xv*ow));
            split2h(siluf(y), mxs_h[idx], mxs_l[idx]);
        }
    }
}

// ---------------- pipelined fp16 2-pass tensor-core GEMM ----------------
// A split (hi+lo fp16) [m][k]; B single fp16 plane [k][n]; 3-stage ring; 2 CTA/SM.
// MODE 0: vs_h  = fp16(silu(xs @ Wv + bv))         N=1024 K=512
// MODE 1: g_base= act(mxs @ Wmx + bmx)             N=2176 K=512
// MODE 2: g_o   = gate(silu(hr @ Wh + bh + hx))    N=512  K=1024
// MODE 3: hr    = split((attn @ v) * r)  (256 bat) N=1024 K=128
template<int MODE>
__global__ void __launch_bounds__(256, 2) mma_gemm(
    const float* __restrict__ Xres, const float* __restrict__ bias)
{
    constexpr int K   = (MODE==2) ? 1024 : (MODE==3) ? 128 : 512;
    constexpr int ldA = (MODE==2) ? 1024 : (MODE==3) ? 128 : 512;
    constexpr int ldB = (MODE==0) ? 1024 : (MODE==1) ? 2176 : (MODE==2) ? 512 : 16384;
    constexpr int NK  = K/32;
    constexpr int APS = 128*80;               // 10240 per A plane
    constexpr int BOFF = 2*APS;               // 20480
    constexpr int STAGE = BOFF + 8192;        // 28672

    extern __shared__ __align__(128) char smem_raw[];
    const uint32_t sb = (uint32_t)__cvta_generic_to_shared(smem_raw);

    const int t = threadIdx.x;
    const int warp = t >> 5, lane = t & 31;
    const int wm = warp & 1, wn = warp >> 1;        // 2m x 4n
    const int group = lane >> 2, tid4 = lane & 3;
    const int mat = lane >> 3, rim = lane & 7;
    const int rOff = ((mat & 1) << 3) + rim;
    const int cOff = mat >> 1;

    const int bn = blockIdx.x * 128;
    const int bm = (MODE==3) ? 0 : blockIdx.y * 128;

    int bb = 0, cc = 0, batch = 0;
    if (MODE == 3) { batch = blockIdx.z; bb = batch >> 4; cc = batch & 15; }

    const __half *pA0, *pA1, *pB0;
    if (MODE == 0) { pA0 = xs_h  + (size_t)bm*ldA; pA1 = xs_l  + (size_t)bm*ldA;
                     pB0 = wv_h  + bn; }
    else if (MODE == 1) { pA0 = mxs_h + (size_t)bm*ldA; pA1 = mxs_l + (size_t)bm*ldA;
                          pB0 = wmx_h + bn; }
    else if (MODE == 2) { pA0 = hr_h  + (size_t)bm*ldA; pA1 = hr_l  + (size_t)bm*ldA;
                          pB0 = wh_h  + bn; }
    else { pA0 = at_h + (size_t)batch*16384; pA1 = at_l + (size_t)batch*16384;
           pB0 = vs_h + (size_t)(cc*2048 + bb)*H_ + bn; }

    // cp.async descriptors: A = 4/thread, B = 2/thread
    const __half* gA[4]; uint32_t sA[4];
    #pragma unroll
    for (int e = 0; e < 4; e++) {
        int idx = e*256 + t;                  // 0..1023
        int plane = idx >> 9, w = idx & 511;
        int r = w >> 2, c = w & 3;
        gA[e] = (plane ? pA1 : pA0) + (size_t)r*ldA + c*8;
        sA[e] = sb + plane*APS + r*80 + (c << 4);
    }
    const __half* gB[2]; uint32_t sB[2];
    #pragma unroll
    for (int e = 0; e < 2; e++) {
        int idx = e*256 + t;                  // 0..511
        int r = idx >> 4, c = idx & 15;
        gB[e] = pB0 + (size_t)r*ldB + c*8;
        sB[e] = sb + BOFF + r*256 + (((uint32_t)(c ^ (r & 7))) << 4);
    }

    auto load_chunk = [&](int ck) {
        uint32_t so = (uint32_t)(ck % 3) * STAGE;
        int ka = ck * 32;
        #pragma unroll
        for (int e = 0; e < 4; e++) CPA16(sA[e] + so, gA[e] + ka);
        #pragma unroll
        for (int e = 0; e < 2; e++) CPA16(sB[e] + so, gB[e] + (size_t)ka*ldB);
        asm volatile("cp.async.commit_group;");
    };

    float acc[4][4][4];
    #pragma unroll
    for (int a = 0; a < 4; a++)
        #pragma unroll
        for (int b2 = 0; b2 < 4; b2++)
            #pragma unroll
            for (int e = 0; e < 4; e++) acc[a][b2][e] = 0.f;

    load_chunk(0);
    load_chunk(1);

    for (int it = 0; it < NK; it++) {
        if (it + 1 < NK) asm volatile("cp.async.wait_group 1;" ::: "memory");
        else             asm volatile("cp.async.wait_group 0;" ::: "memory");
        __syncthreads();
        if (it + 2 < NK) load_chunk(it + 2);

        const uint32_t stg = sb + (uint32_t)(it % 3)*STAGE;
        #pragma unroll
        for (int ks = 0; ks < 2; ks++) {
            uint32_t bh[2][4];
            const int kin = ks*16 + rOff;
            #pragma unroll
            for (int g = 0; g < 2; g++) {
                int cB = wn*4 + g*2 + cOff;
                uint32_t bd = stg + BOFF + kin*256 + (((uint32_t)(cB ^ (kin & 7))) << 4);
                LDSM4T(bh[g][0], bh[g][1], bh[g][2], bh[g][3], bd);
            }
            #pragma unroll
            for (int mp = 0; mp < 2; mp++) {
                uint32_t ah[2][4], al[2][4];
                #pragma unroll
                for (int ml = 0; ml < 2; ml++) {
                    int row = wm*64 + (mp*2 + ml)*16 + rOff;
                    uint32_t ad = stg + row*80 + ((uint32_t)(ks*2 + cOff) << 4);
                    LDSM4(ah[ml][0], ah[ml][1], ah[ml][2], ah[ml][3], ad);
                    LDSM4(al[ml][0], al[ml][1], al[ml][2], al[ml][3], ad + APS);
                }
                #pragma unroll
                for (int g = 0; g < 2; g++) {
                    #pragma unroll
                    for (int ml = 0; ml < 2; ml++) {
                        int mt = mp*2 + ml;
                        MMA16816(acc[mt][g*2],   ah[ml], bh[g][0], bh[g][1]);
                        MMA16816(acc[mt][g*2],   al[ml], bh[g][0], bh[g][1]);
                        MMA16816(acc[mt][g*2+1], ah[ml], bh[g][2], bh[g][3]);
                        MMA16816(acc[mt][g*2+1], al[ml], bh[g][2], bh[g][3]);
                    }
                }
            }
        }
        __syncthreads();
    }

    // ---- epilogue ----
    #pragma unroll
    for (int mt = 0; mt < 4; mt++) {
        #pragma unroll
        for (int nt = 0; nt < 4; nt++) {
            #pragma unroll
            for (int half = 0; half < 2; half++) {
                int m = bm + wm*64 + mt*16 + group + half*8;
                #pragma unroll
                for (int e = 0; e < 2; e++) {
                    int n = bn + wn*32 + nt*8 + tid4*2 + e;
                    float v = acc[mt][nt][half*2 + e];
                    if (MODE == 0) {
                        float s = siluf(v + bias[n]);
                        vs_h[(size_t)m*H_ + n] = __float2half_rn(s);
                    } else if (MODE == 1) {
                        v += bias[n];
                        if (n < 512)       v = sigmf(v);
                        else if (n < 1664) v = siluf(v);
                        g_base[(size_t)m*NBASE + n] = v;
                    } else if (MODE == 2) {
                        float hx = g_base[(size_t)m*NBASE + 1664 + n];
                        float s  = siluf(v + bias[n] + hx);
                        float u  = g_base[(size_t)m*NBASE + n];
                        float xr = Xres[(size_t)m*D_ + n];
                        g_o[(size_t)m*D_ + n] = xr + u*(s - xr);
                    } else {
                        size_t row = (size_t)(cc*128 + m)*B_ + bb;
                        float rv = g_base[row*NBASE + 640 + n];
                        split2h(v*rv, hr_h[row*H_ + n], hr_l[row*H_ + n]);
                    }
                }
            }
        }
    }
}

// ---------------- QK + softmax ----------------
__global__ void __launch_bounds__(256) qk_kernel(
    const float* __restrict__ qkg, const float* __restrict__ qkb,
    const float* __restrict__ rp, float* __restrict__ attn_out)
{
    extern __shared__ float sm[];
    float* qT = sm;
    float* kT = sm + 16384;
    float* sT = sm + 32768;
    float* red = sm;

    const int b = blockIdx.x >> 4;
    const int c = blockIdx.x & 15;
    const int t = threadIdx.x;
    const float qscale = 0.08838834764831845f;

    for (int idx = t; idx < 16384; idx += 256) {
        int i = idx >> 7, z = idx & 127;
        int row = (c*128 + i)*B_ + b;
        float zv = g_base[(size_t)row*NBASE + 512 + z];
        qT[z*128 + i] = (zv*qkg[z]     + qkb[z]    ) * qscale;
        kT[z*128 + i] =  zv*qkg[128+z] + qkb[128+z];
    }
    __syncthreads();

    {
        const int tx = t & 15, ty = t >> 4;
        const int i0 = ty*8, j0 = tx*8;
        float acc[8][8];
        #pragma unroll
        for (int i = 0; i < 8; i++)
            #pragma unroll
            for (int j = 0; j < 8; j++) acc[i][j] = 0.f;

        #pragma unroll 4
        for (int z = 0; z < 128; z++) {
            float qa[8], ka[8];
            *(float4*)(qa)   = *(const float4*)&qT[z*128 + i0];
            *(float4*)(qa+4) = *(const float4*)&qT[z*128 + i0 + 4];
            *(float4*)(ka)   = *(const float4*)&kT[z*128 + j0];
            *(float4*)(ka+4) = *(const float4*)&kT[z*128 + j0 + 4];
            #pragma unroll
            for (int i = 0; i < 8; i++)
                #pragma unroll
                for (int j = 0; j < 8; j++)
                    acc[i][j] = fmaf(qa[i], ka[j], acc[i][j]);
        }
        #pragma unroll
        for (int r = 0; r < 8; r++)
            #pragma unroll
            for (int cc2 = 0; cc2 < 8; cc2++) {
                int i = i0 + r, j = j0 + cc2;
                sT[j*132 + i] = acc[r][cc2] + rp[1023 + j - i];
            }
    }
    __syncthreads();

    {
        const int i = t & 127, half = t >> 7;
        const int jb = half*64;
        float mx = -1e30f;
        for (int j = jb; j < jb + 64; j++) mx = fmaxf(mx, sT[j*132 + i]);
        red[half*128 + i] = mx;
        __syncthreads();
        float M = fmaxf(red[i], red[128 + i]);
        float s = 0.f;
        for (int j = jb; j < jb + 64; j++) {
            float e = expf(sT[j*132 + i] - M);
            sT[j*132 + i] = e;
            s += e;
        }
        red[256 + half*128 + i] = s;
        __syncthreads();
        if (half == 0) red[512 + i] = 1.f / (red[256 + i] + red[384 + i]);
        __syncthreads();
    }

    size_t base = (size_t)(b*NC_ + c)*16384;
    float* aout = attn_out + base;
    for (int idx = t; idx < 16384; idx += 256) {
        int i = idx >> 7, j = idx & 127;
        float p = sT[j*132 + i] * red[512 + i];
        aout[idx] = p;
        split2h(p, at_h[base + idx], at_l[base + idx]);
    }
}

// ---------------- final rmsnorm ----------------
__global__ void __launch_bounds__(256) norm_kernel(
    const float* __restrict__ ns, float* __restrict__ out)
{
    int row  = blockIdx.x*8 + (threadIdx.x >> 5);
    int lane = threadIdx.x & 31;
    const float* op = g_o + (size_t)row*512;
    float vals[16];
    float ss = 0.f;
    #pragma unroll
    for (int k = 0; k < 16; k++) {
        float v = op[lane + k*32];
        vals[k] = v;
        ss += v*v;
    }
    #pragma unroll
    for (int off = 16; off; off >>= 1) ss += __shfl_xor_sync(0xffffffffu, ss, off);
    float scale = ns[0] * rsqrtf(ss*(1.f/512.f) + 1e-6f);
    float* outp = out + (size_t)row*512;
    #pragma unroll
    for (int k = 0; k < 16; k++) outp[lane + k*32] = vals[k]*scale;
}

// ---------------- launch ----------------
extern "C" void kernel_launch(void* const* d_in, const int* in_sizes, int n_in,
                              void* d_out, int out_size)
{
    const float* x   = (const float*)d_in[0];
    const float* edl = (const float*)d_in[1];
    const float* eal = (const float*)d_in[2];
    const float* ebt = (const float*)d_in[3];
    const float* egm = (const float*)d_in[4];
    const float* eom = (const float*)d_in[5];
    const float* Wv  = (const float*)d_in[6];
    const float* bv  = (const float*)d_in[7];
    const float* Wmx = (const float*)d_in[8];
    const float* bmx = (const float*)d_in[9];
    const float* Wh  = (const float*)d_in[10];
    const float* bh  = (const float*)d_in[11];
    const float* qkg = (const float*)d_in[12];
    const float* qkb = (const float*)d_in[13];
    const float* rp  = (const float*)d_in[14];
    const float* ns  = (const float*)d_in[15];

    float* out      = (float*)d_out;
    float* attn_out = out + (size_t)L_*B_*D_;

    static __half *p_wvh=nullptr,*p_wmxh,*p_whh;
    if (!p_wvh) {
        cudaGetSymbolAddress((void**)&p_wvh,  wv_h);
        cudaGetSymbolAddress((void**)&p_wmxh, wmx_h);
        cudaGetSymbolAddress((void**)&p_whh,  wh_h);
        cudaFuncSetAttribute(qk_kernel,   cudaFuncAttributeMaxDynamicSharedMemorySize, 198656);
        cudaFuncSetAttribute(ema_p3,      cudaFuncAttributeMaxDynamicSharedMemorySize, 65536);
        cudaFuncSetAttribute(mma_gemm<0>, cudaFuncAttributeMaxDynamicSharedMemorySize, 86016);
        cudaFuncSetAttribute(mma_gemm<1>, cudaFuncAttributeMaxDynamicSharedMemorySize, 86016);
        cudaFuncSetAttribute(mma_gemm<2>, cudaFuncAttributeMaxDynamicSharedMemorySize, 86016);
        cudaFuncSetAttribute(mma_gemm<3>, cudaFuncAttributeMaxDynamicSharedMemorySize, 86016);
    }

    splitw_kernel<<<512,  256>>>(Wv,  p_wvh);
    splitw_kernel<<<1088, 256>>>(Wmx, p_wmxh);
    splitw_kernel<<<512,  256>>>(Wh,  p_whh);

    ema_p1<<<512, 256>>>(x, edl, eal);
    ema_p2<<<32, 256>>>(edl, eal);
    ema_p3<<<1024, 128, 65536>>>(x, edl, eal, ebt, egm, eom);

    { dim3 g(8, 256);  mma_gemm<0><<<g, 256, 86016>>>(x, bv); }
    { dim3 g(17, 256); mma_gemm<1><<<g, 256, 86016>>>(x, bmx); }

    qk_kernel<<<B_*NC_, 256, 198656>>>(qkg, qkb, rp, attn_out);

    { dim3 g(8, 1, 256); mma_gemm<3><<<g, 256, 86016>>>(x, bv); }
    { dim3 g(4, 256);    mma_gemm<2><<<g, 256, 86016>>>(x, bh); }

    norm_kernel<<<MROWS/8, 256>>>(ns, out);
}

// round 11
// speedup vs baseline: 3.7438x; 1.0882x over previous
#include <cuda_runtime.h>
#include <cuda_fp16.h>
#include <stdint.h>
#include <math.h>

#define L_ 2048
#define B_ 16
#define D_ 512
#define H_ 1024
#define NC_ 16
#define NBASE 2176            // Z + H + 2D
#define MROWS (L_*B_)         // 32768
#define NCH 16                // EMA chunks
#define CHL 128               // chunk length

// ---------------- fp32 scratch ----------------
__device__ float g_base[MROWS*NBASE];  // activated base: [u | z | r | hx]
__device__ float g_o   [MROWS*D_];     // pre-norm output
__device__ float e_st  [4*NCH*8192];   // per-chunk local states
__device__ float seed_st[4*NCH*8192];  // per-chunk seeds

// ---------------- fp16 planes ----------------
// A-split (hi+lo) only where precision-critical: mxs (mode1), hr (mode2).
// Single-plane: xs (mode0 A), at (mode3 A), vs/w* (all B operands).
__device__ __align__(16) __half xs_h [MROWS*D_];
__device__ __align__(16) __half mxs_h[MROWS*D_],  mxs_l[MROWS*D_];
__device__ __align__(16) __half hr_h [MROWS*H_],  hr_l [MROWS*H_];
__device__ __align__(16) __half at_h [B_*NC_*128*128];
__device__ __align__(16) __half vs_h [MROWS*H_];
__device__ __align__(16) __half wv_h [512*1024];
__device__ __align__(16) __half wmx_h[512*2176];
__device__ __align__(16) __half wh_h [1024*512];

__device__ __forceinline__ float sigmf(float x){ return 1.0f/(1.0f + expf(-x)); }
__device__ __forceinline__ float siluf(float x){ return x/(1.0f + expf(-x)); }
__device__ __forceinline__ void split2h(float v, __half& h, __half& l){
    h = __float2half_rn(v);
    l = __float2half_rn(v - __half2float(h));
}

#define MMA16816(d, a, b0, b1) \
  asm volatile("mma.sync.aligned.m16n8k16.row.col.f32.f16.f16.f32 " \
    "{%0,%1,%2,%3}, {%4,%5,%6,%7}, {%8,%9}, {%0,%1,%2,%3};" \
    : "+f"(d[0]), "+f"(d[1]), "+f"(d[2]), "+f"(d[3]) \
    : "r"(a[0]), "r"(a[1]), "r"(a[2]), "r"(a[3]), "r"(b0), "r"(b1))

#define LDSM4(r0,r1,r2,r3,a) \
  asm volatile("ldmatrix.sync.aligned.m8n8.x4.shared.b16 {%0,%1,%2,%3}, [%4];" \
    : "=r"(r0),"=r"(r1),"=r"(r2),"=r"(r3) : "r"(a))

#define LDSM4T(r0,r1,r2,r3,a) \
  asm volatile("ldmatrix.sync.aligned.m8n8.x4.trans.shared.b16 {%0,%1,%2,%3}, [%4];" \
    : "=r"(r0),"=r"(r1),"=r"(r2),"=r"(r3) : "r"(a))

#define CPA16(s,g) asm volatile("cp.async.cg.shared.global [%0], [%1], 16;" :: "r"(s), "l"(g))

// ---------------- weights: fp32 -> fp16 hi plane ----------------
__global__ void __launch_bounds__(256) splitw_kernel(
    const float* __restrict__ src, __half* __restrict__ oh)
{
    size_t i4 = (size_t)blockIdx.x*256 + threadIdx.x;
    float4 v = *(const float4*)&src[i4*4];
    size_t o = i4*4;
    oh[o+0] = __float2half_rn(v.x);
    oh[o+1] = __float2half_rn(v.y);
    oh[o+2] = __float2half_rn(v.z);
    oh[o+3] = __float2half_rn(v.w);
}

// ---------------- EMA phase 1: per-chunk local states + x->fp16 ----------------
__global__ void __launch_bounds__(256) ema_p1(
    const float* __restrict__ x, const float* __restrict__ dlt,
    const float* __restrict__ alp)
{
    int t = blockIdx.x*256 + threadIdx.x;
    int c = t >> 13, bd = t & 8191;
    int d = bd & 511;
    int i0f = d*2, i1f = d*2 + 1;
    int i0b = (512 + d)*2, i1b = i0b + 1;
    float q0f = 1.f - sigmf(dlt[i0f])*sigmf(alp[i0f]);
    float q1f = 1.f - sigmf(dlt[i1f])*sigmf(alp[i1f]);
    float q0b = 1.f - sigmf(dlt[i0b])*sigmf(alp[i0b]);
    float q1b = 1.f - sigmf(dlt[i1b])*sigmf(alp[i1b]);

    float f0 = 0.f, f1 = 0.f, a0 = 0.f, a1 = 0.f, pw0 = 1.f, pw1 = 1.f;
    size_t idx = (size_t)(c*CHL)*8192 + bd;
    #pragma unroll 4
    for (int j = 0; j < CHL; j++, idx += 8192) {
        float xv = x[idx];
        f0 = fmaf(q0f, f0, xv);
        f1 = fmaf(q1f, f1, xv);
        a0 = fmaf(pw0, xv, a0);
        a1 = fmaf(pw1, xv, a1);
        pw0 *= q0b; pw1 *= q1b;
        xs_h[idx] = __float2half_rn(xv);
    }
    int o = c*8192 + bd;
    e_st[0*NCH*8192 + o] = f0;
    e_st[1*NCH*8192 + o] = f1;
    e_st[2*NCH*8192 + o] = a0;
    e_st[3*NCH*8192 + o] = a1;
}

// ---------------- EMA phase 2: cross-chunk prefix/suffix combine ----------------
__global__ void __launch_bounds__(256) ema_p2(
    const float* __restrict__ dlt, const float* __restrict__ alp)
{
    int bd = blockIdx.x*256 + threadIdx.x;
    int d = bd & 511;
    int i0f = d*2, i1f = d*2 + 1;
    int i0b = (512 + d)*2, i1b = i0b + 1;
    float q0f = 1.f - sigmf(dlt[i0f])*sigmf(alp[i0f]);
    float q1f = 1.f - sigmf(dlt[i1f])*sigmf(alp[i1f]);
    float q0b = 1.f - sigmf(dlt[i0b])*sigmf(alp[i0b]);
    float q1b = 1.f - sigmf(dlt[i1b])*sigmf(alp[i1b]);
    float q0f8 = q0f, q1f8 = q1f, q0b8 = q0b, q1b8 = q1b;
    #pragma unroll
    for (int i = 0; i < 7; i++) { q0f8 *= q0f8; q1f8 *= q1f8; q0b8 *= q0b8; q1b8 *= q1b8; }

    float P0 = 0.f, P1 = 0.f;
    #pragma unroll
    for (int c = 0; c < NCH; c++) {
        int o = c*8192 + bd;
        seed_st[0*NCH*8192 + o] = P0;
        seed_st[1*NCH*8192 + o] = P1;
        P0 = fmaf(q0f8, P0, e_st[0*NCH*8192 + o]);
        P1 = fmaf(q1f8, P1, e_st[1*NCH*8192 + o]);
    }
    float T0 = 0.f, T1 = 0.f;
    #pragma unroll
    for (int c = NCH-1; c >= 0; c--) {
        int o = c*8192 + bd;
        seed_st[2*NCH*8192 + o] = T0;
        seed_st[3*NCH*8192 + o] = T1;
        T0 = fmaf(q0b8, T0, e_st[2*NCH*8192 + o]);
        T1 = fmaf(q1b8, T1, e_st[3*NCH*8192 + o]);
    }
}

// ---------------- EMA phase 3: seeded scans + silu + split ----------------
__global__ void __launch_bounds__(128) ema_p3(
    const float* __restrict__ x, const float* __restrict__ dlt,
    const float* __restrict__ alp, const float* __restrict__ bet,
    const float* __restrict__ gam, const float* __restrict__ omg)
{
    extern __shared__ float ybuf[];            // [CHL][128]
    int t = blockIdx.x*128 + threadIdx.x;
    int tid = threadIdx.x;
    int c = t >> 13, bd = t & 8191;
    int d = bd & 511;
    const float invs = 0.7071067811865476f;

    int i0f = d*2, i1f = d*2 + 1;
    int i0b = (512 + d)*2, i1b = i0b + 1;
    float p0f = sigmf(dlt[i0f]), p1f = sigmf(dlt[i1f]);
    float p0b = sigmf(dlt[i0b]), p1b = sigmf(dlt[i1b]);
    float q0f = 1.f - p0f*sigmf(alp[i0f]);
    float q1f = 1.f - p1f*sigmf(alp[i1f]);
    float q0b = 1.f - p0b*sigmf(alp[i0b]);
    float q1b = 1.f - p1b*sigmf(alp[i1b]);
    float w0f = p0f*bet[i0f]*gam[i0f]*invs;
    float w1f = p1f*bet[i1f]*gam[i1f]*invs;
    float w0b = p0b*bet[i0b]*gam[i0b]*invs;
    float w1b = p1b*bet[i1b]*gam[i1b]*invs;
    float ow = omg[d];

    int o = c*8192 + bd;
    size_t base = (size_t)(c*CHL)*8192 + bd;

    {
        float g0 = seed_st[2*NCH*8192 + o];
        float g1 = seed_st[3*NCH*8192 + o];
        size_t idx = base + (size_t)(CHL-1)*8192;
        #pragma unroll 4
        for (int j = CHL-1; j >= 0; j--, idx -= 8192) {
            float xv = x[idx];
            g0 = fmaf(q0b, g0, xv);
            g1 = fmaf(q1b, g1, xv);
            ybuf[j*128 + tid] = fmaf(w0b, g0, w1b*g1);
        }
    }
    {
        float f0 = seed_st[0*NCH*8192 + o];
        float f1 = seed_st[1*NCH*8192 + o];
        size_t idx = base;
        #pragma unroll 4
        for (int j = 0; j < CHL; j++, idx += 8192) {
            float xv = x[idx];
            f0 = fmaf(q0f, f0, xv);
            f1 = fmaf(q1f, f1, xv);
            float y = ybuf[j*128 + tid] + fmaf(w0f, f0, fmaf(w1f, f1, xv*ow));
            split2h(siluf(y), mxs_h[idx], mxs_l[idx]);
        }
    }
}

// ---------------- pipelined fp16 tensor-core GEMM ----------------
// A split 2-pass only for MODE 1/2; single-pass for MODE 0/3. B single plane.
// 3-stage ring, 2 CTAs/SM.
// MODE 0: vs_h  = fp16(silu(xs @ Wv + bv))         N=1024 K=512   1-pass
// MODE 1: g_base= act(mxs @ Wmx + bmx)             N=2176 K=512   2-pass
// MODE 2: g_o   = gate(silu(hr @ Wh + bh + hx))    N=512  K=1024  2-pass
// MODE 3: hr    = split((attn @ v) * r)  (256 bat) N=1024 K=128   1-pass
template<int MODE>
__global__ void __launch_bounds__(256, 2) mma_gemm(
    const float* __restrict__ Xres, const float* __restrict__ bias)
{
    constexpr bool AS = (MODE==1 || MODE==2);
    constexpr int K   = (MODE==2) ? 1024 : (MODE==3) ? 128 : 512;
    constexpr int ldA = (MODE==2) ? 1024 : (MODE==3) ? 128 : 512;
    constexpr int ldB = (MODE==0) ? 1024 : (MODE==1) ? 2176 : (MODE==2) ? 512 : 16384;
    constexpr int NK  = K/32;
    constexpr int APS = 128*80;               // 10240 per A plane
    constexpr int BOFF = (AS ? 2 : 1)*APS;
    constexpr int STAGE = BOFF + 8192;
    constexpr int NAE = AS ? 4 : 2;

    extern __shared__ __align__(128) char smem_raw[];
    const uint32_t sb = (uint32_t)__cvta_generic_to_shared(smem_raw);

    const int t = threadIdx.x;
    const int warp = t >> 5, lane = t & 31;
    const int wm = warp & 1, wn = warp >> 1;        // 2m x 4n
    const int group = lane >> 2, tid4 = lane & 3;
    const int mat = lane >> 3, rim = lane & 7;
    const int rOff = ((mat & 1) << 3) + rim;
    const int cOff = mat >> 1;

    const int bn = blockIdx.x * 128;
    const int bm = (MODE==3) ? 0 : blockIdx.y * 128;

    int bb = 0, cc = 0, batch = 0;
    if (MODE == 3) { batch = blockIdx.z; bb = batch >> 4; cc = batch & 15; }

    const __half *pA0, *pA1 = nullptr, *pB0;
    if (MODE == 0) { pA0 = xs_h  + (size_t)bm*ldA;
                     pB0 = wv_h  + bn; }
    else if (MODE == 1) { pA0 = mxs_h + (size_t)bm*ldA; pA1 = mxs_l + (size_t)bm*ldA;
                          pB0 = wmx_h + bn; }
    else if (MODE == 2) { pA0 = hr_h  + (size_t)bm*ldA; pA1 = hr_l  + (size_t)bm*ldA;
                          pB0 = wh_h  + bn; }
    else { pA0 = at_h + (size_t)batch*16384;
           pB0 = vs_h + (size_t)(cc*2048 + bb)*H_ + bn; }

    // cp.async descriptors
    const __half* gA[NAE]; uint32_t sA[NAE];
    #pragma unroll
    for (int e = 0; e < NAE; e++) {
        int idx = e*256 + t;
        int plane = idx >> 9, w = idx & 511;
        int r = w >> 2, c = w & 3;
        gA[e] = (plane ? pA1 : pA0) + (size_t)r*ldA + c*8;
        sA[e] = sb + plane*APS + r*80 + (c << 4);
    }
    const __half* gB[2]; uint32_t sB[2];
    #pragma unroll
    for (int e = 0; e < 2; e++) {
        int idx = e*256 + t;
        int r = idx >> 4, c = idx & 15;
        gB[e] = pB0 + (size_t)r*ldB + c*8;
        sB[e] = sb + BOFF + r*256 + (((uint32_t)(c ^ (r & 7))) << 4);
    }

    auto load_chunk = [&](int ck) {
        uint32_t so = (uint32_t)(ck % 3) * STAGE;
        int ka = ck * 32;
        #pragma unroll
        for (int e = 0; e < NAE; e++) CPA16(sA[e] + so, gA[e] + ka);
        #pragma unroll
        for (int e = 0; e < 2; e++) CPA16(sB[e] + so, gB[e] + (size_t)ka*ldB);
        asm volatile("cp.async.commit_group;");
    };

    float acc[4][4][4];
    #pragma unroll
    for (int a = 0; a < 4; a++)
        #pragma unroll
        for (int b2 = 0; b2 < 4; b2++)
            #pragma unroll
            for (int e = 0; e < 4; e++) acc[a][b2][e] = 0.f;

    load_chunk(0);
    load_chunk(1);

    for (int it = 0; it < NK; it++) {
        if (it + 1 < NK) asm volatile("cp.async.wait_group 1;" ::: "memory");
        else             asm volatile("cp.async.wait_group 0;" ::: "memory");
        __syncthreads();
        if (it + 2 < NK) load_chunk(it + 2);

        const uint32_t stg = sb + (uint32_t)(it % 3)*STAGE;
        #pragma unroll
        for (int ks = 0; ks < 2; ks++) {
            uint32_t bh[2][4];
            const int kin = ks*16 + rOff;
            #pragma unroll
            for (int g = 0; g < 2; g++) {
                int cB = wn*4 + g*2 + cOff;
                uint32_t bd = stg + BOFF + kin*256 + (((uint32_t)(cB ^ (kin & 7))) << 4);
                LDSM4T(bh[g][0], bh[g][1], bh[g][2], bh[g][3], bd);
            }
            #pragma unroll
            for (int mp = 0; mp < 2; mp++) {
                uint32_t ah[2][4], al[2][4];
                #pragma unroll
                for (int ml = 0; ml < 2; ml++) {
                    int row = wm*64 + (mp*2 + ml)*16 + rOff;
                    uint32_t ad = stg + row*80 + ((uint32_t)(ks*2 + cOff) << 4);
                    LDSM4(ah[ml][0], ah[ml][1], ah[ml][2], ah[ml][3], ad);
                    if (AS) LDSM4(al[ml][0], al[ml][1], al[ml][2], al[ml][3], ad + APS);
                }
                #pragma unroll
                for (int g = 0; g < 2; g++) {
                    #pragma unroll
                    for (int ml = 0; ml < 2; ml++) {
                        int mt = mp*2 + ml;
                        MMA16816(acc[mt][g*2],   ah[ml], bh[g][0], bh[g][1]);
                        MMA16816(acc[mt][g*2+1], ah[ml], bh[g][2], bh[g][3]);
                        if (AS) {
                            MMA16816(acc[mt][g*2],   al[ml], bh[g][0], bh[g][1]);
                            MMA16816(acc[mt][g*2+1], al[ml], bh[g][2], bh[g][3]);
                        }
                    }
                }
            }
        }
        __syncthreads();
    }

    // ---- epilogue ----
    #pragma unroll
    for (int mt = 0; mt < 4; mt++) {
        #pragma unroll
        for (int nt = 0; nt < 4; nt++) {
            #pragma unroll
            for (int half = 0; half < 2; half++) {
                int m = bm + wm*64 + mt*16 + group + half*8;
                #pragma unroll
                for (int e = 0; e < 2; e++) {
                    int n = bn + wn*32 + nt*8 + tid4*2 + e;
                    float v = acc[mt][nt][half*2 + e];
                    if (MODE == 0) {
                        float s = siluf(v + bias[n]);
                        vs_h[(size_t)m*H_ + n] = __float2half_rn(s);
                    } else if (MODE == 1) {
                        v += bias[n];
                        if (n < 512)       v = sigmf(v);
                        else if (n < 1664) v = siluf(v);
                        g_base[(size_t)m*NBASE + n] = v;
                    } else if (MODE == 2) {
                        float hx = g_base[(size_t)m*NBASE + 1664 + n];
                        float s  = siluf(v + bias[n] + hx);
                        float u  = g_base[(size_t)m*NBASE + n];
                        float xr = Xres[(size_t)m*D_ + n];
                        g_o[(size_t)m*D_ + n] = xr + u*(s - xr);
                    } else {
                        size_t row = (size_t)(cc*128 + m)*B_ + bb;
                        float rv = g_base[row*NBASE + 640 + n];
                        split2h(v*rv, hr_h[row*H_ + n], hr_l[row*H_ + n]);
                    }
                }
            }
        }
    }
}

// ---------------- QK + softmax ----------------
__global__ void __launch_bounds__(256) qk_kernel(
    const float* __restrict__ qkg, const float* __restrict__ qkb,
    const float* __restrict__ rp, float* __restrict__ attn_out)
{
    extern __shared__ float sm[];
    float* qT = sm;
    float* kT = sm + 16384;
    float* sT = sm + 32768;
    float* red = sm;

    const int b = blockIdx.x >> 4;
    const int c = blockIdx.x & 15;
    const int t = threadIdx.x;
    const float qscale = 0.08838834764831845f;

    for (int idx = t; idx < 16384; idx += 256) {
        int i = idx >> 7, z = idx & 127;
        int row = (c*128 + i)*B_ + b;
        float zv = g_base[(size_t)row*NBASE + 512 + z];
        qT[z*128 + i] = (zv*qkg[z]     + qkb[z]    ) * qscale;
        kT[z*128 + i] =  zv*qkg[128+z] + qkb[128+z];
    }
    __syncthreads();

    {
        const int tx = t & 15, ty = t >> 4;
        const int i0 = ty*8, j0 = tx*8;
        float acc[8][8];
        #pragma unroll
        for (int i = 0; i < 8; i++)
            #pragma unroll
            for (int j = 0; j < 8; j++) acc[i][j] = 0.f;

        #pragma unroll 4
        for (int z = 0; z < 128; z++) {
            float qa[8], ka[8];
            *(float4*)(qa)   = *(const float4*)&qT[z*128 + i0];
            *(float4*)(qa+4) = *(const float4*)&qT[z*128 + i0 + 4];
            *(float4*)(ka)   = *(const float4*)&kT[z*128 + j0];
            *(float4*)(ka+4) = *(const float4*)&kT[z*128 + j0 + 4];
            #pragma unroll
            for (int i = 0; i < 8; i++)
                #pragma unroll
                for (int j = 0; j < 8; j++)
                    acc[i][j] = fmaf(qa[i], ka[j], acc[i][j]);
        }
        #pragma unroll
        for (int r = 0; r < 8; r++)
            #pragma unroll
            for (int cc2 = 0; cc2 < 8; cc2++) {
                int i = i0 + r, j = j0 + cc2;
                sT[j*132 + i] = acc[r][cc2] + rp[1023 + j - i];
            }
    }
    __syncthreads();

    {
        const int i = t & 127, half = t >> 7;
        const int jb = half*64;
        float mx = -1e30f;
        for (int j = jb; j < jb + 64; j++) mx = fmaxf(mx, sT[j*132 + i]);
        red[half*128 + i] = mx;
        __syncthreads();
        float M = fmaxf(red[i], red[128 + i]);
        float s = 0.f;
        for (int j = jb; j < jb + 64; j++) {
            float e = expf(sT[j*132 + i] - M);
            sT[j*132 + i] = e;
            s += e;
        }
        red[256 + half*128 + i] = s;
        __syncthreads();
        if (half == 0) red[512 + i] = 1.f / (red[256 + i] + red[384 + i]);
        __syncthreads();
    }

    size_t base = (size_t)(b*NC_ + c)*16384;
    float* aout = attn_out + base;
    for (int idx = t; idx < 16384; idx += 256) {
        int i = idx >> 7, j = idx & 127;
        float p = sT[j*132 + i] * red[512 + i];
        aout[idx] = p;
        at_h[base + idx] = __float2half_rn(p);
    }
}

// ---------------- final rmsnorm ----------------
__global__ void __launch_bounds__(256) norm_kernel(
    const float* __restrict__ ns, float* __restrict__ out)
{
    int row  = blockIdx.x*8 + (threadIdx.x >> 5);
    int lane = threadIdx.x & 31;
    const float* op = g_o + (size_t)row*512;
    float vals[16];
    float ss = 0.f;
    #pragma unroll
    for (int k = 0; k < 16; k++) {
        float v = op[lane + k*32];
        vals[k] = v;
        ss += v*v;
    }
    #pragma unroll
    for (int off = 16; off; off >>= 1) ss += __shfl_xor_sync(0xffffffffu, ss, off);
    float scale = ns[0] * rsqrtf(ss*(1.f/512.f) + 1e-6f);
    float* outp = out + (size_t)row*512;
    #pragma unroll
    for (int k = 0; k < 16; k++) outp[lane + k*32] = vals[k]*scale;
}

// ---------------- launch ----------------
extern "C" void kernel_launch(void* const* d_in, const int* in_sizes, int n_in,
                              void* d_out, int out_size)
{
    const float* x   = (const float*)d_in[0];
    const float* edl = (const float*)d_in[1];
    const float* eal = (const float*)d_in[2];
    const float* ebt = (const float*)d_in[3];
    const float* egm = (const float*)d_in[4];
    const float* eom = (const float*)d_in[5];
    const float* Wv  = (const float*)d_in[6];
    const float* bv  = (const float*)d_in[7];
    const float* Wmx = (const float*)d_in[8];
    const float* bmx = (const float*)d_in[9];
    const float* Wh  = (const float*)d_in[10];
    const float* bh  = (const float*)d_in[11];
    const float* qkg = (const float*)d_in[12];
    const float* qkb = (const float*)d_in[13];
    const float* rp  = (const float*)d_in[14];
    const float* ns  = (const float*)d_in[15];

    float* out      = (float*)d_out;
    float* attn_out = out + (size_t)L_*B_*D_;

    static __half *p_wvh=nullptr,*p_wmxh,*p_whh;
    if (!p_wvh) {
        cudaGetSymbolAddress((void**)&p_wvh,  wv_h);
        cudaGetSymbolAddress((void**)&p_wmxh, wmx_h);
        cudaGetSymbolAddress((void**)&p_whh,  wh_h);
        cudaFuncSetAttribute(qk_kernel,   cudaFuncAttributeMaxDynamicSharedMemorySize, 198656);
        cudaFuncSetAttribute(ema_p3,      cudaFuncAttributeMaxDynamicSharedMemorySize, 65536);
        cudaFuncSetAttribute(mma_gemm<0>, cudaFuncAttributeMaxDynamicSharedMemorySize, 55296);
        cudaFuncSetAttribute(mma_gemm<1>, cudaFuncAttributeMaxDynamicSharedMemorySize, 86016);
        cudaFuncSetAttribute(mma_gemm<2>, cudaFuncAttributeMaxDynamicSharedMemorySize, 86016);
        cudaFuncSetAttribute(mma_gemm<3>, cudaFuncAttributeMaxDynamicSharedMemorySize, 55296);
    }

    splitw_kernel<<<512,  256>>>(Wv,  p_wvh);
    splitw_kernel<<<1088, 256>>>(Wmx, p_wmxh);
    splitw_kernel<<<512,  256>>>(Wh,  p_whh);

    ema_p1<<<512, 256>>>(x, edl, eal);
    ema_p2<<<32, 256>>>(edl, eal);
    ema_p3<<<1024, 128, 65536>>>(x, edl, eal, ebt, egm, eom);

    { dim3 g(8, 256);  mma_gemm<0><<<g, 256, 55296>>>(x, bv); }
    { dim3 g(17, 256); mma_gemm<1><<<g, 256, 86016>>>(x, bmx); }

    qk_kernel<<<B_*NC_, 256, 198656>>>(qkg, qkb, rp, attn_out);

    { dim3 g(8, 1, 256); mma_gemm<3><<<g, 256, 55296>>>(x, bv); }
    { dim3 g(4, 256);    mma_gemm<2><<<g, 256, 86016>>>(x, bh); }

    norm_kernel<<<MROWS/8, 256>>>(ns, out);
}

// round 12
// speedup vs baseline: 4.6011x; 1.2290x over previous
#include <cuda_runtime.h>
#include <cuda_fp16.h>
#include <stdint.h>
#include <math.h>

#define L_ 2048
#define B_ 16
#define D_ 512
#define H_ 1024
#define NC_ 16
#define NBASE 2176            // Z + H + 2D
#define MROWS (L_*B_)         // 32768
#define NCH 16                // EMA chunks
#define CHL 128               // chunk length

// ---------------- fp32 scratch ----------------
__device__ float g_base[MROWS*NBASE];  // activated base: [u | z | r | hx]
__device__ float g_o   [MROWS*D_];     // pre-norm output
__device__ float e_st  [4*NCH*8192];   // per-chunk local states
__device__ float seed_st[4*NCH*8192];  // per-chunk seeds

// ---------------- fp16 planes ----------------
// A-split (hi+lo) kept ONLY for mode-1 u/z columns (mxs). Everything else 1-plane.
__device__ __align__(16) __half xs_h [MROWS*D_];
__device__ __align__(16) __half mxs_h[MROWS*D_],  mxs_l[MROWS*D_];
__device__ __align__(16) __half hr_h [MROWS*H_];
__device__ __align__(16) __half at_h [B_*NC_*128*128];
__device__ __align__(16) __half vs_h [MROWS*H_];
__device__ __align__(16) __half wv_h [512*1024];
__device__ __align__(16) __half wmx_h[512*2176];
__device__ __align__(16) __half wh_h [1024*512];

__device__ __forceinline__ float sigmf(float x){ return 1.0f/(1.0f + expf(-x)); }
__device__ __forceinline__ float siluf(float x){ return x/(1.0f + expf(-x)); }
__device__ __forceinline__ void split2h(float v, __half& h, __half& l){
    h = __float2half_rn(v);
    l = __float2half_rn(v - __half2float(h));
}

#define MMA16816(d, a, b0, b1) \
  asm volatile("mma.sync.aligned.m16n8k16.row.col.f32.f16.f16.f32 " \
    "{%0,%1,%2,%3}, {%4,%5,%6,%7}, {%8,%9}, {%0,%1,%2,%3};" \
    : "+f"(d[0]), "+f"(d[1]), "+f"(d[2]), "+f"(d[3]) \
    : "r"(a[0]), "r"(a[1]), "r"(a[2]), "r"(a[3]), "r"(b0), "r"(b1))

#define LDSM4(r0,r1,r2,r3,a) \
  asm volatile("ldmatrix.sync.aligned.m8n8.x4.shared.b16 {%0,%1,%2,%3}, [%4];" \
    : "=r"(r0),"=r"(r1),"=r"(r2),"=r"(r3) : "r"(a))

#define LDSM4T(r0,r1,r2,r3,a) \
  asm volatile("ldmatrix.sync.aligned.m8n8.x4.trans.shared.b16 {%0,%1,%2,%3}, [%4];" \
    : "=r"(r0),"=r"(r1),"=r"(r2),"=r"(r3) : "r"(a))

#define CPA16(s,g) asm volatile("cp.async.cg.shared.global [%0], [%1], 16;" :: "r"(s), "l"(g))

// ---------------- weights: fp32 -> fp16 hi plane ----------------
__global__ void __launch_bounds__(256) splitw_kernel(
    const float* __restrict__ src, __half* __restrict__ oh)
{
    size_t i4 = (size_t)blockIdx.x*256 + threadIdx.x;
    float4 v = *(const float4*)&src[i4*4];
    size_t o = i4*4;
    oh[o+0] = __float2half_rn(v.x);
    oh[o+1] = __float2half_rn(v.y);
    oh[o+2] = __float2half_rn(v.z);
    oh[o+3] = __float2half_rn(v.w);
}

// ---------------- EMA phase 1: per-chunk local states + x->fp16 ----------------
__global__ void __launch_bounds__(256) ema_p1(
    const float* __restrict__ x, const float* __restrict__ dlt,
    const float* __restrict__ alp)
{
    int t = blockIdx.x*256 + threadIdx.x;
    int c = t >> 13, bd = t & 8191;
    int d = bd & 511;
    int i0f = d*2, i1f = d*2 + 1;
    int i0b = (512 + d)*2, i1b = i0b + 1;
    float q0f = 1.f - sigmf(dlt[i0f])*sigmf(alp[i0f]);
    float q1f = 1.f - sigmf(dlt[i1f])*sigmf(alp[i1f]);
    float q0b = 1.f - sigmf(dlt[i0b])*sigmf(alp[i0b]);
    float q1b = 1.f - sigmf(dlt[i1b])*sigmf(alp[i1b]);

    float f0 = 0.f, f1 = 0.f, a0 = 0.f, a1 = 0.f, pw0 = 1.f, pw1 = 1.f;
    size_t idx = (size_t)(c*CHL)*8192 + bd;
    #pragma unroll 4
    for (int j = 0; j < CHL; j++, idx += 8192) {
        float xv = x[idx];
        f0 = fmaf(q0f, f0, xv);
        f1 = fmaf(q1f, f1, xv);
        a0 = fmaf(pw0, xv, a0);
        a1 = fmaf(pw1, xv, a1);
        pw0 *= q0b; pw1 *= q1b;
        xs_h[idx] = __float2half_rn(xv);
    }
    int o = c*8192 + bd;
    e_st[0*NCH*8192 + o] = f0;
    e_st[1*NCH*8192 + o] = f1;
    e_st[2*NCH*8192 + o] = a0;
    e_st[3*NCH*8192 + o] = a1;
}

// ---------------- EMA phase 2: cross-chunk prefix/suffix combine ----------------
__global__ void __launch_bounds__(256) ema_p2(
    const float* __restrict__ dlt, const float* __restrict__ alp)
{
    int bd = blockIdx.x*256 + threadIdx.x;
    int d = bd & 511;
    int i0f = d*2, i1f = d*2 + 1;
    int i0b = (512 + d)*2, i1b = i0b + 1;
    float q0f = 1.f - sigmf(dlt[i0f])*sigmf(alp[i0f]);
    float q1f = 1.f - sigmf(dlt[i1f])*sigmf(alp[i1f]);
    float q0b = 1.f - sigmf(dlt[i0b])*sigmf(alp[i0b]);
    float q1b = 1.f - sigmf(dlt[i1b])*sigmf(alp[i1b]);
    float q0f8 = q0f, q1f8 = q1f, q0b8 = q0b, q1b8 = q1b;
    #pragma unroll
    for (int i = 0; i < 7; i++) { q0f8 *= q0f8; q1f8 *= q1f8; q0b8 *= q0b8; q1b8 *= q1b8; }

    float P0 = 0.f, P1 = 0.f;
    #pragma unroll
    for (int c = 0; c < NCH; c++) {
        int o = c*8192 + bd;
        seed_st[0*NCH*8192 + o] = P0;
        seed_st[1*NCH*8192 + o] = P1;
        P0 = fmaf(q0f8, P0, e_st[0*NCH*8192 + o]);
        P1 = fmaf(q1f8, P1, e_st[1*NCH*8192 + o]);
    }
    float T0 = 0.f, T1 = 0.f;
    #pragma unroll
    for (int c = NCH-1; c >= 0; c--) {
        int o = c*8192 + bd;
        seed_st[2*NCH*8192 + o] = T0;
        seed_st[3*NCH*8192 + o] = T1;
        T0 = fmaf(q0b8, T0, e_st[2*NCH*8192 + o]);
        T1 = fmaf(q1b8, T1, e_st[3*NCH*8192 + o]);
    }
}

// ---------------- EMA phase 3: seeded scans + silu + split ----------------
__global__ void __launch_bounds__(128) ema_p3(
    const float* __restrict__ x, const float* __restrict__ dlt,
    const float* __restrict__ alp, const float* __restrict__ bet,
    const float* __restrict__ gam, const float* __restrict__ omg)
{
    extern __shared__ float ybuf[];            // [CHL][128]
    int t = blockIdx.x*128 + threadIdx.x;
    int tid = threadIdx.x;
    int c = t >> 13, bd = t & 8191;
    int d = bd & 511;
    const float invs = 0.7071067811865476f;

    int i0f = d*2, i1f = d*2 + 1;
    int i0b = (512 + d)*2, i1b = i0b + 1;
    float p0f = sigmf(dlt[i0f]), p1f = sigmf(dlt[i1f]);
    float p0b = sigmf(dlt[i0b]), p1b = sigmf(dlt[i1b]);
    float q0f = 1.f - p0f*sigmf(alp[i0f]);
    float q1f = 1.f - p1f*sigmf(alp[i1f]);
    float q0b = 1.f - p0b*sigmf(alp[i0b]);
    float q1b = 1.f - p1b*sigmf(alp[i1b]);
    float w0f = p0f*bet[i0f]*gam[i0f]*invs;
    float w1f = p1f*bet[i1f]*gam[i1f]*invs;
    float w0b = p0b*bet[i0b]*gam[i0b]*invs;
    float w1b = p1b*bet[i1b]*gam[i1b]*invs;
    float ow = omg[d];

    int o = c*8192 + bd;
    size_t base = (size_t)(c*CHL)*8192 + bd;

    {
        float g0 = seed_st[2*NCH*8192 + o];
        float g1 = seed_st[3*NCH*8192 + o];
        size_t idx = base + (size_t)(CHL-1)*8192;
        #pragma unroll 4
        for (int j = CHL-1; j >= 0; j--, idx -= 8192) {
            float xv = x[idx];
            g0 = fmaf(q0b, g0, xv);
            g1 = fmaf(q1b, g1, xv);
            ybuf[j*128 + tid] = fmaf(w0b, g0, w1b*g1);
        }
    }
    {
        float f0 = seed_st[0*NCH*8192 + o];
        float f1 = seed_st[1*NCH*8192 + o];
        size_t idx = base;
        #pragma unroll 4
        for (int j = 0; j < CHL; j++, idx += 8192) {
            float xv = x[idx];
            f0 = fmaf(q0f, f0, xv);
            f1 = fmaf(q1f, f1, xv);
            float y = ybuf[j*128 + tid] + fmaf(w0f, f0, fmaf(w1f, f1, xv*ow));
            split2h(siluf(y), mxs_h[idx], mxs_l[idx]);
        }
    }
}

// ---------------- pipelined fp16 tensor-core GEMM ----------------
// AS = 2-pass A-split (only mode-1 u/z columns); NOFF = n-offset of this launch.
// 3-stage ring, 2 CTAs/SM.
// MODE 0: vs_h  = fp16(silu(xs @ Wv + bv))         N=1024 K=512   1-pass
// MODE 1: g_base= act(mxs @ Wmx + bmx)             N=2176 K=512   2-pass n<640, 1-pass n>=640
// MODE 2: g_o   = gate(silu(hr @ Wh + bh + hx))    N=512  K=1024  1-pass
// MODE 3: hr_h  = fp16((attn @ v) * r)  (256 bat)  N=1024 K=128   1-pass
template<int MODE, bool AS, int NOFF>
__global__ void __launch_bounds__(256, 2) mma_gemm(
    const float* __restrict__ Xres, const float* __restrict__ bias)
{
    constexpr int K   = (MODE==2) ? 1024 : (MODE==3) ? 128 : 512;
    constexpr int ldA = (MODE==2) ? 1024 : (MODE==3) ? 128 : 512;
    constexpr int ldB = (MODE==0) ? 1024 : (MODE==1) ? 2176 : (MODE==2) ? 512 : 16384;
    constexpr int NK  = K/32;
    constexpr int APS = 128*80;               // 10240 per A plane
    constexpr int BOFF = (AS ? 2 : 1)*APS;
    constexpr int STAGE = BOFF + 8192;
    constexpr int NAE = AS ? 4 : 2;

    extern __shared__ __align__(128) char smem_raw[];
    const uint32_t sb = (uint32_t)__cvta_generic_to_shared(smem_raw);

    const int t = threadIdx.x;
    const int warp = t >> 5, lane = t & 31;
    const int wm = warp & 1, wn = warp >> 1;        // 2m x 4n
    const int group = lane >> 2, tid4 = lane & 3;
    const int mat = lane >> 3, rim = lane & 7;
    const int rOff = ((mat & 1) << 3) + rim;
    const int cOff = mat >> 1;

    const int bn = NOFF + blockIdx.x * 128;
    const int bm = (MODE==3) ? 0 : blockIdx.y * 128;

    int bb = 0, cc = 0, batch = 0;
    if (MODE == 3) { batch = blockIdx.z; bb = batch >> 4; cc = batch & 15; }

    const __half *pA0, *pA1 = nullptr, *pB0;
    if (MODE == 0) { pA0 = xs_h  + (size_t)bm*ldA;
                     pB0 = wv_h  + bn; }
    else if (MODE == 1) { pA0 = mxs_h + (size_t)bm*ldA; pA1 = mxs_l + (size_t)bm*ldA;
                          pB0 = wmx_h + bn; }
    else if (MODE == 2) { pA0 = hr_h  + (size_t)bm*ldA;
                          pB0 = wh_h  + bn; }
    else { pA0 = at_h + (size_t)batch*16384;
           pB0 = vs_h + (size_t)(cc*2048 + bb)*H_ + bn; }

    // cp.async descriptors
    const __half* gA[NAE]; uint32_t sA[NAE];
    #pragma unroll
    for (int e = 0; e < NAE; e++) {
        int idx = e*256 + t;
        int plane = idx >> 9, w = idx & 511;
        int r = w >> 2, c = w & 3;
        gA[e] = (plane ? pA1 : pA0) + (size_t)r*ldA + c*8;
        sA[e] = sb + plane*APS + r*80 + (c << 4);
    }
    const __half* gB[2]; uint32_t sB[2];
    #pragma unroll
    for (int e = 0; e < 2; e++) {
        int idx = e*256 + t;
        int r = idx >> 4, c = idx & 15;
        gB[e] = pB0 + (size_t)r*ldB + c*8;
        sB[e] = sb + BOFF + r*256 + (((uint32_t)(c ^ (r & 7))) << 4);
    }

    auto load_chunk = [&](int ck) {
        uint32_t so = (uint32_t)(ck % 3) * STAGE;
        int ka = ck * 32;
        #pragma unroll
        for (int e = 0; e < NAE; e++) CPA16(sA[e] + so, gA[e] + ka);
        #pragma unroll
        for (int e = 0; e < 2; e++) CPA16(sB[e] + so, gB[e] + (size_t)ka*ldB);
        asm volatile("cp.async.commit_group;");
    };

    float acc[4][4][4];
    #pragma unroll
    for (int a = 0; a < 4; a++)
        #pragma unroll
        for (int b2 = 0; b2 < 4; b2++)
            #pragma unroll
            for (int e = 0; e < 4; e++) acc[a][b2][e] = 0.f;

    load_chunk(0);
    load_chunk(1);

    for (int it = 0; it < NK; it++) {
        if (it + 1 < NK) asm volatile("cp.async.wait_group 1;" ::: "memory");
        else             asm volatile("cp.async.wait_group 0;" ::: "memory");
        __syncthreads();
        if (it + 2 < NK) load_chunk(it + 2);

        const uint32_t stg = sb + (uint32_t)(it % 3)*STAGE;
        #pragma unroll
        for (int ks = 0; ks < 2; ks++) {
            uint32_t bh[2][4];
            const int kin = ks*16 + rOff;
            #pragma unroll
            for (int g = 0; g < 2; g++) {
                int cB = wn*4 + g*2 + cOff;
                uint32_t bd = stg + BOFF + kin*256 + (((uint32_t)(cB ^ (kin & 7))) << 4);
                LDSM4T(bh[g][0], bh[g][1], bh[g][2], bh[g][3], bd);
            }
            #pragma unroll
            for (int mp = 0; mp < 2; mp++) {
                uint32_t ah[2][4], al[2][4];
                #pragma unroll
                for (int ml = 0; ml < 2; ml++) {
                    int row = wm*64 + (mp*2 + ml)*16 + rOff;
                    uint32_t ad = stg + row*80 + ((uint32_t)(ks*2 + cOff) << 4);
                    LDSM4(ah[ml][0], ah[ml][1], ah[ml][2], ah[ml][3], ad);
                    if (AS) LDSM4(al[ml][0], al[ml][1], al[ml][2], al[ml][3], ad + APS);
                }
                #pragma unroll
                for (int g = 0; g < 2; g++) {
                    #pragma unroll
                    for (int ml = 0; ml < 2; ml++) {
                        int mt = mp*2 + ml;
                        MMA16816(acc[mt][g*2],   ah[ml], bh[g][0], bh[g][1]);
                        MMA16816(acc[mt][g*2+1], ah[ml], bh[g][2], bh[g][3]);
                        if (AS) {
                            MMA16816(acc[mt][g*2],   al[ml], bh[g][0], bh[g][1]);
                            MMA16816(acc[mt][g*2+1], al[ml], bh[g][2], bh[g][3]);
                        }
                    }
                }
            }
        }
        __syncthreads();
    }

    // ---- epilogue ----
    #pragma unroll
    for (int mt = 0; mt < 4; mt++) {
        #pragma unroll
        for (int nt = 0; nt < 4; nt++) {
            #pragma unroll
            for (int half = 0; half < 2; half++) {
                int m = bm + wm*64 + mt*16 + group + half*8;
                #pragma unroll
                for (int e = 0; e < 2; e++) {
                    int n = bn + wn*32 + nt*8 + tid4*2 + e;
                    float v = acc[mt][nt][half*2 + e];
                    if (MODE == 0) {
                        float s = siluf(v + bias[n]);
                        vs_h[(size_t)m*H_ + n] = __float2half_rn(s);
                    } else if (MODE == 1) {
                        v += bias[n];
                        if (n < 512)       v = sigmf(v);
                        else if (n < 1664) v = siluf(v);
                        g_base[(size_t)m*NBASE + n] = v;
                    } else if (MODE == 2) {
                        float hx = g_base[(size_t)m*NBASE + 1664 + n];
                        float s  = siluf(v + bias[n] + hx);
                        float u  = g_base[(size_t)m*NBASE + n];
                        float xr = Xres[(size_t)m*D_ + n];
                        g_o[(size_t)m*D_ + n] = xr + u*(s - xr);
                    } else {
                        size_t row = (size_t)(cc*128 + m)*B_ + bb;
                        float rv = g_base[row*NBASE + 640 + n];
                        hr_h[row*H_ + n] = __float2half_rn(v*rv);
                    }
                }
            }
        }
    }
}

// ---------------- QK + softmax ----------------
__global__ void __launch_bounds__(256) qk_kernel(
    const float* __restrict__ qkg, const float* __restrict__ qkb,
    const float* __restrict__ rp, float* __restrict__ attn_out)
{
    extern __shared__ float sm[];
    float* qT = sm;
    float* kT = sm + 16384;
    float* sT = sm + 32768;
    float* red = sm;

    const int b = blockIdx.x >> 4;
    const int c = blockIdx.x & 15;
    const int t = threadIdx.x;
    const float qscale = 0.08838834764831845f;

    for (int idx = t; idx < 16384; idx += 256) {
        int i = idx >> 7, z = idx & 127;
        int row = (c*128 + i)*B_ + b;
        float zv = g_base[(size_t)row*NBASE + 512 + z];
        qT[z*128 + i] = (zv*qkg[z]     + qkb[z]    ) * qscale;
        kT[z*128 + i] =  zv*qkg[128+z] + qkb[128+z];
    }
    __syncthreads();

    {
        const int tx = t & 15, ty = t >> 4;
        const int i0 = ty*8, j0 = tx*8;
        float acc[8][8];
        #pragma unroll
        for (int i = 0; i < 8; i++)
            #pragma unroll
            for (int j = 0; j < 8; j++) acc[i][j] = 0.f;

        #pragma unroll 4
        for (int z = 0; z < 128; z++) {
            float qa[8], ka[8];
            *(float4*)(qa)   = *(const float4*)&qT[z*128 + i0];
            *(float4*)(qa+4) = *(const float4*)&qT[z*128 + i0 + 4];
            *(float4*)(ka)   = *(const float4*)&kT[z*128 + j0];
            *(float4*)(ka+4) = *(const float4*)&kT[z*128 + j0 + 4];
            #pragma unroll
            for (int i = 0; i < 8; i++)
                #pragma unroll
                for (int j = 0; j < 8; j++)
                    acc[i][j] = fmaf(qa[i], ka[j], acc[i][j]);
        }
        #pragma unroll
        for (int r = 0; r < 8; r++)
            #pragma unroll
            for (int cc2 = 0; cc2 < 8; cc2++) {
                int i = i0 + r, j = j0 + cc2;
                sT[j*132 + i] = acc[r][cc2] + rp[1023 + j - i];
            }
    }
    __syncthreads();

    {
        const int i = t & 127, half = t >> 7;
        const int jb = half*64;
        float mx = -1e30f;
        for (int j = jb; j < jb + 64; j++) mx = fmaxf(mx, sT[j*132 + i]);
        red[half*128 + i] = mx;
        __syncthreads();
        float M = fmaxf(red[i], red[128 + i]);
        float s = 0.f;
        for (int j = jb; j < jb + 64; j++) {
            float e = expf(sT[j*132 + i] - M);
            sT[j*132 + i] = e;
            s += e;
        }
        red[256 + half*128 + i] = s;
        __syncthreads();
        if (half == 0) red[512 + i] = 1.f / (red[256 + i] + red[384 + i]);
        __syncthreads();
    }

    size_t base = (size_t)(b*NC_ + c)*16384;
    float* aout = attn_out + base;
    for (int idx = t; idx < 16384; idx += 256) {
        int i = idx >> 7, j = idx & 127;
        float p = sT[j*132 + i] * red[512 + i];
        aout[idx] = p;
        at_h[base + idx] = __float2half_rn(p);
    }
}

// ---------------- final rmsnorm ----------------
__global__ void __launch_bounds__(256) norm_kernel(
    const float* __restrict__ ns, float* __restrict__ out)
{
    int row  = blockIdx.x*8 + (threadIdx.x >> 5);
    int lane = threadIdx.x & 31;
    const float* op = g_o + (size_t)row*512;
    float vals[16];
    float ss = 0.f;
    #pragma unroll
    for (int k = 0; k < 16; k++) {
        float v = op[lane + k*32];
        vals[k] = v;
        ss += v*v;
    }
    #pragma unroll
    for (int off = 16; off; off >>= 1) ss += __shfl_xor_sync(0xffffffffu, ss, off);
    float scale = ns[0] * rsqrtf(ss*(1.f/512.f) + 1e-6f);
    float* outp = out + (size_t)row*512;
    #pragma unroll
    for (int k = 0; k < 16; k++) outp[lane + k*32] = vals[k]*scale;
}

// ---------------- launch ----------------
extern "C" void kernel_launch(void* const* d_in, const int* in_sizes, int n_in,
                              void* d_out, int out_size)
{
    const float* x   = (const float*)d_in[0];
    const float* edl = (const float*)d_in[1];
    const float* eal = (const float*)d_in[2];
    const float* ebt = (const float*)d_in[3];
    const float* egm = (const float*)d_in[4];
    const float* eom = (const float*)d_in[5];
    const float* Wv  = (const float*)d_in[6];
    const float* bv  = (const float*)d_in[7];
    const float* Wmx = (const float*)d_in[8];
    const float* bmx = (const float*)d_in[9];
    const float* Wh  = (const float*)d_in[10];
    const float* bh  = (const float*)d_in[11];
    const float* qkg = (const float*)d_in[12];
    const float* qkb = (const float*)d_in[13];
    const float* rp  = (const float*)d_in[14];
    const float* ns  = (const float*)d_in[15];

    float* out      = (float*)d_out;
    float* attn_out = out + (size_t)L_*B_*D_;

    static __half *p_wvh=nullptr,*p_wmxh,*p_whh;
    if (!p_wvh) {
        cudaGetSymbolAddress((void**)&p_wvh,  wv_h);
        cudaGetSymbolAddress((void**)&p_wmxh, wmx_h);
        cudaGetSymbolAddress((void**)&p_whh,  wh_h);
        cudaFuncSetAttribute(qk_kernel,   cudaFuncAttributeMaxDynamicSharedMemorySize, 198656);
        cudaFuncSetAttribute(ema_p3,      cudaFuncAttributeMaxDynamicSharedMemorySize, 65536);
        cudaFuncSetAttribute((const void*)mma_gemm<0,false,0>,   cudaFuncAttributeMaxDynamicSharedMemorySize, 55296);
        cudaFuncSetAttribute((const void*)mma_gemm<1,true,0>,    cudaFuncAttributeMaxDynamicSharedMemorySize, 86016);
        cudaFuncSetAttribute((const void*)mma_gemm<1,false,640>, cudaFuncAttributeMaxDynamicSharedMemorySize, 55296);
        cudaFuncSetAttribute((const void*)mma_gemm<2,false,0>,   cudaFuncAttributeMaxDynamicSharedMemorySize, 55296);
        cudaFuncSetAttribute((const void*)mma_gemm<3,false,0>,   cudaFuncAttributeMaxDynamicSharedMemorySize, 55296);
    }

    splitw_kernel<<<512,  256>>>(Wv,  p_wvh);
    splitw_kernel<<<1088, 256>>>(Wmx, p_wmxh);
    splitw_kernel<<<512,  256>>>(Wh,  p_whh);

    ema_p1<<<512, 256>>>(x, edl, eal);
    ema_p2<<<32, 256>>>(edl, eal);
    ema_p3<<<1024, 128, 65536>>>(x, edl, eal, ebt, egm, eom);

    { dim3 g(8, 256);  mma_gemm<0,false,0><<<g, 256, 55296>>>(x, bv); }
    { dim3 g(5, 256);  mma_gemm<1,true,0><<<g, 256, 86016>>>(x, bmx); }      // u + z cols
    { dim3 g(12, 256); mma_gemm<1,false,640><<<g, 256, 55296>>>(x, bmx); }   // r + hx cols

    qk_kernel<<<B_*NC_, 256, 198656>>>(qkg, qkb, rp, attn_out);

    { dim3 g(8, 1, 256); mma_gemm<3,false,0><<<g, 256, 55296>>>(x, bv); }
    { dim3 g(4, 256);    mma_gemm<2,false,0><<<g, 256, 55296>>>(x, bh); }

    norm_kernel<<<MROWS/8, 256>>>(ns, out);
}

// round 13
// speedup vs baseline: 4.9055x; 1.0662x over previous
#include <cuda_runtime.h>
#include <cuda_fp16.h>
#include <stdint.h>
#include <math.h>

#define L_ 2048
#define B_ 16
#define D_ 512
#define H_ 1024
#define NC_ 16
#define NBASE 2176            // Z + H + 2D
#define MROWS (L_*B_)         // 32768
#define NCH 16                // EMA chunks
#define CHL 128               // chunk length

// ---------------- fp32 scratch ----------------
__device__ float g_base[MROWS*NBASE];  // activated base: [u | z | r | hx]
__device__ float g_o   [MROWS*D_];     // pre-norm output
__device__ float e_st  [4*NCH*8192];   // per-chunk local states
__device__ float seed_st[4*NCH*8192];  // per-chunk seeds

// ---------------- fp16 planes ----------------
// A-split (hi+lo) kept ONLY for mode-1 z columns. Everything else single-plane.
__device__ __align__(16) __half xs_h [MROWS*D_];
__device__ __align__(16) __half mxs_h[MROWS*D_],  mxs_l[MROWS*D_];
__device__ __align__(16) __half hr_h [MROWS*H_];
__device__ __align__(16) __half at_h [B_*NC_*128*128];
__device__ __align__(16) __half vs_h [MROWS*H_];
__device__ __align__(16) __half wv_h [512*1024];
__device__ __align__(16) __half wmx_h[512*2176];
__device__ __align__(16) __half wh_h [1024*512];

__device__ __forceinline__ float sigmf(float x){ return 1.0f/(1.0f + expf(-x)); }
__device__ __forceinline__ float siluf(float x){ return x/(1.0f + expf(-x)); }
__device__ __forceinline__ void split2h(float v, __half& h, __half& l){
    h = __float2half_rn(v);
    l = __float2half_rn(v - __half2float(h));
}

#define MMA16816(d, a, b0, b1) \
  asm volatile("mma.sync.aligned.m16n8k16.row.col.f32.f16.f16.f32 " \
    "{%0,%1,%2,%3}, {%4,%5,%6,%7}, {%8,%9}, {%0,%1,%2,%3};" \
    : "+f"(d[0]), "+f"(d[1]), "+f"(d[2]), "+f"(d[3]) \
    : "r"(a[0]), "r"(a[1]), "r"(a[2]), "r"(a[3]), "r"(b0), "r"(b1))

#define LDSM4(r0,r1,r2,r3,a) \
  asm volatile("ldmatrix.sync.aligned.m8n8.x4.shared.b16 {%0,%1,%2,%3}, [%4];" \
    : "=r"(r0),"=r"(r1),"=r"(r2),"=r"(r3) : "r"(a))

#define LDSM4T(r0,r1,r2,r3,a) \
  asm volatile("ldmatrix.sync.aligned.m8n8.x4.trans.shared.b16 {%0,%1,%2,%3}, [%4];" \
    : "=r"(r0),"=r"(r1),"=r"(r2),"=r"(r3) : "r"(a))

#define CPA16(s,g) asm volatile("cp.async.cg.shared.global [%0], [%1], 16;" :: "r"(s), "l"(g))

// ---------------- weights: fp32 -> fp16 ----------------
__global__ void __launch_bounds__(256) splitw_kernel(
    const float* __restrict__ src, __half* __restrict__ oh)
{
    size_t i4 = (size_t)blockIdx.x*256 + threadIdx.x;
    float4 v = *(const float4*)&src[i4*4];
    size_t o = i4*4;
    oh[o+0] = __float2half_rn(v.x);
    oh[o+1] = __float2half_rn(v.y);
    oh[o+2] = __float2half_rn(v.z);
    oh[o+3] = __float2half_rn(v.w);
}

// ---------------- EMA phase 1 ----------------
__global__ void __launch_bounds__(256) ema_p1(
    const float* __restrict__ x, const float* __restrict__ dlt,
    const float* __restrict__ alp)
{
    int t = blockIdx.x*256 + threadIdx.x;
    int c = t >> 13, bd = t & 8191;
    int d = bd & 511;
    int i0f = d*2, i1f = d*2 + 1;
    int i0b = (512 + d)*2, i1b = i0b + 1;
    float q0f = 1.f - sigmf(dlt[i0f])*sigmf(alp[i0f]);
    float q1f = 1.f - sigmf(dlt[i1f])*sigmf(alp[i1f]);
    float q0b = 1.f - sigmf(dlt[i0b])*sigmf(alp[i0b]);
    float q1b = 1.f - sigmf(dlt[i1b])*sigmf(alp[i1b]);

    float f0 = 0.f, f1 = 0.f, a0 = 0.f, a1 = 0.f, pw0 = 1.f, pw1 = 1.f;
    size_t idx = (size_t)(c*CHL)*8192 + bd;
    #pragma unroll 4
    for (int j = 0; j < CHL; j++, idx += 8192) {
        float xv = x[idx];
        f0 = fmaf(q0f, f0, xv);
        f1 = fmaf(q1f, f1, xv);
        a0 = fmaf(pw0, xv, a0);
        a1 = fmaf(pw1, xv, a1);
        pw0 *= q0b; pw1 *= q1b;
        xs_h[idx] = __float2half_rn(xv);
    }
    int o = c*8192 + bd;
    e_st[0*NCH*8192 + o] = f0;
    e_st[1*NCH*8192 + o] = f1;
    e_st[2*NCH*8192 + o] = a0;
    e_st[3*NCH*8192 + o] = a1;
}

// ---------------- EMA phase 2 ----------------
__global__ void __launch_bounds__(256) ema_p2(
    const float* __restrict__ dlt, const float* __restrict__ alp)
{
    int bd = blockIdx.x*256 + threadIdx.x;
    int d = bd & 511;
    int i0f = d*2, i1f = d*2 + 1;
    int i0b = (512 + d)*2, i1b = i0b + 1;
    float q0f = 1.f - sigmf(dlt[i0f])*sigmf(alp[i0f]);
    float q1f = 1.f - sigmf(dlt[i1f])*sigmf(alp[i1f]);
    float q0b = 1.f - sigmf(dlt[i0b])*sigmf(alp[i0b]);
    float q1b = 1.f - sigmf(dlt[i1b])*sigmf(alp[i1b]);
    float q0f8 = q0f, q1f8 = q1f, q0b8 = q0b, q1b8 = q1b;
    #pragma unroll
    for (int i = 0; i < 7; i++) { q0f8 *= q0f8; q1f8 *= q1f8; q0b8 *= q0b8; q1b8 *= q1b8; }

    float P0 = 0.f, P1 = 0.f;
    #pragma unroll
    for (int c = 0; c < NCH; c++) {
        int o = c*8192 + bd;
        seed_st[0*NCH*8192 + o] = P0;
        seed_st[1*NCH*8192 + o] = P1;
        P0 = fmaf(q0f8, P0, e_st[0*NCH*8192 + o]);
        P1 = fmaf(q1f8, P1, e_st[1*NCH*8192 + o]);
    }
    float T0 = 0.f, T1 = 0.f;
    #pragma unroll
    for (int c = NCH-1; c >= 0; c--) {
        int o = c*8192 + bd;
        seed_st[2*NCH*8192 + o] = T0;
        seed_st[3*NCH*8192 + o] = T1;
        T0 = fmaf(q0b8, T0, e_st[2*NCH*8192 + o]);
        T1 = fmaf(q1b8, T1, e_st[3*NCH*8192 + o]);
    }
}

// ---------------- EMA phase 3 ----------------
__global__ void __launch_bounds__(128) ema_p3(
    const float* __restrict__ x, const float* __restrict__ dlt,
    const float* __restrict__ alp, const float* __restrict__ bet,
    const float* __restrict__ gam, const float* __restrict__ omg)
{
    extern __shared__ float ybuf[];            // [CHL][128]
    int t = blockIdx.x*128 + threadIdx.x;
    int tid = threadIdx.x;
    int c = t >> 13, bd = t & 8191;
    int d = bd & 511;
    const float invs = 0.7071067811865476f;

    int i0f = d*2, i1f = d*2 + 1;
    int i0b = (512 + d)*2, i1b = i0b + 1;
    float p0f = sigmf(dlt[i0f]), p1f = sigmf(dlt[i1f]);
    float p0b = sigmf(dlt[i0b]), p1b = sigmf(dlt[i1b]);
    float q0f = 1.f - p0f*sigmf(alp[i0f]);
    float q1f = 1.f - p1f*sigmf(alp[i1f]);
    float q0b = 1.f - p0b*sigmf(alp[i0b]);
    float q1b = 1.f - p1b*sigmf(alp[i1b]);
    float w0f = p0f*bet[i0f]*gam[i0f]*invs;
    float w1f = p1f*bet[i1f]*gam[i1f]*invs;
    float w0b = p0b*bet[i0b]*gam[i0b]*invs;
    float w1b = p1b*bet[i1b]*gam[i1b]*invs;
    float ow = omg[d];

    int o = c*8192 + bd;
    size_t base = (size_t)(c*CHL)*8192 + bd;

    {
        float g0 = seed_st[2*NCH*8192 + o];
        float g1 = seed_st[3*NCH*8192 + o];
        size_t idx = base + (size_t)(CHL-1)*8192;
        #pragma unroll 4
        for (int j = CHL-1; j >= 0; j--, idx -= 8192) {
            float xv = x[idx];
            g0 = fmaf(q0b, g0, xv);
            g1 = fmaf(q1b, g1, xv);
            ybuf[j*128 + tid] = fmaf(w0b, g0, w1b*g1);
        }
    }
    {
        float f0 = seed_st[0*NCH*8192 + o];
        float f1 = seed_st[1*NCH*8192 + o];
        size_t idx = base;
        #pragma unroll 4
        for (int j = 0; j < CHL; j++, idx += 8192) {
            float xv = x[idx];
            f0 = fmaf(q0f, f0, xv);
            f1 = fmaf(q1f, f1, xv);
            float y = ybuf[j*128 + tid] + fmaf(w0f, f0, fmaf(w1f, f1, xv*ow));
            split2h(siluf(y), mxs_h[idx], mxs_l[idx]);
        }
    }
}

// ---------------- pipelined fp16 tensor-core GEMM (K-chunk 64) ----------------
// AS = 2-pass A-split (only mode-1 z columns); NOFF = n-offset of this launch.
// 1-pass: 3-stage ring (one sync/iter); 2-pass: 2-stage ring. 2 CTAs/SM.
// MODE 0: vs_h  = fp16(silu(xs @ Wv + bv))         N=1024 K=512
// MODE 1: g_base= act(mxs @ Wmx + bmx)             (u/r/hx 1-pass, z 2-pass)
// MODE 2: g_o   = gate(silu(hr @ Wh + bh + hx))    N=512  K=1024
// MODE 3: hr_h  = fp16((attn @ v) * r)  (256 bat)  N=1024 K=128
template<int MODE, bool AS, int NOFF>
__global__ void __launch_bounds__(256, 2) mma_gemm(
    const float* __restrict__ Xres, const float* __restrict__ bias)
{
    constexpr int K   = (MODE==2) ? 1024 : (MODE==3) ? 128 : 512;
    constexpr int ldA = (MODE==2) ? 1024 : (MODE==3) ? 128 : 512;
    constexpr int ldB = (MODE==0) ? 1024 : (MODE==1) ? 2176 : (MODE==2) ? 512 : 16384;
    constexpr int NK  = K/64;
    constexpr int APS = 128*128;              // 16384: A plane (128 rows x 128B)
    constexpr int BOFF = (AS ? 2 : 1)*APS;
    constexpr int STAGE = BOFF + 16384;       // + B tile 64x256B
    constexpr int NST = AS ? 2 : 3;
    constexpr int NAE = AS ? 8 : 4;

    extern __shared__ __align__(128) char smem_raw[];
    const uint32_t sb = (uint32_t)__cvta_generic_to_shared(smem_raw);

    const int t = threadIdx.x;
    const int warp = t >> 5, lane = t & 31;
    const int wm = warp & 1, wn = warp >> 1;        // 2m x 4n
    const int group = lane >> 2, tid4 = lane & 3;
    const int mat = lane >> 3, rim = lane & 7;
    const int rOff = ((mat & 1) << 3) + rim;
    const int cOff = mat >> 1;

    const int bn = NOFF + blockIdx.x * 128;
    const int bm = (MODE==3) ? 0 : blockIdx.y * 128;

    int bb = 0, cc = 0, batch = 0;
    if (MODE == 3) { batch = blockIdx.z; bb = batch >> 4; cc = batch & 15; }

    const __half *pA0, *pA1 = nullptr, *pB0;
    if (MODE == 0) { pA0 = xs_h  + (size_t)bm*ldA;
                     pB0 = wv_h  + bn; }
    else if (MODE == 1) { pA0 = mxs_h + (size_t)bm*ldA; pA1 = mxs_l + (size_t)bm*ldA;
                          pB0 = wmx_h + bn; }
    else if (MODE == 2) { pA0 = hr_h  + (size_t)bm*ldA;
                          pB0 = wh_h  + bn; }
    else { pA0 = at_h + (size_t)batch*16384;
           pB0 = vs_h + (size_t)(cc*2048 + bb)*H_ + bn; }

    // cp.async descriptors: A rows 128B swizzled; B rows 256B swizzled
    const __half* gA[NAE]; uint32_t sA[NAE];
    #pragma unroll
    for (int e = 0; e < NAE; e++) {
        int idx = e*256 + t;                  // 0..(NAE*256-1)
        int plane = idx >> 10, w = idx & 1023;
        int r = w >> 3, c = w & 7;
        gA[e] = (plane ? pA1 : pA0) + (size_t)r*ldA + c*8;
        sA[e] = sb + plane*APS + r*128 + (((uint32_t)(c ^ (r & 7))) << 4);
    }
    const __half* gB[4]; uint32_t sB[4];
    #pragma unroll
    for (int e = 0; e < 4; e++) {
        int idx = e*256 + t;                  // 0..1023
        int r = idx >> 4, c = idx & 15;
        gB[e] = pB0 + (size_t)r*ldB + c*8;
        sB[e] = sb + BOFF + r*256 + (((uint32_t)(c ^ (r & 7))) << 4);
    }

    auto load_chunk = [&](int ck) {
        uint32_t so = (uint32_t)(ck % NST) * STAGE;
        int ka = ck * 64;
        #pragma unroll
        for (int e = 0; e < NAE; e++) CPA16(sA[e] + so, gA[e] + ka);
        #pragma unroll
        for (int e = 0; e < 4; e++) CPA16(sB[e] + so, gB[e] + (size_t)ka*ldB);
        asm volatile("cp.async.commit_group;");
    };

    float acc[4][4][4];
    #pragma unroll
    for (int a = 0; a < 4; a++)
        #pragma unroll
        for (int b2 = 0; b2 < 4; b2++)
            #pragma unroll
            for (int e = 0; e < 4; e++) acc[a][b2][e] = 0.f;

    load_chunk(0);
    load_chunk(1);

    for (int it = 0; it < NK; it++) {
        if (it + 1 < NK) asm volatile("cp.async.wait_group 1;" ::: "memory");
        else             asm volatile("cp.async.wait_group 0;" ::: "memory");
        __syncthreads();
        if (NST == 3 && it + 2 < NK) load_chunk(it + 2);

        const uint32_t stg = sb + (uint32_t)(it % NST)*STAGE;
        #pragma unroll
        for (int ks = 0; ks < 4; ks++) {
            uint32_t bh[2][4];
            const int kin = ks*16 + rOff;
            #pragma unroll
            for (int g = 0; g < 2; g++) {
                int cB = wn*4 + g*2 + cOff;
                uint32_t bd = stg + BOFF + kin*256 + (((uint32_t)(cB ^ (kin & 7))) << 4);
                LDSM4T(bh[g][0], bh[g][1], bh[g][2], bh[g][3], bd);
            }
            #pragma unroll
            for (int mp = 0; mp < 2; mp++) {
                uint32_t ah[2][4], al[2][4];
                #pragma unroll
                for (int ml = 0; ml < 2; ml++) {
                    int row = wm*64 + (mp*2 + ml)*16 + rOff;
                    int cA = ks*2 + cOff;
                    uint32_t ad = stg + row*128 + (((uint32_t)(cA ^ (row & 7))) << 4);
                    LDSM4(ah[ml][0], ah[ml][1], ah[ml][2], ah[ml][3], ad);
                    if (AS) LDSM4(al[ml][0], al[ml][1], al[ml][2], al[ml][3], ad + APS);
                }
                #pragma unroll
                for (int g = 0; g < 2; g++) {
                    #pragma unroll
                    for (int ml = 0; ml < 2; ml++) {
                        int mt = mp*2 + ml;
                        MMA16816(acc[mt][g*2],   ah[ml], bh[g][0], bh[g][1]);
                        MMA16816(acc[mt][g*2+1], ah[ml], bh[g][2], bh[g][3]);
                        if (AS) {
                            MMA16816(acc[mt][g*2],   al[ml], bh[g][0], bh[g][1]);
                            MMA16816(acc[mt][g*2+1], al[ml], bh[g][2], bh[g][3]);
                        }
                    }
                }
            }
        }
        if (NST == 2) {
            __syncthreads();
            if (it + 2 < NK) load_chunk(it + 2);
        }
    }

    // ---- epilogue ----
    #pragma unroll
    for (int mt = 0; mt < 4; mt++) {
        #pragma unroll
        for (int nt = 0; nt < 4; nt++) {
            #pragma unroll
            for (int half = 0; half < 2; half++) {
                int m = bm + wm*64 + mt*16 + group + half*8;
                #pragma unroll
                for (int e = 0; e < 2; e++) {
                    int n = bn + wn*32 + nt*8 + tid4*2 + e;
                    float v = acc[mt][nt][half*2 + e];
                    if (MODE == 0) {
                        float s = siluf(v + bias[n]);
                        vs_h[(size_t)m*H_ + n] = __float2half_rn(s);
                    } else if (MODE == 1) {
                        v += bias[n];
                        if (n < 512)       v = sigmf(v);
                        else if (n < 1664) v = siluf(v);
                        g_base[(size_t)m*NBASE + n] = v;
                    } else if (MODE == 2) {
                        float hx = g_base[(size_t)m*NBASE + 1664 + n];
                        float s  = siluf(v + bias[n] + hx);
                        float u  = g_base[(size_t)m*NBASE + n];
                        float xr = Xres[(size_t)m*D_ + n];
                        g_o[(size_t)m*D_ + n] = xr + u*(s - xr);
                    } else {
                        size_t row = (size_t)(cc*128 + m)*B_ + bb;
                        float rv = g_base[row*NBASE + 640 + n];
                        hr_h[row*H_ + n] = __float2half_rn(v*rv);
                    }
                }
            }
        }
    }
}

// ---------------- QK + softmax ----------------
__global__ void __launch_bounds__(256) qk_kernel(
    const float* __restrict__ qkg, const float* __restrict__ qkb,
    const float* __restrict__ rp, float* __restrict__ attn_out)
{
    extern __shared__ float sm[];
    float* qT = sm;
    float* kT = sm + 16384;
    float* sT = sm + 32768;
    float* red = sm;

    const int b = blockIdx.x >> 4;
    const int c = blockIdx.x & 15;
    const int t = threadIdx.x;
    const float qscale = 0.08838834764831845f;

    for (int idx = t; idx < 16384; idx += 256) {
        int i = idx >> 7, z = idx & 127;
        int row = (c*128 + i)*B_ + b;
        float zv = g_base[(size_t)row*NBASE + 512 + z];
        qT[z*128 + i] = (zv*qkg[z]     + qkb[z]    ) * qscale;
        kT[z*128 + i] =  zv*qkg[128+z] + qkb[128+z];
    }
    __syncthreads();

    {
        const int tx = t & 15, ty = t >> 4;
        const int i0 = ty*8, j0 = tx*8;
        float acc[8][8];
        #pragma unroll
        for (int i = 0; i < 8; i++)
            #pragma unroll
            for (int j = 0; j < 8; j++) acc[i][j] = 0.f;

        #pragma unroll 4
        for (int z = 0; z < 128; z++) {
            float qa[8], ka[8];
            *(float4*)(qa)   = *(const float4*)&qT[z*128 + i0];
            *(float4*)(qa+4) = *(const float4*)&qT[z*128 + i0 + 4];
            *(float4*)(ka)   = *(const float4*)&kT[z*128 + j0];
            *(float4*)(ka+4) = *(const float4*)&kT[z*128 + j0 + 4];
            #pragma unroll
            for (int i = 0; i < 8; i++)
                #pragma unroll
                for (int j = 0; j < 8; j++)
                    acc[i][j] = fmaf(qa[i], ka[j], acc[i][j]);
        }
        #pragma unroll
        for (int r = 0; r < 8; r++)
            #pragma unroll
            for (int cc2 = 0; cc2 < 8; cc2++) {
                int i = i0 + r, j = j0 + cc2;
                sT[j*132 + i] = acc[r][cc2] + rp[1023 + j - i];
            }
    }
    __syncthreads();

    {
        const int i = t & 127, half = t >> 7;
        const int jb = half*64;
        float mx = -1e30f;
        for (int j = jb; j < jb + 64; j++) mx = fmaxf(mx, sT[j*132 + i]);
        red[half*128 + i] = mx;
        __syncthreads();
        float M = fmaxf(red[i], red[128 + i]);
        float s = 0.f;
        for (int j = jb; j < jb + 64; j++) {
            float e = expf(sT[j*132 + i] - M);
            sT[j*132 + i] = e;
            s += e;
        }
        red[256 + half*128 + i] = s;
        __syncthreads();
        if (half == 0) red[512 + i] = 1.f / (red[256 + i] + red[384 + i]);
        __syncthreads();
    }

    size_t base = (size_t)(b*NC_ + c)*16384;
    float* aout = attn_out + base;
    for (int idx = t; idx < 16384; idx += 256) {
        int i = idx >> 7, j = idx & 127;
        float p = sT[j*132 + i] * red[512 + i];
        aout[idx] = p;
        at_h[base + idx] = __float2half_rn(p);
    }
}

// ---------------- final rmsnorm ----------------
__global__ void __launch_bounds__(256) norm_kernel(
    const float* __restrict__ ns, float* __restrict__ out)
{
    int row  = blockIdx.x*8 + (threadIdx.x >> 5);
    int lane = threadIdx.x & 31;
    const float* op = g_o + (size_t)row*512;
    float vals[16];
    float ss = 0.f;
    #pragma unroll
    for (int k = 0; k < 16; k++) {
        float v = op[lane + k*32];
        vals[k] = v;
        ss += v*v;
    }
    #pragma unroll
    for (int off = 16; off; off >>= 1) ss += __shfl_xor_sync(0xffffffffu, ss, off);
    float scale = ns[0] * rsqrtf(ss*(1.f/512.f) + 1e-6f);
    float* outp = out + (size_t)row*512;
    #pragma unroll
    for (int k = 0; k < 16; k++) outp[lane + k*32] = vals[k]*scale;
}

// ---------------- launch ----------------
extern "C" void kernel_launch(void* const* d_in, const int* in_sizes, int n_in,
                              void* d_out, int out_size)
{
    const float* x   = (const float*)d_in[0];
    const float* edl = (const float*)d_in[1];
    const float* eal = (const float*)d_in[2];
    const float* ebt = (const float*)d_in[3];
    const float* egm = (const float*)d_in[4];
    const float* eom = (const float*)d_in[5];
    const float* Wv  = (const float*)d_in[6];
    const float* bv  = (const float*)d_in[7];
    const float* Wmx = (const float*)d_in[8];
    const float* bmx = (const float*)d_in[9];
    const float* Wh  = (const float*)d_in[10];
    const float* bh  = (const float*)d_in[11];
    const float* qkg = (const float*)d_in[12];
    const float* qkb = (const float*)d_in[13];
    const float* rp  = (const float*)d_in[14];
    const float* ns  = (const float*)d_in[15];

    float* out      = (float*)d_out;
    float* attn_out = out + (size_t)L_*B_*D_;

    static __half *p_wvh=nullptr,*p_wmxh,*p_whh;
    if (!p_wvh) {
        cudaGetSymbolAddress((void**)&p_wvh,  wv_h);
        cudaGetSymbolAddress((void**)&p_wmxh, wmx_h);
        cudaGetSymbolAddress((void**)&p_whh,  wh_h);
        cudaFuncSetAttribute(qk_kernel,   cudaFuncAttributeMaxDynamicSharedMemorySize, 198656);
        cudaFuncSetAttribute(ema_p3,      cudaFuncAttributeMaxDynamicSharedMemorySize, 65536);
        cudaFuncSetAttribute((const void*)mma_gemm<0,false,0>,   cudaFuncAttributeMaxDynamicSharedMemorySize, 98304);
        cudaFuncSetAttribute((const void*)mma_gemm<1,false,0>,   cudaFuncAttributeMaxDynamicSharedMemorySize, 98304);
        cudaFuncSetAttribute((const void*)mma_gemm<1,true,512>,  cudaFuncAttributeMaxDynamicSharedMemorySize, 98304);
        cudaFuncSetAttribute((const void*)mma_gemm<1,false,640>, cudaFuncAttributeMaxDynamicSharedMemorySize, 98304);
        cudaFuncSetAttribute((const void*)mma_gemm<2,false,0>,   cudaFuncAttributeMaxDynamicSharedMemorySize, 98304);
        cudaFuncSetAttribute((const void*)mma_gemm<3,false,0>,   cudaFuncAttributeMaxDynamicSharedMemorySize, 98304);
    }

    splitw_kernel<<<512,  256>>>(Wv,  p_wvh);
    splitw_kernel<<<1088, 256>>>(Wmx, p_wmxh);
    splitw_kernel<<<512,  256>>>(Wh,  p_whh);

    ema_p1<<<512, 256>>>(x, edl, eal);
    ema_p2<<<32, 256>>>(edl, eal);
    ema_p3<<<1024, 128, 65536>>>(x, edl, eal, ebt, egm, eom);

    { dim3 g(8, 256);  mma_gemm<0,false,0><<<g, 256, 98304>>>(x, bv); }
    { dim3 g(4, 256);  mma_gemm<1,false,0><<<g, 256, 98304>>>(x, bmx); }     // u cols (1-pass)
    { dim3 g(1, 256);  mma_gemm<1,true,512><<<g, 256, 98304>>>(x, bmx); }    // z cols (2-pass)
    { dim3 g(12, 256); mma_gemm<1,false,640><<<g, 256, 98304>>>(x, bmx); }   // r + hx cols

    qk_kernel<<<B_*NC_, 256, 198656>>>(qkg, qkb, rp, attn_out);

    { dim3 g(8, 1, 256); mma_gemm<3,false,0><<<g, 256, 98304>>>(x, bv); }
    { dim3 g(4, 256);    mma_gemm<2,false,0><<<g, 256, 98304>>>(x, bh); }

    norm_kernel<<<MROWS/8, 256>>>(ns, out);
}